// round 6
// baseline (speedup 1.0000x reference)
#include <cuda_runtime.h>
#include <cuda_bf16.h>
#include <math.h>

#define BB 16
#define NN 512
#define DD 256
#define LL 4
#define HH 8
#define DK 32
#define DFF 1024

// ------------------------- scratch (device globals) -------------------------
__device__ float g_x[BB * NN * DD];
__device__ float g_xv[BB * NN * DD];
__device__ float g_q[BB * NN * DD];
__device__ float g_k[BB * NN * DD];
__device__ float g_v[BB * NN * DD];
__device__ float g_ao[BB * NN * DD];
__device__ float g_o[BB * NN * DD];
__device__ float g_h[BB * NN * DFF];
__device__ float g_h2[BB * NN * DD];

// ------------------------- add positional embedding -------------------------
__global__ void add_pos_kernel(const float* __restrict__ in,
                               const float* __restrict__ in_v,
                               const float* __restrict__ pos,
                               float* __restrict__ x, float* __restrict__ xv) {
    size_t i = (size_t)blockIdx.x * 256 + threadIdx.x;
    float p = pos[i % (NN * DD)];
    x[i]  = in[i]  + p;
    xv[i] = in_v[i] + p;
}

// ------------------- 128x128x8 double-buffered GEMM body --------------------
#define GM 128
#define GN 128
#define GKK 8

__device__ __forceinline__
void gemm128_body(const float* __restrict__ A,
                  const float* __restrict__ W,
                  const float* __restrict__ bias,
                  float* __restrict__ C,
                  int M, int K, int Nc, int apply_gelu) {
    __shared__ float As[2][GKK][GM];
    __shared__ float Bs[2][GKK][GN];
    const int tid = threadIdx.x;
    const int tx = tid & 15, ty = tid >> 4;
    const int row0 = blockIdx.y * GM, col0 = blockIdx.x * GN;

    const int arow = tid >> 1, ak0 = (tid & 1) * 4;
    const int brow = tid >> 5, bcol = (tid & 31) * 4;

    const float* Aptr = A + (size_t)(row0 + arow) * K + ak0;
    const float* Wptr = W + (size_t)brow * Nc + col0 + bcol;

    {
        float4 a4 = *(const float4*)Aptr;
        float4 b4 = *(const float4*)Wptr;
        As[0][ak0 + 0][arow] = a4.x;
        As[0][ak0 + 1][arow] = a4.y;
        As[0][ak0 + 2][arow] = a4.z;
        As[0][ak0 + 3][arow] = a4.w;
        *(float4*)&Bs[0][brow][bcol] = b4;
    }
    __syncthreads();

    float acc[8][8];
#pragma unroll
    for (int i = 0; i < 8; i++)
#pragma unroll
        for (int j = 0; j < 8; j++) acc[i][j] = 0.0f;

    int buf = 0;
    for (int k0 = 0; k0 < K; k0 += GKK) {
        const bool has_next = (k0 + GKK < K);
        float4 na, nb;
        if (has_next) {
            na = *(const float4*)(Aptr + k0 + GKK);
            nb = *(const float4*)(Wptr + (size_t)(k0 + GKK) * Nc);
        }
#pragma unroll
        for (int kk = 0; kk < GKK; kk++) {
            float a[8], b[8];
            *(float4*)(a)     = *(const float4*)&As[buf][kk][ty * 4];
            *(float4*)(a + 4) = *(const float4*)&As[buf][kk][64 + ty * 4];
            *(float4*)(b)     = *(const float4*)&Bs[buf][kk][tx * 4];
            *(float4*)(b + 4) = *(const float4*)&Bs[buf][kk][64 + tx * 4];
#pragma unroll
            for (int i = 0; i < 8; i++)
#pragma unroll
                for (int j = 0; j < 8; j++)
                    acc[i][j] += a[i] * b[j];
        }
        if (has_next) {
            As[buf ^ 1][ak0 + 0][arow] = na.x;
            As[buf ^ 1][ak0 + 1][arow] = na.y;
            As[buf ^ 1][ak0 + 2][arow] = na.z;
            As[buf ^ 1][ak0 + 3][arow] = na.w;
            *(float4*)&Bs[buf ^ 1][brow][bcol] = nb;
            __syncthreads();
            buf ^= 1;
        }
    }

    const int c0 = col0 + tx * 4;
    const int c1 = col0 + 64 + tx * 4;
    float4 bia0 = *(const float4*)&bias[c0];
    float4 bia1 = *(const float4*)&bias[c1];
#pragma unroll
    for (int i = 0; i < 8; i++) {
        int r = row0 + (i < 4 ? ty * 4 + i : 64 + ty * 4 + (i - 4));
        float o0[4] = {acc[i][0] + bia0.x, acc[i][1] + bia0.y,
                       acc[i][2] + bia0.z, acc[i][3] + bia0.w};
        float o1[4] = {acc[i][4] + bia1.x, acc[i][5] + bia1.y,
                       acc[i][6] + bia1.z, acc[i][7] + bia1.w};
        if (apply_gelu) {
#pragma unroll
            for (int j = 0; j < 4; j++) {
                o0[j] = 0.5f * o0[j] * (1.0f + erff(o0[j] * 0.70710678118654752f));
                o1[j] = 0.5f * o1[j] * (1.0f + erff(o1[j] * 0.70710678118654752f));
            }
        }
        *(float4*)&C[(size_t)r * Nc + c0] = *(float4*)o0;
        *(float4*)&C[(size_t)r * Nc + c1] = *(float4*)o1;
    }
}

__global__ __launch_bounds__(256, 2)
void gemm128_kernel(const float* __restrict__ A,
                    const float* __restrict__ W,
                    const float* __restrict__ bias,
                    float* __restrict__ C,
                    int M, int K, int Nc, int apply_gelu) {
    gemm128_body(A, W, bias, C, M, K, Nc, apply_gelu);
}

// Batched QKV: blockIdx.z selects {x@Wq, x@Wk, xv@Wv}. One launch, 3x grid.
__global__ __launch_bounds__(256, 2)
void gemm_qkv_kernel(const float* __restrict__ x, const float* __restrict__ xv,
                     const float* __restrict__ Wq, const float* __restrict__ Wk,
                     const float* __restrict__ Wv,
                     const float* __restrict__ bq, const float* __restrict__ bk,
                     const float* __restrict__ bv,
                     float* __restrict__ q, float* __restrict__ k,
                     float* __restrict__ v, int M, int K, int Nc) {
    const float* A;
    const float* W;
    const float* b;
    float* C;
    if (blockIdx.z == 0)      { A = x;  W = Wq; b = bq; C = q; }
    else if (blockIdx.z == 1) { A = x;  W = Wk; b = bk; C = k; }
    else                      { A = xv; W = Wv; b = bv; C = v; }
    gemm128_body(A, W, b, C, M, K, Nc, 0);
}

// ------------------------- fused attention -------------------------
// 32-query tiles, dynamic smem: S[32][512] + Qs[32][33] + Kt[32][68].
// grid (N/32, H, B), block 256. mask read as 32-bit words (nonzero == True).
#define QT 32
#define ATTN_SMEM_FLOATS (QT * 512 + QT * 33 + 32 * 68)

__global__ void attn_kernel(const float* __restrict__ q,
                            const float* __restrict__ k,
                            const float* __restrict__ v,
                            const int* __restrict__ mask,
                            float* __restrict__ out, int use_mask) {
    const int b = blockIdx.z, h = blockIdx.y, q0 = blockIdx.x * QT;
    extern __shared__ float sm[];
    float* S  = sm;                       // QT * 512
    float* Qs = sm + QT * 512;            // QT * 33
    float* Kt = Qs + QT * 33;             // 32 * 68 (transposed K chunk [d][key])
    const int tid = threadIdx.x;
    const float scale = 0.17677669529663687f;  // 1/sqrt(32)

    // load Q tile
    for (int e = tid; e < QT * 32; e += 256) {
        int r = e >> 5, d = e & 31;
        Qs[r * 33 + d] = q[(size_t)(b * NN + q0 + r) * DD + h * DK + d];
    }

    // scores: thread handles rows sr, sr+16; cols scg*4..scg*4+3 per 64-chunk
    const int sr = tid >> 4;
    const int scg = tid & 15;
    for (int kc = 0; kc < NN; kc += 64) {
        __syncthreads();
        for (int e = tid; e < 64 * 32; e += 256) {
            int rr = e >> 5, d = e & 31;
            Kt[d * 68 + rr] = k[(size_t)(b * NN + kc + rr) * DD + h * DK + d];
        }
        __syncthreads();
        float a0[4] = {}, a1[4] = {};
#pragma unroll
        for (int d = 0; d < DK; d++) {
            float4 kv = *(const float4*)&Kt[d * 68 + scg * 4];
            float qv0 = Qs[sr * 33 + d];
            float qv1 = Qs[(sr + 16) * 33 + d];
            a0[0] += qv0 * kv.x; a0[1] += qv0 * kv.y;
            a0[2] += qv0 * kv.z; a0[3] += qv0 * kv.w;
            a1[0] += qv1 * kv.x; a1[1] += qv1 * kv.y;
            a1[2] += qv1 * kv.z; a1[3] += qv1 * kv.w;
        }
#pragma unroll
        for (int j = 0; j < 4; j++) { a0[j] *= scale; a1[j] *= scale; }
        if (use_mask) {
            int4 m0 = *(const int4*)&mask[(size_t)(q0 + sr) * NN + kc + scg * 4];
            int4 m1 = *(const int4*)&mask[(size_t)(q0 + sr + 16) * NN + kc + scg * 4];
            if (m0.x) a0[0] = -1e30f;
            if (m0.y) a0[1] = -1e30f;
            if (m0.z) a0[2] = -1e30f;
            if (m0.w) a0[3] = -1e30f;
            if (m1.x) a1[0] = -1e30f;
            if (m1.y) a1[1] = -1e30f;
            if (m1.z) a1[2] = -1e30f;
            if (m1.w) a1[3] = -1e30f;
        }
        *(float4*)&S[sr * 512 + kc + scg * 4] = *(float4*)a0;
        *(float4*)&S[(sr + 16) * 512 + kc + scg * 4] = *(float4*)a1;
    }
    __syncthreads();

    // softmax: 8 warps, 4 rows each
    const int warp = tid >> 5, lane = tid & 31;
    for (int r = warp; r < QT; r += 8) {
        float* Sr = &S[r * 512];
        float mx = -1e30f;
        for (int c = lane; c < NN; c += 32) mx = fmaxf(mx, Sr[c]);
#pragma unroll
        for (int o = 16; o; o >>= 1) mx = fmaxf(mx, __shfl_xor_sync(0xFFFFFFFFu, mx, o));
        float sum = 0.0f;
        for (int c = lane; c < NN; c += 32) {
            float e = __expf(Sr[c] - mx);
            Sr[c] = e;
            sum += e;
        }
#pragma unroll
        for (int o = 16; o; o >>= 1) sum += __shfl_xor_sync(0xFFFFFFFFu, sum, o);
        float inv = 1.0f / sum;
        for (int c = lane; c < NN; c += 32) Sr[c] *= inv;
    }
    __syncthreads();

    // O = P @ V.  thread (r=warp, d=lane) handles rows r, r+8, r+16, r+24;
    // one V load feeds 4 accumulators.
    {
        const int d = lane;
        const int r = warp;
        float acc0 = 0.0f, acc1 = 0.0f, acc2 = 0.0f, acc3 = 0.0f;
        const float* vb = v + (size_t)b * NN * DD + h * DK + d;
        const float* S0 = &S[r * 512];
        const float* S1 = &S[(r + 8) * 512];
        const float* S2 = &S[(r + 16) * 512];
        const float* S3 = &S[(r + 24) * 512];
#pragma unroll 4
        for (int kk = 0; kk < NN; kk++) {
            float vv = vb[(size_t)kk * DD];
            acc0 += S0[kk] * vv;
            acc1 += S1[kk] * vv;
            acc2 += S2[kk] * vv;
            acc3 += S3[kk] * vv;
        }
        size_t ob = (size_t)(b * NN + q0) * DD + h * DK + d;
        out[ob + (size_t)r * DD] = acc0;
        out[ob + (size_t)(r + 8) * DD] = acc1;
        out[ob + (size_t)(r + 16) * DD] = acc2;
        out[ob + (size_t)(r + 24) * DD] = acc3;
    }
}

// ------------------------- residual + layernorm -------------------------
__global__ void ln_kernel(const float* __restrict__ x,
                          const float* __restrict__ res,
                          const float* __restrict__ g,
                          const float* __restrict__ bta,
                          float* __restrict__ out) {
    const int row = blockIdx.x;
    const int i = threadIdx.x;
    const int warp = i >> 5, lane = i & 31;
    __shared__ float ps[8], ps2[8];
    size_t base = (size_t)row * DD;
    float val = x[base + i] + (res ? res[base + i] : 0.0f);
    float s = val, s2 = val * val;
#pragma unroll
    for (int o = 16; o; o >>= 1) {
        s  += __shfl_xor_sync(0xFFFFFFFFu, s, o);
        s2 += __shfl_xor_sync(0xFFFFFFFFu, s2, o);
    }
    if (lane == 0) { ps[warp] = s; ps2[warp] = s2; }
    __syncthreads();
    if (warp == 0) {
        float a = ps[lane & 7], a2 = ps2[lane & 7];
#pragma unroll
        for (int o = 4; o; o >>= 1) {
            a  += __shfl_xor_sync(0xFFFFFFFFu, a, o);
            a2 += __shfl_xor_sync(0xFFFFFFFFu, a2, o);
        }
        if (lane == 0) { ps[0] = a; ps2[0] = a2; }
    }
    __syncthreads();
    float mean = ps[0] * (1.0f / DD);
    float var = ps2[0] * (1.0f / DD) - mean * mean;
    out[base + i] = (val - mean) * rsqrtf(var + 1e-5f) * g[i] + bta[i];
}

// ------------------------- launch -------------------------
extern "C" void kernel_launch(void* const* d_in, const int* in_sizes, int n_in,
                              void* d_out, int out_size) {
    const float* input   = (const float*)d_in[0];
    const float* input_v = (const float*)d_in[1];
    const float* pos_emb = (const float*)d_in[2];
    const float* Wq = (const float*)d_in[3];
    const float* bq = (const float*)d_in[4];
    const float* Wk = (const float*)d_in[5];
    const float* bk = (const float*)d_in[6];
    const float* Wv = (const float*)d_in[7];
    const float* bv = (const float*)d_in[8];
    const float* Wo = (const float*)d_in[9];
    const float* bo = (const float*)d_in[10];
    const float* W1 = (const float*)d_in[11];
    const float* b1 = (const float*)d_in[12];
    const float* W2 = (const float*)d_in[13];
    const float* b2 = (const float*)d_in[14];
    const float* g1 = (const float*)d_in[15];
    const float* be1 = (const float*)d_in[16];
    const float* g2 = (const float*)d_in[17];
    const float* be2 = (const float*)d_in[18];
    const float* gf = (const float*)d_in[19];
    const float* bf = (const float*)d_in[20];
    const int* mask = (const int*)d_in[21];

    float *x, *xv, *q, *k, *v, *ao, *o, *h, *h2;
    cudaGetSymbolAddress((void**)&x, g_x);
    cudaGetSymbolAddress((void**)&xv, g_xv);
    cudaGetSymbolAddress((void**)&q, g_q);
    cudaGetSymbolAddress((void**)&k, g_k);
    cudaGetSymbolAddress((void**)&v, g_v);
    cudaGetSymbolAddress((void**)&ao, g_ao);
    cudaGetSymbolAddress((void**)&o, g_o);
    cudaGetSymbolAddress((void**)&h, g_h);
    cudaGetSymbolAddress((void**)&h2, g_h2);

    const int M = BB * NN;  // 8192
    const int attn_smem = ATTN_SMEM_FLOATS * sizeof(float);  // ~78.5 KB
    static int attn_attr_set = 0;
    if (!attn_attr_set) {
        cudaFuncSetAttribute(attn_kernel,
                             cudaFuncAttributeMaxDynamicSharedMemorySize, attn_smem);
        attn_attr_set = 1;
    }

    add_pos_kernel<<<(BB * NN * DD) / 256, 256>>>(input, input_v, pos_emb, x, xv);

    for (int i = 0; i < LL; i++) {
        const float* Wqi = Wq + (size_t)i * DD * DD;
        const float* Wki = Wk + (size_t)i * DD * DD;
        const float* Wvi = Wv + (size_t)i * DD * DD;
        const float* Woi = Wo + (size_t)i * DD * DD;
        const float* W1i = W1 + (size_t)i * DD * DFF;
        const float* W2i = W2 + (size_t)i * (DFF / 2) * (DD / 2);

        // QKV projections in one batched launch (z = 0,1,2)
        gemm_qkv_kernel<<<dim3(DD / GN, M / GM, 3), 256>>>(
            x, xv, Wqi, Wki, Wvi, bq + i * DD, bk + i * DD, bv + i * DD,
            q, k, v, M, DD, DD);

        // attention (32-query tiles)
        attn_kernel<<<dim3(NN / QT, HH, BB), 256, attn_smem>>>(
            q, k, v, mask, ao, (i % 2) ? 1 : 0);

        // output projection
        gemm128_kernel<<<dim3(DD / GN, M / GM), 256>>>(ao, Woi, bo + i * DD, o, M, DD, DD, 0);

        // x = LN(x + o)
        ln_kernel<<<M, 256>>>(x, o, g1 + i * DD, be1 + i * DD, x);

        // FFN1 + GELU
        gemm128_kernel<<<dim3(DFF / GN, M / GM), 256>>>(x, W1i, b1 + i * DFF, h, M, DD, DFF, 1);

        // FFN2 grouped: (B*N*2, 512) @ (512, 128) -> contiguous (B*N, 256)
        gemm128_kernel<<<dim3((DD / 2) / GN, (2 * M) / GM), 256>>>(
            h, W2i, b2 + i * (DD / 2), h2, 2 * M, DFF / 2, DD / 2, 0);

        // x = LN(x + h2)
        ln_kernel<<<M, 256>>>(x, h2, g2 + i * DD, be2 + i * DD, x);
    }

    // final LN -> output
    ln_kernel<<<M, 256>>>(x, nullptr, gf, bf, (float*)d_out);
}

// round 8
// speedup vs baseline: 1.9293x; 1.9293x over previous
#include <cuda_runtime.h>
#include <cuda_bf16.h>
#include <math.h>

#define BB 16
#define NN 512
#define DD 256
#define LL 4
#define HH 8
#define DK 32
#define DFF 1024

// ------------------------- scratch (device globals) -------------------------
__device__ float g_x[BB * NN * DD];
__device__ float g_xv[BB * NN * DD];
__device__ float g_q[BB * NN * DD];
__device__ float g_k[BB * NN * DD];
__device__ float g_v[BB * NN * DD];
__device__ float g_ao[BB * NN * DD];
__device__ float g_o[BB * NN * DD];
__device__ float g_h[BB * NN * DFF];
__device__ float g_h2[BB * NN * DD];

// ------------------------- add positional embedding -------------------------
__global__ void add_pos_kernel(const float* __restrict__ in,
                               const float* __restrict__ in_v,
                               const float* __restrict__ pos,
                               float* __restrict__ x, float* __restrict__ xv) {
    size_t i = (size_t)blockIdx.x * 256 + threadIdx.x;
    float p = pos[i % (NN * DD)];
    x[i]  = in[i]  + p;
    xv[i] = in_v[i] + p;
}

// ------------------- 128x128x8 double-buffered GEMM body --------------------
#define GM 128
#define GN 128
#define GKK 8

__device__ __forceinline__
void gemm128_body(const float* __restrict__ A,
                  const float* __restrict__ W,
                  const float* __restrict__ bias,
                  float* __restrict__ C,
                  int M, int K, int Nc, int apply_gelu) {
    __shared__ float As[2][GKK][GM];
    __shared__ float Bs[2][GKK][GN];
    const int tid = threadIdx.x;
    const int tx = tid & 15, ty = tid >> 4;
    const int row0 = blockIdx.y * GM, col0 = blockIdx.x * GN;

    const int arow = tid >> 1, ak0 = (tid & 1) * 4;
    const int brow = tid >> 5, bcol = (tid & 31) * 4;

    const float* Aptr = A + (size_t)(row0 + arow) * K + ak0;
    const float* Wptr = W + (size_t)brow * Nc + col0 + bcol;

    {
        float4 a4 = *(const float4*)Aptr;
        float4 b4 = *(const float4*)Wptr;
        As[0][ak0 + 0][arow] = a4.x;
        As[0][ak0 + 1][arow] = a4.y;
        As[0][ak0 + 2][arow] = a4.z;
        As[0][ak0 + 3][arow] = a4.w;
        *(float4*)&Bs[0][brow][bcol] = b4;
    }
    __syncthreads();

    float acc[8][8];
#pragma unroll
    for (int i = 0; i < 8; i++)
#pragma unroll
        for (int j = 0; j < 8; j++) acc[i][j] = 0.0f;

    int buf = 0;
    for (int k0 = 0; k0 < K; k0 += GKK) {
        const bool has_next = (k0 + GKK < K);
        float4 na, nb;
        if (has_next) {
            na = *(const float4*)(Aptr + k0 + GKK);
            nb = *(const float4*)(Wptr + (size_t)(k0 + GKK) * Nc);
        }
#pragma unroll
        for (int kk = 0; kk < GKK; kk++) {
            float a[8], b[8];
            *(float4*)(a)     = *(const float4*)&As[buf][kk][ty * 4];
            *(float4*)(a + 4) = *(const float4*)&As[buf][kk][64 + ty * 4];
            *(float4*)(b)     = *(const float4*)&Bs[buf][kk][tx * 4];
            *(float4*)(b + 4) = *(const float4*)&Bs[buf][kk][64 + tx * 4];
#pragma unroll
            for (int i = 0; i < 8; i++)
#pragma unroll
                for (int j = 0; j < 8; j++)
                    acc[i][j] += a[i] * b[j];
        }
        if (has_next) {
            As[buf ^ 1][ak0 + 0][arow] = na.x;
            As[buf ^ 1][ak0 + 1][arow] = na.y;
            As[buf ^ 1][ak0 + 2][arow] = na.z;
            As[buf ^ 1][ak0 + 3][arow] = na.w;
            *(float4*)&Bs[buf ^ 1][brow][bcol] = nb;
            __syncthreads();
            buf ^= 1;
        }
    }

    const int c0 = col0 + tx * 4;
    const int c1 = col0 + 64 + tx * 4;
    float4 bia0 = *(const float4*)&bias[c0];
    float4 bia1 = *(const float4*)&bias[c1];
#pragma unroll
    for (int i = 0; i < 8; i++) {
        int r = row0 + (i < 4 ? ty * 4 + i : 64 + ty * 4 + (i - 4));
        float o0[4] = {acc[i][0] + bia0.x, acc[i][1] + bia0.y,
                       acc[i][2] + bia0.z, acc[i][3] + bia0.w};
        float o1[4] = {acc[i][4] + bia1.x, acc[i][5] + bia1.y,
                       acc[i][6] + bia1.z, acc[i][7] + bia1.w};
        if (apply_gelu) {
#pragma unroll
            for (int j = 0; j < 4; j++) {
                o0[j] = 0.5f * o0[j] * (1.0f + erff(o0[j] * 0.70710678118654752f));
                o1[j] = 0.5f * o1[j] * (1.0f + erff(o1[j] * 0.70710678118654752f));
            }
        }
        *(float4*)&C[(size_t)r * Nc + c0] = *(float4*)o0;
        *(float4*)&C[(size_t)r * Nc + c1] = *(float4*)o1;
    }
}

__global__ __launch_bounds__(256, 2)
void gemm128_kernel(const float* __restrict__ A,
                    const float* __restrict__ W,
                    const float* __restrict__ bias,
                    float* __restrict__ C,
                    int M, int K, int Nc, int apply_gelu) {
    gemm128_body(A, W, bias, C, M, K, Nc, apply_gelu);
}

// Batched QKV: blockIdx.z selects {x@Wq, x@Wk, xv@Wv}. One launch, 3x grid.
__global__ __launch_bounds__(256, 2)
void gemm_qkv_kernel(const float* __restrict__ x, const float* __restrict__ xv,
                     const float* __restrict__ Wq, const float* __restrict__ Wk,
                     const float* __restrict__ Wv,
                     const float* __restrict__ bq, const float* __restrict__ bk,
                     const float* __restrict__ bv,
                     float* __restrict__ q, float* __restrict__ k,
                     float* __restrict__ v, int M, int K, int Nc) {
    const float* A;
    const float* W;
    const float* b;
    float* C;
    if (blockIdx.z == 0)      { A = x;  W = Wq; b = bq; C = q; }
    else if (blockIdx.z == 1) { A = x;  W = Wk; b = bk; C = k; }
    else                      { A = xv; W = Wv; b = bv; C = v; }
    gemm128_body(A, W, b, C, M, K, Nc, 0);
}

// ------------------------- fused attention -------------------------
// 16-query tiles, static smem (~43.6 KB -> ~5 CTAs/SM).
// grid (N/16, H, B), block 256. mask read as 32-bit words (nonzero == True).
__global__ void attn_kernel(const float* __restrict__ q,
                            const float* __restrict__ k,
                            const float* __restrict__ v,
                            const int* __restrict__ mask,
                            float* __restrict__ out, int use_mask) {
    const int b = blockIdx.z, h = blockIdx.y, q0 = blockIdx.x * 16;
    __shared__ float Qs[16][33];
    __shared__ float Kt[32][68];    // transposed K chunk: [d][key]
    __shared__ float S[16][512];
    const int tid = threadIdx.x;
    const float scale = 0.17677669529663687f;  // 1/sqrt(32)

    // load Q tile
    for (int e = tid; e < 16 * 32; e += 256) {
        int r = e >> 5, d = e & 31;
        Qs[r][d] = q[(size_t)(b * NN + q0 + r) * DD + h * DK + d];
    }

    // scores: thread handles row sr = tid>>4, cols scg*4..scg*4+3
    const int sr = tid >> 4;
    const int scg = tid & 15;
    for (int kc = 0; kc < NN; kc += 64) {
        __syncthreads();
        for (int e = tid; e < 64 * 32; e += 256) {
            int rr = e >> 5, d = e & 31;
            Kt[d][rr] = k[(size_t)(b * NN + kc + rr) * DD + h * DK + d];
        }
        __syncthreads();
        float a0 = 0.0f, a1 = 0.0f, a2 = 0.0f, a3 = 0.0f;
#pragma unroll
        for (int d = 0; d < DK; d++) {
            float qv = Qs[sr][d];
            float4 kv = *(const float4*)&Kt[d][scg * 4];
            a0 += qv * kv.x;
            a1 += qv * kv.y;
            a2 += qv * kv.z;
            a3 += qv * kv.w;
        }
        float s0 = a0 * scale, s1 = a1 * scale, s2 = a2 * scale, s3 = a3 * scale;
        if (use_mask) {
            int4 m4 = *(const int4*)&mask[(size_t)(q0 + sr) * NN + kc + scg * 4];
            if (m4.x) s0 = -1e30f;
            if (m4.y) s1 = -1e30f;
            if (m4.z) s2 = -1e30f;
            if (m4.w) s3 = -1e30f;
        }
        float4 sv = make_float4(s0, s1, s2, s3);
        *(float4*)&S[sr][kc + scg * 4] = sv;
    }
    __syncthreads();

    // softmax: 8 warps, 2 rows each
    const int warp = tid >> 5, lane = tid & 31;
    for (int r = warp; r < 16; r += 8) {
        float mx = -1e30f;
        for (int c = lane; c < NN; c += 32) mx = fmaxf(mx, S[r][c]);
#pragma unroll
        for (int o = 16; o; o >>= 1) mx = fmaxf(mx, __shfl_xor_sync(0xFFFFFFFFu, mx, o));
        float sum = 0.0f;
        for (int c = lane; c < NN; c += 32) {
            float e = __expf(S[r][c] - mx);
            S[r][c] = e;
            sum += e;
        }
#pragma unroll
        for (int o = 16; o; o >>= 1) sum += __shfl_xor_sync(0xFFFFFFFFu, sum, o);
        float inv = 1.0f / sum;
        for (int c = lane; c < NN; c += 32) S[r][c] *= inv;
    }
    __syncthreads();

    // O = P @ V.  thread (warp=r1, lane=d); also r2=r1+8.
    // kk unrolled x4: S rows read as float4 (LDS.128), 4 independent V LDGs.
    {
        const int d = tid & 31;
        const int r1 = tid >> 5;
        const int r2 = r1 + 8;
        float acc1 = 0.0f, acc2 = 0.0f;
        const float* vb = v + (size_t)b * NN * DD + h * DK + d;
        const float* S1 = &S[r1][0];
        const float* S2 = &S[r2][0];
#pragma unroll 2
        for (int kk = 0; kk < NN; kk += 4) {
            float4 s1 = *(const float4*)&S1[kk];
            float4 s2 = *(const float4*)&S2[kk];
            float v0 = vb[(size_t)(kk + 0) * DD];
            float v1 = vb[(size_t)(kk + 1) * DD];
            float v2 = vb[(size_t)(kk + 2) * DD];
            float v3 = vb[(size_t)(kk + 3) * DD];
            acc1 += s1.x * v0;
            acc2 += s2.x * v0;
            acc1 += s1.y * v1;
            acc2 += s2.y * v1;
            acc1 += s1.z * v2;
            acc2 += s2.z * v2;
            acc1 += s1.w * v3;
            acc2 += s2.w * v3;
        }
        out[(size_t)(b * NN + q0 + r1) * DD + h * DK + d] = acc1;
        out[(size_t)(b * NN + q0 + r2) * DD + h * DK + d] = acc2;
    }
}

// ------------------------- residual + layernorm -------------------------
__global__ void ln_kernel(const float* __restrict__ x,
                          const float* __restrict__ res,
                          const float* __restrict__ g,
                          const float* __restrict__ bta,
                          float* __restrict__ out) {
    const int row = blockIdx.x;
    const int i = threadIdx.x;
    const int warp = i >> 5, lane = i & 31;
    __shared__ float ps[8], ps2[8];
    size_t base = (size_t)row * DD;
    float val = x[base + i] + (res ? res[base + i] : 0.0f);
    float s = val, s2 = val * val;
#pragma unroll
    for (int o = 16; o; o >>= 1) {
        s  += __shfl_xor_sync(0xFFFFFFFFu, s, o);
        s2 += __shfl_xor_sync(0xFFFFFFFFu, s2, o);
    }
    if (lane == 0) { ps[warp] = s; ps2[warp] = s2; }
    __syncthreads();
    if (warp == 0) {
        float a = ps[lane & 7], a2 = ps2[lane & 7];
#pragma unroll
        for (int o = 4; o; o >>= 1) {
            a  += __shfl_xor_sync(0xFFFFFFFFu, a, o);
            a2 += __shfl_xor_sync(0xFFFFFFFFu, a2, o);
        }
        if (lane == 0) { ps[0] = a; ps2[0] = a2; }
    }
    __syncthreads();
    float mean = ps[0] * (1.0f / DD);
    float var = ps2[0] * (1.0f / DD) - mean * mean;
    out[base + i] = (val - mean) * rsqrtf(var + 1e-5f) * g[i] + bta[i];
}

// ------------------------- launch -------------------------
extern "C" void kernel_launch(void* const* d_in, const int* in_sizes, int n_in,
                              void* d_out, int out_size) {
    const float* input   = (const float*)d_in[0];
    const float* input_v = (const float*)d_in[1];
    const float* pos_emb = (const float*)d_in[2];
    const float* Wq = (const float*)d_in[3];
    const float* bq = (const float*)d_in[4];
    const float* Wk = (const float*)d_in[5];
    const float* bk = (const float*)d_in[6];
    const float* Wv = (const float*)d_in[7];
    const float* bv = (const float*)d_in[8];
    const float* Wo = (const float*)d_in[9];
    const float* bo = (const float*)d_in[10];
    const float* W1 = (const float*)d_in[11];
    const float* b1 = (const float*)d_in[12];
    const float* W2 = (const float*)d_in[13];
    const float* b2 = (const float*)d_in[14];
    const float* g1 = (const float*)d_in[15];
    const float* be1 = (const float*)d_in[16];
    const float* g2 = (const float*)d_in[17];
    const float* be2 = (const float*)d_in[18];
    const float* gf = (const float*)d_in[19];
    const float* bf = (const float*)d_in[20];
    const int* mask = (const int*)d_in[21];

    float *x, *xv, *q, *k, *v, *ao, *o, *h, *h2;
    cudaGetSymbolAddress((void**)&x, g_x);
    cudaGetSymbolAddress((void**)&xv, g_xv);
    cudaGetSymbolAddress((void**)&q, g_q);
    cudaGetSymbolAddress((void**)&k, g_k);
    cudaGetSymbolAddress((void**)&v, g_v);
    cudaGetSymbolAddress((void**)&ao, g_ao);
    cudaGetSymbolAddress((void**)&o, g_o);
    cudaGetSymbolAddress((void**)&h, g_h);
    cudaGetSymbolAddress((void**)&h2, g_h2);

    const int M = BB * NN;  // 8192

    add_pos_kernel<<<(BB * NN * DD) / 256, 256>>>(input, input_v, pos_emb, x, xv);

    for (int i = 0; i < LL; i++) {
        const float* Wqi = Wq + (size_t)i * DD * DD;
        const float* Wki = Wk + (size_t)i * DD * DD;
        const float* Wvi = Wv + (size_t)i * DD * DD;
        const float* Woi = Wo + (size_t)i * DD * DD;
        const float* W1i = W1 + (size_t)i * DD * DFF;
        const float* W2i = W2 + (size_t)i * (DFF / 2) * (DD / 2);

        // QKV projections in one batched launch (z = 0,1,2)
        gemm_qkv_kernel<<<dim3(DD / GN, M / GM, 3), 256>>>(
            x, xv, Wqi, Wki, Wvi, bq + i * DD, bk + i * DD, bv + i * DD,
            q, k, v, M, DD, DD);

        // attention (16-query tiles, static smem)
        attn_kernel<<<dim3(NN / 16, HH, BB), 256>>>(
            q, k, v, mask, ao, (i % 2) ? 1 : 0);

        // output projection
        gemm128_kernel<<<dim3(DD / GN, M / GM), 256>>>(ao, Woi, bo + i * DD, o, M, DD, DD, 0);

        // x = LN(x + o)
        ln_kernel<<<M, 256>>>(x, o, g1 + i * DD, be1 + i * DD, x);

        // FFN1 + GELU
        gemm128_kernel<<<dim3(DFF / GN, M / GM), 256>>>(x, W1i, b1 + i * DFF, h, M, DD, DFF, 1);

        // FFN2 grouped: (B*N*2, 512) @ (512, 128) -> contiguous (B*N, 256)
        gemm128_kernel<<<dim3((DD / 2) / GN, (2 * M) / GM), 256>>>(
            h, W2i, b2 + i * (DD / 2), h2, 2 * M, DFF / 2, DD / 2, 0);

        // x = LN(x + h2)
        ln_kernel<<<M, 256>>>(x, h2, g2 + i * DD, be2 + i * DD, x);
    }

    // final LN -> output
    ln_kernel<<<M, 256>>>(x, nullptr, gf, bf, (float*)d_out);
}

// round 9
// speedup vs baseline: 1.9774x; 1.0249x over previous
#include <cuda_runtime.h>
#include <cuda_bf16.h>
#include <math.h>

#define BB 16
#define NN 512
#define DD 256
#define LL 4
#define HH 8
#define DK 32
#define DFF 1024

typedef unsigned long long u64t;

// packed f32x2 helpers (FFMA2 path — ptxas never emits this from C++)
__device__ __forceinline__ u64t pack2(float lo, float hi) {
    u64t r;
    asm("mov.b64 %0, {%1, %2};" : "=l"(r) : "f"(lo), "f"(hi));
    return r;
}
__device__ __forceinline__ float2 unpack2(u64t p) {
    float lo, hi;
    asm("mov.b64 {%0, %1}, %2;" : "=f"(lo), "=f"(hi) : "l"(p));
    return make_float2(lo, hi);
}
#define FMA_F32X2(acc, a, b) \
    asm("fma.rn.f32x2 %0, %1, %2, %0;" : "+l"(acc) : "l"(a), "l"(b))

// ------------------------- scratch (device globals) -------------------------
__device__ float g_x[BB * NN * DD];
__device__ float g_xv[BB * NN * DD];
__device__ float g_q[BB * NN * DD];
__device__ float g_k[BB * NN * DD];
__device__ float g_v[BB * NN * DD];
__device__ float g_ao[BB * NN * DD];
__device__ float g_o[BB * NN * DD];
__device__ float g_h[BB * NN * DFF];
__device__ float g_h2[BB * NN * DD];

// ------------------------- add positional embedding -------------------------
__global__ void add_pos_kernel(const float* __restrict__ in,
                               const float* __restrict__ in_v,
                               const float* __restrict__ pos,
                               float* __restrict__ x, float* __restrict__ xv) {
    size_t i = (size_t)blockIdx.x * 256 + threadIdx.x;
    float p = pos[i % (NN * DD)];
    x[i]  = in[i]  + p;
    xv[i] = in_v[i] + p;
}

// ------------- 128x128x8 double-buffered GEMM body (FFMA2 core) -------------
#define GM 128
#define GN 128
#define GKK 8

__device__ __forceinline__
void gemm128_body(const float* __restrict__ A,
                  const float* __restrict__ W,
                  const float* __restrict__ bias,
                  float* __restrict__ C,
                  int M, int K, int Nc, int apply_gelu) {
    __shared__ float As[2][GKK][GM];
    __shared__ float Bs[2][GKK][GN];
    const int tid = threadIdx.x;
    const int tx = tid & 15, ty = tid >> 4;
    const int row0 = blockIdx.y * GM, col0 = blockIdx.x * GN;

    const int arow = tid >> 1, ak0 = (tid & 1) * 4;
    const int brow = tid >> 5, bcol = (tid & 31) * 4;

    const float* Aptr = A + (size_t)(row0 + arow) * K + ak0;
    const float* Wptr = W + (size_t)brow * Nc + col0 + bcol;

    {
        float4 a4 = *(const float4*)Aptr;
        float4 b4 = *(const float4*)Wptr;
        As[0][ak0 + 0][arow] = a4.x;
        As[0][ak0 + 1][arow] = a4.y;
        As[0][ak0 + 2][arow] = a4.z;
        As[0][ak0 + 3][arow] = a4.w;
        *(float4*)&Bs[0][brow][bcol] = b4;
    }
    __syncthreads();

    // acc2[ip][j]: row-pair ip (pairs: ty*4+{0,1}, ty*4+{2,3}, 64+ty*4+{0,1},
    // 64+ty*4+{2,3}), column j (8 cols: tx*4..+3 and 64+tx*4..+3)
    u64t acc2[4][8];
#pragma unroll
    for (int ip = 0; ip < 4; ip++)
#pragma unroll
        for (int j = 0; j < 8; j++) acc2[ip][j] = 0ULL;

    int buf = 0;
    for (int k0 = 0; k0 < K; k0 += GKK) {
        const bool has_next = (k0 + GKK < K);
        float4 na, nb;
        if (has_next) {
            na = *(const float4*)(Aptr + k0 + GKK);
            nb = *(const float4*)(Wptr + (size_t)(k0 + GKK) * Nc);
        }
#pragma unroll
        for (int kk = 0; kk < GKK; kk++) {
            // a row pairs straight from smem (16B-aligned float4 -> two f32x2)
            const ulonglong2 ap0 = *(const ulonglong2*)&As[buf][kk][ty * 4];
            const ulonglong2 ap1 = *(const ulonglong2*)&As[buf][kk][64 + ty * 4];
            float b[8];
            *(float4*)(b)     = *(const float4*)&Bs[buf][kk][tx * 4];
            *(float4*)(b + 4) = *(const float4*)&Bs[buf][kk][64 + tx * 4];
            u64t ap[4] = {ap0.x, ap0.y, ap1.x, ap1.y};
#pragma unroll
            for (int j = 0; j < 8; j++) {
                u64t bd = pack2(b[j], b[j]);
#pragma unroll
                for (int ip = 0; ip < 4; ip++)
                    FMA_F32X2(acc2[ip][j], ap[ip], bd);
            }
        }
        if (has_next) {
            As[buf ^ 1][ak0 + 0][arow] = na.x;
            As[buf ^ 1][ak0 + 1][arow] = na.y;
            As[buf ^ 1][ak0 + 2][arow] = na.z;
            As[buf ^ 1][ak0 + 3][arow] = na.w;
            *(float4*)&Bs[buf ^ 1][brow][bcol] = nb;
            __syncthreads();
            buf ^= 1;
        }
    }

    const int c0 = col0 + tx * 4;
    const int c1 = col0 + 64 + tx * 4;
    float4 bia0 = *(const float4*)&bias[c0];
    float4 bia1 = *(const float4*)&bias[c1];
    const float bi0[4] = {bia0.x, bia0.y, bia0.z, bia0.w};
    const float bi1[4] = {bia1.x, bia1.y, bia1.z, bia1.w};
#pragma unroll
    for (int ip = 0; ip < 4; ip++) {
        const int rbase = row0 + (ip < 2 ? ty * 4 + ip * 2 : 64 + ty * 4 + (ip - 2) * 2);
        float2 u[8];
#pragma unroll
        for (int j = 0; j < 8; j++) u[j] = unpack2(acc2[ip][j]);
#pragma unroll
        for (int hh = 0; hh < 2; hh++) {
            const int r = rbase + hh;
            float o0[4], o1[4];
#pragma unroll
            for (int j = 0; j < 4; j++) {
                o0[j] = (hh ? u[j].y : u[j].x) + bi0[j];
                o1[j] = (hh ? u[j + 4].y : u[j + 4].x) + bi1[j];
            }
            if (apply_gelu) {
#pragma unroll
                for (int j = 0; j < 4; j++) {
                    o0[j] = 0.5f * o0[j] * (1.0f + erff(o0[j] * 0.70710678118654752f));
                    o1[j] = 0.5f * o1[j] * (1.0f + erff(o1[j] * 0.70710678118654752f));
                }
            }
            *(float4*)&C[(size_t)r * Nc + c0] = *(float4*)o0;
            *(float4*)&C[(size_t)r * Nc + c1] = *(float4*)o1;
        }
    }
}

__global__ __launch_bounds__(256, 2)
void gemm128_kernel(const float* __restrict__ A,
                    const float* __restrict__ W,
                    const float* __restrict__ bias,
                    float* __restrict__ C,
                    int M, int K, int Nc, int apply_gelu) {
    gemm128_body(A, W, bias, C, M, K, Nc, apply_gelu);
}

// Batched QKV: blockIdx.z selects {x@Wq, x@Wk, xv@Wv}. One launch, 3x grid.
__global__ __launch_bounds__(256, 2)
void gemm_qkv_kernel(const float* __restrict__ x, const float* __restrict__ xv,
                     const float* __restrict__ Wq, const float* __restrict__ Wk,
                     const float* __restrict__ Wv,
                     const float* __restrict__ bq, const float* __restrict__ bk,
                     const float* __restrict__ bv,
                     float* __restrict__ q, float* __restrict__ k,
                     float* __restrict__ v, int M, int K, int Nc) {
    const float* A;
    const float* W;
    const float* b;
    float* C;
    if (blockIdx.z == 0)      { A = x;  W = Wq; b = bq; C = q; }
    else if (blockIdx.z == 1) { A = x;  W = Wk; b = bk; C = k; }
    else                      { A = xv; W = Wv; b = bv; C = v; }
    gemm128_body(A, W, b, C, M, K, Nc, 0);
}

// ------------------------- fused attention -------------------------
// 16-query tiles, static smem (~43.6 KB -> ~5 CTAs/SM).
// grid (N/16, H, B), block 256. mask read as 32-bit words (nonzero == True).
__global__ void attn_kernel(const float* __restrict__ q,
                            const float* __restrict__ k,
                            const float* __restrict__ v,
                            const int* __restrict__ mask,
                            float* __restrict__ out, int use_mask) {
    const int b = blockIdx.z, h = blockIdx.y, q0 = blockIdx.x * 16;
    __shared__ float Qs[16][33];
    __shared__ float Kt[32][68];    // transposed K chunk: [d][key]
    __shared__ float S[16][512];
    const int tid = threadIdx.x;
    const float scale = 0.17677669529663687f;  // 1/sqrt(32)

    // load Q tile
    for (int e = tid; e < 16 * 32; e += 256) {
        int r = e >> 5, d = e & 31;
        Qs[r][d] = q[(size_t)(b * NN + q0 + r) * DD + h * DK + d];
    }

    // scores: thread handles row sr = tid>>4, cols scg*4..scg*4+3 (FFMA2 pairs)
    const int sr = tid >> 4;
    const int scg = tid & 15;
    for (int kc = 0; kc < NN; kc += 64) {
        __syncthreads();
        for (int e = tid; e < 64 * 32; e += 256) {
            int rr = e >> 5, d = e & 31;
            Kt[d][rr] = k[(size_t)(b * NN + kc + rr) * DD + h * DK + d];
        }
        __syncthreads();
        u64t acc01 = 0ULL, acc23 = 0ULL;
#pragma unroll
        for (int d = 0; d < DK; d++) {
            float qv = Qs[sr][d];
            u64t qd = pack2(qv, qv);
            ulonglong2 kp = *(const ulonglong2*)&Kt[d][scg * 4];
            FMA_F32X2(acc01, qd, kp.x);
            FMA_F32X2(acc23, qd, kp.y);
        }
        float2 p01 = unpack2(acc01);
        float2 p23 = unpack2(acc23);
        float s0 = p01.x * scale, s1 = p01.y * scale;
        float s2 = p23.x * scale, s3 = p23.y * scale;
        if (use_mask) {
            int4 m4 = *(const int4*)&mask[(size_t)(q0 + sr) * NN + kc + scg * 4];
            if (m4.x) s0 = -1e30f;
            if (m4.y) s1 = -1e30f;
            if (m4.z) s2 = -1e30f;
            if (m4.w) s3 = -1e30f;
        }
        float4 sv = make_float4(s0, s1, s2, s3);
        *(float4*)&S[sr][kc + scg * 4] = sv;
    }
    __syncthreads();

    // softmax: 8 warps, 2 rows each
    const int warp = tid >> 5, lane = tid & 31;
    for (int r = warp; r < 16; r += 8) {
        float mx = -1e30f;
        for (int c = lane; c < NN; c += 32) mx = fmaxf(mx, S[r][c]);
#pragma unroll
        for (int o = 16; o; o >>= 1) mx = fmaxf(mx, __shfl_xor_sync(0xFFFFFFFFu, mx, o));
        float sum = 0.0f;
        for (int c = lane; c < NN; c += 32) {
            float e = __expf(S[r][c] - mx);
            S[r][c] = e;
            sum += e;
        }
#pragma unroll
        for (int o = 16; o; o >>= 1) sum += __shfl_xor_sync(0xFFFFFFFFu, sum, o);
        float inv = 1.0f / sum;
        for (int c = lane; c < NN; c += 32) S[r][c] *= inv;
    }
    __syncthreads();

    // O = P @ V.  thread (warp=r1, lane=d); also r2=r1+8.
    // kk unrolled x4: S rows read as float4 (LDS.128), 4 independent V LDGs.
    {
        const int d = tid & 31;
        const int r1 = tid >> 5;
        const int r2 = r1 + 8;
        float acc1 = 0.0f, acc2 = 0.0f;
        const float* vb = v + (size_t)b * NN * DD + h * DK + d;
        const float* S1 = &S[r1][0];
        const float* S2 = &S[r2][0];
#pragma unroll 2
        for (int kk = 0; kk < NN; kk += 4) {
            float4 s1 = *(const float4*)&S1[kk];
            float4 s2 = *(const float4*)&S2[kk];
            float v0 = vb[(size_t)(kk + 0) * DD];
            float v1 = vb[(size_t)(kk + 1) * DD];
            float v2 = vb[(size_t)(kk + 2) * DD];
            float v3 = vb[(size_t)(kk + 3) * DD];
            acc1 += s1.x * v0;
            acc2 += s2.x * v0;
            acc1 += s1.y * v1;
            acc2 += s2.y * v1;
            acc1 += s1.z * v2;
            acc2 += s2.z * v2;
            acc1 += s1.w * v3;
            acc2 += s2.w * v3;
        }
        out[(size_t)(b * NN + q0 + r1) * DD + h * DK + d] = acc1;
        out[(size_t)(b * NN + q0 + r2) * DD + h * DK + d] = acc2;
    }
}

// ------------------------- residual + layernorm -------------------------
__global__ void ln_kernel(const float* __restrict__ x,
                          const float* __restrict__ res,
                          const float* __restrict__ g,
                          const float* __restrict__ bta,
                          float* __restrict__ out) {
    const int row = blockIdx.x;
    const int i = threadIdx.x;
    const int warp = i >> 5, lane = i & 31;
    __shared__ float ps[8], ps2[8];
    size_t base = (size_t)row * DD;
    float val = x[base + i] + (res ? res[base + i] : 0.0f);
    float s = val, s2 = val * val;
#pragma unroll
    for (int o = 16; o; o >>= 1) {
        s  += __shfl_xor_sync(0xFFFFFFFFu, s, o);
        s2 += __shfl_xor_sync(0xFFFFFFFFu, s2, o);
    }
    if (lane == 0) { ps[warp] = s; ps2[warp] = s2; }
    __syncthreads();
    if (warp == 0) {
        float a = ps[lane & 7], a2 = ps2[lane & 7];
#pragma unroll
        for (int o = 4; o; o >>= 1) {
            a  += __shfl_xor_sync(0xFFFFFFFFu, a, o);
            a2 += __shfl_xor_sync(0xFFFFFFFFu, a2, o);
        }
        if (lane == 0) { ps[0] = a; ps2[0] = a2; }
    }
    __syncthreads();
    float mean = ps[0] * (1.0f / DD);
    float var = ps2[0] * (1.0f / DD) - mean * mean;
    out[base + i] = (val - mean) * rsqrtf(var + 1e-5f) * g[i] + bta[i];
}

// ------------------------- launch -------------------------
extern "C" void kernel_launch(void* const* d_in, const int* in_sizes, int n_in,
                              void* d_out, int out_size) {
    const float* input   = (const float*)d_in[0];
    const float* input_v = (const float*)d_in[1];
    const float* pos_emb = (const float*)d_in[2];
    const float* Wq = (const float*)d_in[3];
    const float* bq = (const float*)d_in[4];
    const float* Wk = (const float*)d_in[5];
    const float* bk = (const float*)d_in[6];
    const float* Wv = (const float*)d_in[7];
    const float* bv = (const float*)d_in[8];
    const float* Wo = (const float*)d_in[9];
    const float* bo = (const float*)d_in[10];
    const float* W1 = (const float*)d_in[11];
    const float* b1 = (const float*)d_in[12];
    const float* W2 = (const float*)d_in[13];
    const float* b2 = (const float*)d_in[14];
    const float* g1 = (const float*)d_in[15];
    const float* be1 = (const float*)d_in[16];
    const float* g2 = (const float*)d_in[17];
    const float* be2 = (const float*)d_in[18];
    const float* gf = (const float*)d_in[19];
    const float* bf = (const float*)d_in[20];
    const int* mask = (const int*)d_in[21];

    float *x, *xv, *q, *k, *v, *ao, *o, *h, *h2;
    cudaGetSymbolAddress((void**)&x, g_x);
    cudaGetSymbolAddress((void**)&xv, g_xv);
    cudaGetSymbolAddress((void**)&q, g_q);
    cudaGetSymbolAddress((void**)&k, g_k);
    cudaGetSymbolAddress((void**)&v, g_v);
    cudaGetSymbolAddress((void**)&ao, g_ao);
    cudaGetSymbolAddress((void**)&o, g_o);
    cudaGetSymbolAddress((void**)&h, g_h);
    cudaGetSymbolAddress((void**)&h2, g_h2);

    const int M = BB * NN;  // 8192

    add_pos_kernel<<<(BB * NN * DD) / 256, 256>>>(input, input_v, pos_emb, x, xv);

    for (int i = 0; i < LL; i++) {
        const float* Wqi = Wq + (size_t)i * DD * DD;
        const float* Wki = Wk + (size_t)i * DD * DD;
        const float* Wvi = Wv + (size_t)i * DD * DD;
        const float* Woi = Wo + (size_t)i * DD * DD;
        const float* W1i = W1 + (size_t)i * DD * DFF;
        const float* W2i = W2 + (size_t)i * (DFF / 2) * (DD / 2);

        // QKV projections in one batched launch (z = 0,1,2)
        gemm_qkv_kernel<<<dim3(DD / GN, M / GM, 3), 256>>>(
            x, xv, Wqi, Wki, Wvi, bq + i * DD, bk + i * DD, bv + i * DD,
            q, k, v, M, DD, DD);

        // attention (16-query tiles, static smem)
        attn_kernel<<<dim3(NN / 16, HH, BB), 256>>>(
            q, k, v, mask, ao, (i % 2) ? 1 : 0);

        // output projection
        gemm128_kernel<<<dim3(DD / GN, M / GM), 256>>>(ao, Woi, bo + i * DD, o, M, DD, DD, 0);

        // x = LN(x + o)
        ln_kernel<<<M, 256>>>(x, o, g1 + i * DD, be1 + i * DD, x);

        // FFN1 + GELU
        gemm128_kernel<<<dim3(DFF / GN, M / GM), 256>>>(x, W1i, b1 + i * DFF, h, M, DD, DFF, 1);

        // FFN2 grouped: (B*N*2, 512) @ (512, 128) -> contiguous (B*N, 256)
        gemm128_kernel<<<dim3((DD / 2) / GN, (2 * M) / GM), 256>>>(
            h, W2i, b2 + i * (DD / 2), h2, 2 * M, DFF / 2, DD / 2, 0);

        // x = LN(x + h2)
        ln_kernel<<<M, 256>>>(x, h2, g2 + i * DD, be2 + i * DD, x);
    }

    // final LN -> output
    ln_kernel<<<M, 256>>>(x, nullptr, gf, bf, (float*)d_out);
}

// round 10
// speedup vs baseline: 2.0037x; 1.0133x over previous
#include <cuda_runtime.h>
#include <cuda_bf16.h>
#include <math.h>

#define BB 16
#define NN 512
#define DD 256
#define LL 4
#define HH 8
#define DK 32
#define DFF 1024

typedef unsigned long long u64t;

// packed f32x2 helpers (FFMA2 path — ptxas never emits this from C++)
__device__ __forceinline__ u64t pack2(float lo, float hi) {
    u64t r;
    asm("mov.b64 %0, {%1, %2};" : "=l"(r) : "f"(lo), "f"(hi));
    return r;
}
__device__ __forceinline__ float2 unpack2(u64t p) {
    float lo, hi;
    asm("mov.b64 {%0, %1}, %2;" : "=f"(lo), "=f"(hi) : "l"(p));
    return make_float2(lo, hi);
}
#define FMA_F32X2(acc, a, b) \
    asm("fma.rn.f32x2 %0, %1, %2, %0;" : "+l"(acc) : "l"(a), "l"(b))

// ------------------------- scratch (device globals) -------------------------
__device__ float g_x[BB * NN * DD];
__device__ float g_xv[BB * NN * DD];
__device__ float g_q[BB * NN * DD];
__device__ float g_k[BB * NN * DD];
__device__ float g_v[BB * NN * DD];
__device__ float g_ao[BB * NN * DD];
__device__ float g_o[BB * NN * DD];
__device__ float g_h[BB * NN * DFF];
__device__ float g_h2[BB * NN * DD];

// ------------------------- add positional embedding -------------------------
__global__ void add_pos_kernel(const float* __restrict__ in,
                               const float* __restrict__ in_v,
                               const float* __restrict__ pos,
                               float* __restrict__ x, float* __restrict__ xv) {
    size_t i = (size_t)blockIdx.x * 256 + threadIdx.x;
    float p = pos[i % (NN * DD)];
    x[i]  = in[i]  + p;
    xv[i] = in_v[i] + p;
}

// ------------- 128x128x8 double-buffered GEMM body (FFMA2 core) -------------
#define GM 128
#define GN 128
#define GKK 8

__device__ __forceinline__
void gemm128_body(const float* __restrict__ A,
                  const float* __restrict__ W,
                  const float* __restrict__ bias,
                  float* __restrict__ C,
                  int M, int K, int Nc, int apply_gelu) {
    __shared__ float As[2][GKK][GM];
    __shared__ float Bs[2][GKK][GN];
    const int tid = threadIdx.x;
    const int tx = tid & 15, ty = tid >> 4;
    const int row0 = blockIdx.y * GM, col0 = blockIdx.x * GN;

    const int arow = tid >> 1, ak0 = (tid & 1) * 4;
    const int brow = tid >> 5, bcol = (tid & 31) * 4;

    const float* Aptr = A + (size_t)(row0 + arow) * K + ak0;
    const float* Wptr = W + (size_t)brow * Nc + col0 + bcol;

    {
        float4 a4 = *(const float4*)Aptr;
        float4 b4 = *(const float4*)Wptr;
        As[0][ak0 + 0][arow] = a4.x;
        As[0][ak0 + 1][arow] = a4.y;
        As[0][ak0 + 2][arow] = a4.z;
        As[0][ak0 + 3][arow] = a4.w;
        *(float4*)&Bs[0][brow][bcol] = b4;
    }
    __syncthreads();

    u64t acc2[4][8];
#pragma unroll
    for (int ip = 0; ip < 4; ip++)
#pragma unroll
        for (int j = 0; j < 8; j++) acc2[ip][j] = 0ULL;

    int buf = 0;
    for (int k0 = 0; k0 < K; k0 += GKK) {
        const bool has_next = (k0 + GKK < K);
        float4 na, nb;
        if (has_next) {
            na = *(const float4*)(Aptr + k0 + GKK);
            nb = *(const float4*)(Wptr + (size_t)(k0 + GKK) * Nc);
        }
#pragma unroll
        for (int kk = 0; kk < GKK; kk++) {
            const ulonglong2 ap0 = *(const ulonglong2*)&As[buf][kk][ty * 4];
            const ulonglong2 ap1 = *(const ulonglong2*)&As[buf][kk][64 + ty * 4];
            float b[8];
            *(float4*)(b)     = *(const float4*)&Bs[buf][kk][tx * 4];
            *(float4*)(b + 4) = *(const float4*)&Bs[buf][kk][64 + tx * 4];
            u64t ap[4] = {ap0.x, ap0.y, ap1.x, ap1.y};
#pragma unroll
            for (int j = 0; j < 8; j++) {
                u64t bd = pack2(b[j], b[j]);
#pragma unroll
                for (int ip = 0; ip < 4; ip++)
                    FMA_F32X2(acc2[ip][j], ap[ip], bd);
            }
        }
        if (has_next) {
            As[buf ^ 1][ak0 + 0][arow] = na.x;
            As[buf ^ 1][ak0 + 1][arow] = na.y;
            As[buf ^ 1][ak0 + 2][arow] = na.z;
            As[buf ^ 1][ak0 + 3][arow] = na.w;
            *(float4*)&Bs[buf ^ 1][brow][bcol] = nb;
            __syncthreads();
            buf ^= 1;
        }
    }

    const int c0 = col0 + tx * 4;
    const int c1 = col0 + 64 + tx * 4;
    float4 bia0 = *(const float4*)&bias[c0];
    float4 bia1 = *(const float4*)&bias[c1];
    const float bi0[4] = {bia0.x, bia0.y, bia0.z, bia0.w};
    const float bi1[4] = {bia1.x, bia1.y, bia1.z, bia1.w};
#pragma unroll
    for (int ip = 0; ip < 4; ip++) {
        const int rbase = row0 + (ip < 2 ? ty * 4 + ip * 2 : 64 + ty * 4 + (ip - 2) * 2);
        float2 u[8];
#pragma unroll
        for (int j = 0; j < 8; j++) u[j] = unpack2(acc2[ip][j]);
#pragma unroll
        for (int hh = 0; hh < 2; hh++) {
            const int r = rbase + hh;
            float o0[4], o1[4];
#pragma unroll
            for (int j = 0; j < 4; j++) {
                o0[j] = (hh ? u[j].y : u[j].x) + bi0[j];
                o1[j] = (hh ? u[j + 4].y : u[j + 4].x) + bi1[j];
            }
            if (apply_gelu) {
#pragma unroll
                for (int j = 0; j < 4; j++) {
                    o0[j] = 0.5f * o0[j] * (1.0f + erff(o0[j] * 0.70710678118654752f));
                    o1[j] = 0.5f * o1[j] * (1.0f + erff(o1[j] * 0.70710678118654752f));
                }
            }
            *(float4*)&C[(size_t)r * Nc + c0] = *(float4*)o0;
            *(float4*)&C[(size_t)r * Nc + c1] = *(float4*)o1;
        }
    }
}

__global__ __launch_bounds__(256, 2)
void gemm128_kernel(const float* __restrict__ A,
                    const float* __restrict__ W,
                    const float* __restrict__ bias,
                    float* __restrict__ C,
                    int M, int K, int Nc, int apply_gelu) {
    gemm128_body(A, W, bias, C, M, K, Nc, apply_gelu);
}

// Batched QKV: blockIdx.z selects {x@Wq, x@Wk, xv@Wv}. One launch, 3x grid.
__global__ __launch_bounds__(256, 2)
void gemm_qkv_kernel(const float* __restrict__ x, const float* __restrict__ xv,
                     const float* __restrict__ Wq, const float* __restrict__ Wk,
                     const float* __restrict__ Wv,
                     const float* __restrict__ bq, const float* __restrict__ bk,
                     const float* __restrict__ bv,
                     float* __restrict__ q, float* __restrict__ k,
                     float* __restrict__ v, int M, int K, int Nc) {
    const float* A;
    const float* W;
    const float* b;
    float* C;
    if (blockIdx.z == 0)      { A = x;  W = Wq; b = bq; C = q; }
    else if (blockIdx.z == 1) { A = x;  W = Wk; b = bk; C = k; }
    else                      { A = xv; W = Wv; b = bv; C = v; }
    gemm128_body(A, W, b, C, M, K, Nc, 0);
}

// ------------------------- fused attention -------------------------
// 16-query tiles, static smem (~43.6 KB -> ~5 CTAs/SM).
// grid (N/16, H, B), block 256. mask read as 32-bit words (nonzero == True).
// PV phase stages V chunks in smem (reuses the Kt buffer) instead of
// per-thread strided LDGs.
__global__ void attn_kernel(const float* __restrict__ q,
                            const float* __restrict__ k,
                            const float* __restrict__ v,
                            const int* __restrict__ mask,
                            float* __restrict__ out, int use_mask) {
    const int b = blockIdx.z, h = blockIdx.y, q0 = blockIdx.x * 16;
    __shared__ float Qs[16][33];
    __shared__ float Kt[32][68];    // score phase: transposed K chunk [d][key]
    __shared__ float S[16][512];
    float* Vb = &Kt[0][0];          // PV phase: V chunk [64][33] (2112 <= 2176)
    const int tid = threadIdx.x;
    const float scale = 0.17677669529663687f;  // 1/sqrt(32)

    // load Q tile
    for (int e = tid; e < 16 * 32; e += 256) {
        int r = e >> 5, d = e & 31;
        Qs[r][d] = q[(size_t)(b * NN + q0 + r) * DD + h * DK + d];
    }

    // scores: thread handles row sr = tid>>4, cols scg*4..scg*4+3 (FFMA2 pairs)
    const int sr = tid >> 4;
    const int scg = tid & 15;
    for (int kc = 0; kc < NN; kc += 64) {
        __syncthreads();
        for (int e = tid; e < 64 * 32; e += 256) {
            int rr = e >> 5, d = e & 31;
            Kt[d][rr] = k[(size_t)(b * NN + kc + rr) * DD + h * DK + d];
        }
        __syncthreads();
        u64t acc01 = 0ULL, acc23 = 0ULL;
#pragma unroll
        for (int d = 0; d < DK; d++) {
            float qv = Qs[sr][d];
            u64t qd = pack2(qv, qv);
            ulonglong2 kp = *(const ulonglong2*)&Kt[d][scg * 4];
            FMA_F32X2(acc01, qd, kp.x);
            FMA_F32X2(acc23, qd, kp.y);
        }
        float2 p01 = unpack2(acc01);
        float2 p23 = unpack2(acc23);
        float s0 = p01.x * scale, s1 = p01.y * scale;
        float s2 = p23.x * scale, s3 = p23.y * scale;
        if (use_mask) {
            int4 m4 = *(const int4*)&mask[(size_t)(q0 + sr) * NN + kc + scg * 4];
            if (m4.x) s0 = -1e30f;
            if (m4.y) s1 = -1e30f;
            if (m4.z) s2 = -1e30f;
            if (m4.w) s3 = -1e30f;
        }
        float4 sv = make_float4(s0, s1, s2, s3);
        *(float4*)&S[sr][kc + scg * 4] = sv;
    }
    __syncthreads();

    // softmax: 8 warps, 2 rows each
    const int warp = tid >> 5, lane = tid & 31;
    for (int r = warp; r < 16; r += 8) {
        float mx = -1e30f;
        for (int c = lane; c < NN; c += 32) mx = fmaxf(mx, S[r][c]);
#pragma unroll
        for (int o = 16; o; o >>= 1) mx = fmaxf(mx, __shfl_xor_sync(0xFFFFFFFFu, mx, o));
        float sum = 0.0f;
        for (int c = lane; c < NN; c += 32) {
            float e = __expf(S[r][c] - mx);
            S[r][c] = e;
            sum += e;
        }
#pragma unroll
        for (int o = 16; o; o >>= 1) sum += __shfl_xor_sync(0xFFFFFFFFu, sum, o);
        float inv = 1.0f / sum;
        for (int c = lane; c < NN; c += 32) S[r][c] *= inv;
    }

    // O = P @ V, chunked: stage V[64][32] in smem, accumulate from smem.
    // thread (warp=r1, lane=d); also r2=r1+8.
    {
        const int d = lane;
        const int r1 = warp;
        const int r2 = r1 + 8;
        float acc1 = 0.0f, acc2 = 0.0f;
        const float* S1 = &S[r1][0];
        const float* S2 = &S[r2][0];
        for (int kc = 0; kc < NN; kc += 64) {
            __syncthreads();   // previous chunk's reads done (also covers Kt->Vb reuse)
            for (int e = tid; e < 64 * 32; e += 256) {
                int rr = e >> 5, dd = e & 31;
                Vb[rr * 33 + dd] = v[(size_t)(b * NN + kc + rr) * DD + h * DK + dd];
            }
            __syncthreads();
#pragma unroll 4
            for (int kk = 0; kk < 64; kk += 4) {
                float4 s1 = *(const float4*)&S1[kc + kk];
                float4 s2 = *(const float4*)&S2[kc + kk];
                float v0 = Vb[(kk + 0) * 33 + d];
                float v1 = Vb[(kk + 1) * 33 + d];
                float v2 = Vb[(kk + 2) * 33 + d];
                float v3 = Vb[(kk + 3) * 33 + d];
                acc1 += s1.x * v0;
                acc2 += s2.x * v0;
                acc1 += s1.y * v1;
                acc2 += s2.y * v1;
                acc1 += s1.z * v2;
                acc2 += s2.z * v2;
                acc1 += s1.w * v3;
                acc2 += s2.w * v3;
            }
        }
        out[(size_t)(b * NN + q0 + r1) * DD + h * DK + d] = acc1;
        out[(size_t)(b * NN + q0 + r2) * DD + h * DK + d] = acc2;
    }
}

// ------------------------- residual + layernorm -------------------------
__global__ void ln_kernel(const float* __restrict__ x,
                          const float* __restrict__ res,
                          const float* __restrict__ g,
                          const float* __restrict__ bta,
                          float* __restrict__ out) {
    const int row = blockIdx.x;
    const int i = threadIdx.x;
    const int warp = i >> 5, lane = i & 31;
    __shared__ float ps[8], ps2[8];
    size_t base = (size_t)row * DD;
    float val = x[base + i] + (res ? res[base + i] : 0.0f);
    float s = val, s2 = val * val;
#pragma unroll
    for (int o = 16; o; o >>= 1) {
        s  += __shfl_xor_sync(0xFFFFFFFFu, s, o);
        s2 += __shfl_xor_sync(0xFFFFFFFFu, s2, o);
    }
    if (lane == 0) { ps[warp] = s; ps2[warp] = s2; }
    __syncthreads();
    if (warp == 0) {
        float a = ps[lane & 7], a2 = ps2[lane & 7];
#pragma unroll
        for (int o = 4; o; o >>= 1) {
            a  += __shfl_xor_sync(0xFFFFFFFFu, a, o);
            a2 += __shfl_xor_sync(0xFFFFFFFFu, a2, o);
        }
        if (lane == 0) { ps[0] = a; ps2[0] = a2; }
    }
    __syncthreads();
    float mean = ps[0] * (1.0f / DD);
    float var = ps2[0] * (1.0f / DD) - mean * mean;
    out[base + i] = (val - mean) * rsqrtf(var + 1e-5f) * g[i] + bta[i];
}

// ------------------------- launch -------------------------
extern "C" void kernel_launch(void* const* d_in, const int* in_sizes, int n_in,
                              void* d_out, int out_size) {
    const float* input   = (const float*)d_in[0];
    const float* input_v = (const float*)d_in[1];
    const float* pos_emb = (const float*)d_in[2];
    const float* Wq = (const float*)d_in[3];
    const float* bq = (const float*)d_in[4];
    const float* Wk = (const float*)d_in[5];
    const float* bk = (const float*)d_in[6];
    const float* Wv = (const float*)d_in[7];
    const float* bv = (const float*)d_in[8];
    const float* Wo = (const float*)d_in[9];
    const float* bo = (const float*)d_in[10];
    const float* W1 = (const float*)d_in[11];
    const float* b1 = (const float*)d_in[12];
    const float* W2 = (const float*)d_in[13];
    const float* b2 = (const float*)d_in[14];
    const float* g1 = (const float*)d_in[15];
    const float* be1 = (const float*)d_in[16];
    const float* g2 = (const float*)d_in[17];
    const float* be2 = (const float*)d_in[18];
    const float* gf = (const float*)d_in[19];
    const float* bf = (const float*)d_in[20];
    const int* mask = (const int*)d_in[21];

    float *x, *xv, *q, *k, *v, *ao, *o, *h, *h2;
    cudaGetSymbolAddress((void**)&x, g_x);
    cudaGetSymbolAddress((void**)&xv, g_xv);
    cudaGetSymbolAddress((void**)&q, g_q);
    cudaGetSymbolAddress((void**)&k, g_k);
    cudaGetSymbolAddress((void**)&v, g_v);
    cudaGetSymbolAddress((void**)&ao, g_ao);
    cudaGetSymbolAddress((void**)&o, g_o);
    cudaGetSymbolAddress((void**)&h, g_h);
    cudaGetSymbolAddress((void**)&h2, g_h2);

    const int M = BB * NN;  // 8192

    add_pos_kernel<<<(BB * NN * DD) / 256, 256>>>(input, input_v, pos_emb, x, xv);

    for (int i = 0; i < LL; i++) {
        const float* Wqi = Wq + (size_t)i * DD * DD;
        const float* Wki = Wk + (size_t)i * DD * DD;
        const float* Wvi = Wv + (size_t)i * DD * DD;
        const float* Woi = Wo + (size_t)i * DD * DD;
        const float* W1i = W1 + (size_t)i * DD * DFF;
        const float* W2i = W2 + (size_t)i * (DFF / 2) * (DD / 2);

        // QKV projections in one batched launch (z = 0,1,2)
        gemm_qkv_kernel<<<dim3(DD / GN, M / GM, 3), 256>>>(
            x, xv, Wqi, Wki, Wvi, bq + i * DD, bk + i * DD, bv + i * DD,
            q, k, v, M, DD, DD);

        // attention (16-query tiles, smem-staged V)
        attn_kernel<<<dim3(NN / 16, HH, BB), 256>>>(
            q, k, v, mask, ao, (i % 2) ? 1 : 0);

        // output projection
        gemm128_kernel<<<dim3(DD / GN, M / GM), 256>>>(ao, Woi, bo + i * DD, o, M, DD, DD, 0);

        // x = LN(x + o)
        ln_kernel<<<M, 256>>>(x, o, g1 + i * DD, be1 + i * DD, x);

        // FFN1 + GELU
        gemm128_kernel<<<dim3(DFF / GN, M / GM), 256>>>(x, W1i, b1 + i * DFF, h, M, DD, DFF, 1);

        // FFN2 grouped: (B*N*2, 512) @ (512, 128) -> contiguous (B*N, 256)
        gemm128_kernel<<<dim3((DD / 2) / GN, (2 * M) / GM), 256>>>(
            h, W2i, b2 + i * (DD / 2), h2, 2 * M, DFF / 2, DD / 2, 0);

        // x = LN(x + h2)
        ln_kernel<<<M, 256>>>(x, h2, g2 + i * DD, be2 + i * DD, x);
    }

    // final LN -> output
    ln_kernel<<<M, 256>>>(x, nullptr, gf, bf, (float*)d_out);
}

// round 11
// speedup vs baseline: 2.2863x; 1.1410x over previous
#include <cuda_runtime.h>
#include <cuda_bf16.h>
#include <math.h>

#define BB 16
#define NN 512
#define DD 256
#define LL 4
#define HH 8
#define DK 32
#define DFF 1024

typedef unsigned long long u64t;

// packed f32x2 helpers (used in attention score phase)
__device__ __forceinline__ u64t pack2(float lo, float hi) {
    u64t r;
    asm("mov.b64 %0, {%1, %2};" : "=l"(r) : "f"(lo), "f"(hi));
    return r;
}
__device__ __forceinline__ float2 unpack2(u64t p) {
    float lo, hi;
    asm("mov.b64 {%0, %1}, %2;" : "=f"(lo), "=f"(hi) : "l"(p));
    return make_float2(lo, hi);
}
#define FMA_F32X2(acc, a, b) \
    asm("fma.rn.f32x2 %0, %1, %2, %0;" : "+l"(acc) : "l"(a), "l"(b))

// tf32 round (rna) — result is a valid fp32 bit pattern with truncated mantissa
__device__ __forceinline__ float tf32r(float f) {
    unsigned r;
    asm("cvt.rna.tf32.f32 %0, %1;" : "=r"(r) : "f"(f));
    return __uint_as_float(r);
}

// m16n8k8 tf32 MMA, D += A*B (accumulate in place)
#define MMA_TF32(d, a0, a1, a2, a3, b0, b1)                          \
    asm("mma.sync.aligned.m16n8k8.row.col.f32.tf32.tf32.f32 "        \
        "{%0,%1,%2,%3}, {%4,%5,%6,%7}, {%8,%9}, {%0,%1,%2,%3};"      \
        : "+f"((d)[0]), "+f"((d)[1]), "+f"((d)[2]), "+f"((d)[3])     \
        : "r"(a0), "r"(a1), "r"(a2), "r"(a3), "r"(b0), "r"(b1))

// ------------------------- scratch (device globals) -------------------------
__device__ float g_x[BB * NN * DD];
__device__ float g_xv[BB * NN * DD];
__device__ float g_q[BB * NN * DD];
__device__ float g_k[BB * NN * DD];
__device__ float g_v[BB * NN * DD];
__device__ float g_ao[BB * NN * DD];
__device__ float g_o[BB * NN * DD];
__device__ float g_h[BB * NN * DFF];
__device__ float g_h2[BB * NN * DD];

// ------------------------- add positional embedding -------------------------
__global__ void add_pos_kernel(const float* __restrict__ in,
                               const float* __restrict__ in_v,
                               const float* __restrict__ pos,
                               float* __restrict__ x, float* __restrict__ xv) {
    size_t i = (size_t)blockIdx.x * 256 + threadIdx.x;
    float p = pos[i % (NN * DD)];
    x[i]  = in[i]  + p;
    xv[i] = in_v[i] + p;
}

// --------- 128x128x8 double-buffered GEMM body (tf32 tensor core) -----------
// A,W staged to smem with tf32 rounding; fp32 accumulation via mma.sync.
#define GM 128
#define GN 128
#define GKK 8
#define SP 136   // padded row: bank = (k*8 + idx) % 32 -> conflict-free frags

__device__ __forceinline__
void gemm128_body(const float* __restrict__ A,
                  const float* __restrict__ W,
                  const float* __restrict__ bias,
                  float* __restrict__ C,
                  int M, int K, int Nc, int apply_gelu) {
    __shared__ float As[2][GKK][SP];   // [k][row]
    __shared__ float Bs[2][GKK][SP];   // [k][col]
    const int tid = threadIdx.x;
    const int lane = tid & 31, warp = tid >> 5;
    const int wm = (warp & 3) * 32;    // warp row offset (4 warps in m)
    const int wn = (warp >> 2) * 64;   // warp col offset (2 warps in n)
    const int gID = lane >> 2, tq = lane & 3;
    const int row0 = blockIdx.y * GM, col0 = blockIdx.x * GN;

    const int arow = tid >> 1, ak0 = (tid & 1) * 4;
    const int brow = tid >> 5, bcol = (tid & 31) * 4;

    const float* Aptr = A + (size_t)(row0 + arow) * K + ak0;
    const float* Wptr = W + (size_t)brow * Nc + col0 + bcol;

    {
        float4 a4 = *(const float4*)Aptr;
        float4 b4 = *(const float4*)Wptr;
        As[0][ak0 + 0][arow] = tf32r(a4.x);
        As[0][ak0 + 1][arow] = tf32r(a4.y);
        As[0][ak0 + 2][arow] = tf32r(a4.z);
        As[0][ak0 + 3][arow] = tf32r(a4.w);
        float4 bc = make_float4(tf32r(b4.x), tf32r(b4.y), tf32r(b4.z), tf32r(b4.w));
        *(float4*)&Bs[0][brow][bcol] = bc;
    }
    __syncthreads();

    float acc[2][8][4];
#pragma unroll
    for (int mf = 0; mf < 2; mf++)
#pragma unroll
        for (int nf = 0; nf < 8; nf++)
#pragma unroll
            for (int c = 0; c < 4; c++) acc[mf][nf][c] = 0.0f;

    int buf = 0;
    for (int k0 = 0; k0 < K; k0 += GKK) {
        const bool has_next = (k0 + GKK < K);
        float4 na, nb;
        if (has_next) {
            na = *(const float4*)(Aptr + k0 + GKK);
            nb = *(const float4*)(Wptr + (size_t)(k0 + GKK) * Nc);
        }

        // A fragments for both 16-row frags of this warp
        unsigned af[2][4];
#pragma unroll
        for (int mf = 0; mf < 2; mf++) {
            const int rb = wm + mf * 16 + gID;
            af[mf][0] = __float_as_uint(As[buf][tq][rb]);
            af[mf][1] = __float_as_uint(As[buf][tq][rb + 8]);
            af[mf][2] = __float_as_uint(As[buf][tq + 4][rb]);
            af[mf][3] = __float_as_uint(As[buf][tq + 4][rb + 8]);
        }
#pragma unroll
        for (int nf = 0; nf < 8; nf++) {
            const int cb = wn + nf * 8 + gID;
            unsigned b0 = __float_as_uint(Bs[buf][tq][cb]);
            unsigned b1 = __float_as_uint(Bs[buf][tq + 4][cb]);
            MMA_TF32(acc[0][nf], af[0][0], af[0][1], af[0][2], af[0][3], b0, b1);
            MMA_TF32(acc[1][nf], af[1][0], af[1][1], af[1][2], af[1][3], b0, b1);
        }

        if (has_next) {
            As[buf ^ 1][ak0 + 0][arow] = tf32r(na.x);
            As[buf ^ 1][ak0 + 1][arow] = tf32r(na.y);
            As[buf ^ 1][ak0 + 2][arow] = tf32r(na.z);
            As[buf ^ 1][ak0 + 3][arow] = tf32r(na.w);
            float4 bc = make_float4(tf32r(nb.x), tf32r(nb.y), tf32r(nb.z), tf32r(nb.w));
            *(float4*)&Bs[buf ^ 1][brow][bcol] = bc;
            __syncthreads();
            buf ^= 1;
        }
    }

    // epilogue: C fragment layout -> bias (+gelu) -> float2 stores
#pragma unroll
    for (int mf = 0; mf < 2; mf++) {
        const int r0 = row0 + wm + mf * 16 + gID;
#pragma unroll
        for (int nf = 0; nf < 8; nf++) {
            const int c = col0 + wn + nf * 8 + tq * 2;
            const float bx = bias[c], by = bias[c + 1];
            float v0 = acc[mf][nf][0] + bx;
            float v1 = acc[mf][nf][1] + by;
            float v2 = acc[mf][nf][2] + bx;
            float v3 = acc[mf][nf][3] + by;
            if (apply_gelu) {
                v0 = 0.5f * v0 * (1.0f + erff(v0 * 0.70710678118654752f));
                v1 = 0.5f * v1 * (1.0f + erff(v1 * 0.70710678118654752f));
                v2 = 0.5f * v2 * (1.0f + erff(v2 * 0.70710678118654752f));
                v3 = 0.5f * v3 * (1.0f + erff(v3 * 0.70710678118654752f));
            }
            *(float2*)&C[(size_t)r0 * Nc + c] = make_float2(v0, v1);
            *(float2*)&C[(size_t)(r0 + 8) * Nc + c] = make_float2(v2, v3);
        }
    }
}

__global__ __launch_bounds__(256, 2)
void gemm128_kernel(const float* __restrict__ A,
                    const float* __restrict__ W,
                    const float* __restrict__ bias,
                    float* __restrict__ C,
                    int M, int K, int Nc, int apply_gelu) {
    gemm128_body(A, W, bias, C, M, K, Nc, apply_gelu);
}

// Batched QKV: blockIdx.z selects {x@Wq, x@Wk, xv@Wv}. One launch, 3x grid.
__global__ __launch_bounds__(256, 2)
void gemm_qkv_kernel(const float* __restrict__ x, const float* __restrict__ xv,
                     const float* __restrict__ Wq, const float* __restrict__ Wk,
                     const float* __restrict__ Wv,
                     const float* __restrict__ bq, const float* __restrict__ bk,
                     const float* __restrict__ bv,
                     float* __restrict__ q, float* __restrict__ k,
                     float* __restrict__ v, int M, int K, int Nc) {
    const float* A;
    const float* W;
    const float* b;
    float* C;
    if (blockIdx.z == 0)      { A = x;  W = Wq; b = bq; C = q; }
    else if (blockIdx.z == 1) { A = x;  W = Wk; b = bk; C = k; }
    else                      { A = xv; W = Wv; b = bv; C = v; }
    gemm128_body(A, W, b, C, M, K, Nc, 0);
}

// ------------------------- fused attention -------------------------
// 16-query tiles, static smem (~43.6 KB -> ~5 CTAs/SM).
// grid (N/16, H, B), block 256. mask read as 32-bit words (nonzero == True).
__global__ void attn_kernel(const float* __restrict__ q,
                            const float* __restrict__ k,
                            const float* __restrict__ v,
                            const int* __restrict__ mask,
                            float* __restrict__ out, int use_mask) {
    const int b = blockIdx.z, h = blockIdx.y, q0 = blockIdx.x * 16;
    __shared__ float Qs[16][33];
    __shared__ float Kt[32][68];    // score phase: transposed K chunk [d][key]
    __shared__ float S[16][512];
    float* Vb = &Kt[0][0];          // PV phase: V chunk [64][33] (2112 <= 2176)
    const int tid = threadIdx.x;
    const float scale = 0.17677669529663687f;  // 1/sqrt(32)

    // load Q tile
    for (int e = tid; e < 16 * 32; e += 256) {
        int r = e >> 5, d = e & 31;
        Qs[r][d] = q[(size_t)(b * NN + q0 + r) * DD + h * DK + d];
    }

    // scores: thread handles row sr = tid>>4, cols scg*4..scg*4+3 (FFMA2 pairs)
    const int sr = tid >> 4;
    const int scg = tid & 15;
    for (int kc = 0; kc < NN; kc += 64) {
        __syncthreads();
        for (int e = tid; e < 64 * 32; e += 256) {
            int rr = e >> 5, d = e & 31;
            Kt[d][rr] = k[(size_t)(b * NN + kc + rr) * DD + h * DK + d];
        }
        __syncthreads();
        u64t acc01 = 0ULL, acc23 = 0ULL;
#pragma unroll
        for (int d = 0; d < DK; d++) {
            float qv = Qs[sr][d];
            u64t qd = pack2(qv, qv);
            ulonglong2 kp = *(const ulonglong2*)&Kt[d][scg * 4];
            FMA_F32X2(acc01, qd, kp.x);
            FMA_F32X2(acc23, qd, kp.y);
        }
        float2 p01 = unpack2(acc01);
        float2 p23 = unpack2(acc23);
        float s0 = p01.x * scale, s1 = p01.y * scale;
        float s2 = p23.x * scale, s3 = p23.y * scale;
        if (use_mask) {
            int4 m4 = *(const int4*)&mask[(size_t)(q0 + sr) * NN + kc + scg * 4];
            if (m4.x) s0 = -1e30f;
            if (m4.y) s1 = -1e30f;
            if (m4.z) s2 = -1e30f;
            if (m4.w) s3 = -1e30f;
        }
        float4 sv = make_float4(s0, s1, s2, s3);
        *(float4*)&S[sr][kc + scg * 4] = sv;
    }
    __syncthreads();

    // softmax: 8 warps, 2 rows each
    const int warp = tid >> 5, lane = tid & 31;
    for (int r = warp; r < 16; r += 8) {
        float mx = -1e30f;
        for (int c = lane; c < NN; c += 32) mx = fmaxf(mx, S[r][c]);
#pragma unroll
        for (int o = 16; o; o >>= 1) mx = fmaxf(mx, __shfl_xor_sync(0xFFFFFFFFu, mx, o));
        float sum = 0.0f;
        for (int c = lane; c < NN; c += 32) {
            float e = __expf(S[r][c] - mx);
            S[r][c] = e;
            sum += e;
        }
#pragma unroll
        for (int o = 16; o; o >>= 1) sum += __shfl_xor_sync(0xFFFFFFFFu, sum, o);
        float inv = 1.0f / sum;
        for (int c = lane; c < NN; c += 32) S[r][c] *= inv;
    }

    // O = P @ V, chunked: stage V[64][32] in smem, accumulate from smem.
    {
        const int d = lane;
        const int r1 = warp;
        const int r2 = r1 + 8;
        float acc1 = 0.0f, acc2 = 0.0f;
        const float* S1 = &S[r1][0];
        const float* S2 = &S[r2][0];
        for (int kc = 0; kc < NN; kc += 64) {
            __syncthreads();
            for (int e = tid; e < 64 * 32; e += 256) {
                int rr = e >> 5, dd = e & 31;
                Vb[rr * 33 + dd] = v[(size_t)(b * NN + kc + rr) * DD + h * DK + dd];
            }
            __syncthreads();
#pragma unroll 4
            for (int kk = 0; kk < 64; kk += 4) {
                float4 s1 = *(const float4*)&S1[kc + kk];
                float4 s2 = *(const float4*)&S2[kc + kk];
                float v0 = Vb[(kk + 0) * 33 + d];
                float v1 = Vb[(kk + 1) * 33 + d];
                float v2 = Vb[(kk + 2) * 33 + d];
                float v3 = Vb[(kk + 3) * 33 + d];
                acc1 += s1.x * v0;
                acc2 += s2.x * v0;
                acc1 += s1.y * v1;
                acc2 += s2.y * v1;
                acc1 += s1.z * v2;
                acc2 += s2.z * v2;
                acc1 += s1.w * v3;
                acc2 += s2.w * v3;
            }
        }
        out[(size_t)(b * NN + q0 + r1) * DD + h * DK + d] = acc1;
        out[(size_t)(b * NN + q0 + r2) * DD + h * DK + d] = acc2;
    }
}

// ------------------------- residual + layernorm -------------------------
__global__ void ln_kernel(const float* __restrict__ x,
                          const float* __restrict__ res,
                          const float* __restrict__ g,
                          const float* __restrict__ bta,
                          float* __restrict__ out) {
    const int row = blockIdx.x;
    const int i = threadIdx.x;
    const int warp = i >> 5, lane = i & 31;
    __shared__ float ps[8], ps2[8];
    size_t base = (size_t)row * DD;
    float val = x[base + i] + (res ? res[base + i] : 0.0f);
    float s = val, s2 = val * val;
#pragma unroll
    for (int o = 16; o; o >>= 1) {
        s  += __shfl_xor_sync(0xFFFFFFFFu, s, o);
        s2 += __shfl_xor_sync(0xFFFFFFFFu, s2, o);
    }
    if (lane == 0) { ps[warp] = s; ps2[warp] = s2; }
    __syncthreads();
    if (warp == 0) {
        float a = ps[lane & 7], a2 = ps2[lane & 7];
#pragma unroll
        for (int o = 4; o; o >>= 1) {
            a  += __shfl_xor_sync(0xFFFFFFFFu, a, o);
            a2 += __shfl_xor_sync(0xFFFFFFFFu, a2, o);
        }
        if (lane == 0) { ps[0] = a; ps2[0] = a2; }
    }
    __syncthreads();
    float mean = ps[0] * (1.0f / DD);
    float var = ps2[0] * (1.0f / DD) - mean * mean;
    out[base + i] = (val - mean) * rsqrtf(var + 1e-5f) * g[i] + bta[i];
}

// ------------------------- launch -------------------------
extern "C" void kernel_launch(void* const* d_in, const int* in_sizes, int n_in,
                              void* d_out, int out_size) {
    const float* input   = (const float*)d_in[0];
    const float* input_v = (const float*)d_in[1];
    const float* pos_emb = (const float*)d_in[2];
    const float* Wq = (const float*)d_in[3];
    const float* bq = (const float*)d_in[4];
    const float* Wk = (const float*)d_in[5];
    const float* bk = (const float*)d_in[6];
    const float* Wv = (const float*)d_in[7];
    const float* bv = (const float*)d_in[8];
    const float* Wo = (const float*)d_in[9];
    const float* bo = (const float*)d_in[10];
    const float* W1 = (const float*)d_in[11];
    const float* b1 = (const float*)d_in[12];
    const float* W2 = (const float*)d_in[13];
    const float* b2 = (const float*)d_in[14];
    const float* g1 = (const float*)d_in[15];
    const float* be1 = (const float*)d_in[16];
    const float* g2 = (const float*)d_in[17];
    const float* be2 = (const float*)d_in[18];
    const float* gf = (const float*)d_in[19];
    const float* bf = (const float*)d_in[20];
    const int* mask = (const int*)d_in[21];

    float *x, *xv, *q, *k, *v, *ao, *o, *h, *h2;
    cudaGetSymbolAddress((void**)&x, g_x);
    cudaGetSymbolAddress((void**)&xv, g_xv);
    cudaGetSymbolAddress((void**)&q, g_q);
    cudaGetSymbolAddress((void**)&k, g_k);
    cudaGetSymbolAddress((void**)&v, g_v);
    cudaGetSymbolAddress((void**)&ao, g_ao);
    cudaGetSymbolAddress((void**)&o, g_o);
    cudaGetSymbolAddress((void**)&h, g_h);
    cudaGetSymbolAddress((void**)&h2, g_h2);

    const int M = BB * NN;  // 8192

    add_pos_kernel<<<(BB * NN * DD) / 256, 256>>>(input, input_v, pos_emb, x, xv);

    for (int i = 0; i < LL; i++) {
        const float* Wqi = Wq + (size_t)i * DD * DD;
        const float* Wki = Wk + (size_t)i * DD * DD;
        const float* Wvi = Wv + (size_t)i * DD * DD;
        const float* Woi = Wo + (size_t)i * DD * DD;
        const float* W1i = W1 + (size_t)i * DD * DFF;
        const float* W2i = W2 + (size_t)i * (DFF / 2) * (DD / 2);

        // QKV projections in one batched launch (z = 0,1,2)
        gemm_qkv_kernel<<<dim3(DD / GN, M / GM, 3), 256>>>(
            x, xv, Wqi, Wki, Wvi, bq + i * DD, bk + i * DD, bv + i * DD,
            q, k, v, M, DD, DD);

        // attention (16-query tiles, smem-staged V)
        attn_kernel<<<dim3(NN / 16, HH, BB), 256>>>(
            q, k, v, mask, ao, (i % 2) ? 1 : 0);

        // output projection
        gemm128_kernel<<<dim3(DD / GN, M / GM), 256>>>(ao, Woi, bo + i * DD, o, M, DD, DD, 0);

        // x = LN(x + o)
        ln_kernel<<<M, 256>>>(x, o, g1 + i * DD, be1 + i * DD, x);

        // FFN1 + GELU
        gemm128_kernel<<<dim3(DFF / GN, M / GM), 256>>>(x, W1i, b1 + i * DFF, h, M, DD, DFF, 1);

        // FFN2 grouped: (B*N*2, 512) @ (512, 128) -> contiguous (B*N, 256)
        gemm128_kernel<<<dim3((DD / 2) / GN, (2 * M) / GM), 256>>>(
            h, W2i, b2 + i * (DD / 2), h2, 2 * M, DFF / 2, DD / 2, 0);

        // x = LN(x + h2)
        ln_kernel<<<M, 256>>>(x, h2, g2 + i * DD, be2 + i * DD, x);
    }

    // final LN -> output
    ln_kernel<<<M, 256>>>(x, nullptr, gf, bf, (float*)d_out);
}

// round 13
// speedup vs baseline: 2.4818x; 1.0855x over previous
#include <cuda_runtime.h>
#include <cuda_bf16.h>
#include <math.h>

#define BB 16
#define NN 512
#define DD 256
#define LL 4
#define HH 8
#define DK 32
#define DFF 1024

typedef unsigned long long u64t;

// packed f32x2 helpers (used in attention score phase)
__device__ __forceinline__ u64t pack2(float lo, float hi) {
    u64t r;
    asm("mov.b64 %0, {%1, %2};" : "=l"(r) : "f"(lo), "f"(hi));
    return r;
}
__device__ __forceinline__ float2 unpack2(u64t p) {
    float lo, hi;
    asm("mov.b64 {%0, %1}, %2;" : "=f"(lo), "=f"(hi) : "l"(p));
    return make_float2(lo, hi);
}
#define FMA_F32X2(acc, a, b) \
    asm("fma.rn.f32x2 %0, %1, %2, %0;" : "+l"(acc) : "l"(a), "l"(b))

// tf32 round (rna) — result is a valid fp32 bit pattern with truncated mantissa
__device__ __forceinline__ float tf32r(float f) {
    unsigned r;
    asm("cvt.rna.tf32.f32 %0, %1;" : "=r"(r) : "f"(f));
    return __uint_as_float(r);
}

// m16n8k8 tf32 MMA, D += A*B (accumulate in place)
#define MMA_TF32(d, a0, a1, a2, a3, b0, b1)                          \
    asm("mma.sync.aligned.m16n8k8.row.col.f32.tf32.tf32.f32 "        \
        "{%0,%1,%2,%3}, {%4,%5,%6,%7}, {%8,%9}, {%0,%1,%2,%3};"      \
        : "+f"((d)[0]), "+f"((d)[1]), "+f"((d)[2]), "+f"((d)[3])     \
        : "r"(a0), "r"(a1), "r"(a2), "r"(a3), "r"(b0), "r"(b1))

// ------------------------- scratch (device globals) -------------------------
__device__ float g_x[BB * NN * DD];
__device__ float g_xv[BB * NN * DD];
__device__ float g_q[BB * NN * DD];
__device__ float g_k[BB * NN * DD];
__device__ float g_v[BB * NN * DD];
__device__ float g_ao[BB * NN * DD];
__device__ float g_o[BB * NN * DD];
__device__ float g_h[BB * NN * DFF];
__device__ float g_h2[BB * NN * DD];

// ------------------------- add positional embedding -------------------------
__global__ void add_pos_kernel(const float* __restrict__ in,
                               const float* __restrict__ in_v,
                               const float* __restrict__ pos,
                               float* __restrict__ x, float* __restrict__ xv) {
    size_t i = (size_t)blockIdx.x * 256 + threadIdx.x;
    float p = pos[i % (NN * DD)];
    x[i]  = in[i]  + p;
    xv[i] = in_v[i] + p;
}

// --------- 128x128x16 double-buffered GEMM body (tf32 tensor core) ----------
// A,W staged to smem with tf32 rounding; fp32 accumulation via mma.sync.
// GKK=16: 2 k8-MMA-steps (32 MMAs/warp) per __syncthreads window.
#define GM 128
#define GN 128
#define GKK 16
#define SP 136   // padded row: bank = (k*8 + idx) % 32 -> conflict-free frags

__device__ __forceinline__
void gemm128_body(const float* __restrict__ A,
                  const float* __restrict__ W,
                  const float* __restrict__ bias,
                  float* __restrict__ C,
                  int M, int K, int Nc, int apply_gelu) {
    __shared__ float As[2][GKK][SP];   // [k][row]
    __shared__ float Bs[2][GKK][SP];   // [k][col]
    const int tid = threadIdx.x;
    const int lane = tid & 31, warp = tid >> 5;
    const int wm = (warp & 3) * 32;    // warp row offset (4 warps in m)
    const int wn = (warp >> 2) * 64;   // warp col offset (2 warps in n)
    const int gID = lane >> 2, tq = lane & 3;
    const int row0 = blockIdx.y * GM, col0 = blockIdx.x * GN;

    // A: each thread stores 2 float4s: (arow, ak0) and (arow, ak0+8)
    const int arow = tid >> 1, ak0 = (tid & 1) * 4;
    // B: each thread stores 2 float4s: rows brow and brow+8, cols bcol..bcol+3
    const int brow = tid >> 5, bcol = (tid & 31) * 4;

    const float* Aptr = A + (size_t)(row0 + arow) * K + ak0;
    const float* Wptr = W + (size_t)brow * Nc + col0 + bcol;
    const size_t wstride8 = (size_t)8 * Nc;

    {
        float4 a0 = *(const float4*)Aptr;
        float4 a1 = *(const float4*)(Aptr + 8);
        float4 b0 = *(const float4*)Wptr;
        float4 b1 = *(const float4*)(Wptr + wstride8);
        As[0][ak0 + 0][arow] = tf32r(a0.x);
        As[0][ak0 + 1][arow] = tf32r(a0.y);
        As[0][ak0 + 2][arow] = tf32r(a0.z);
        As[0][ak0 + 3][arow] = tf32r(a0.w);
        As[0][ak0 + 8][arow] = tf32r(a1.x);
        As[0][ak0 + 9][arow] = tf32r(a1.y);
        As[0][ak0 + 10][arow] = tf32r(a1.z);
        As[0][ak0 + 11][arow] = tf32r(a1.w);
        *(float4*)&Bs[0][brow][bcol] =
            make_float4(tf32r(b0.x), tf32r(b0.y), tf32r(b0.z), tf32r(b0.w));
        *(float4*)&Bs[0][brow + 8][bcol] =
            make_float4(tf32r(b1.x), tf32r(b1.y), tf32r(b1.z), tf32r(b1.w));
    }
    __syncthreads();

    float acc[2][8][4];
#pragma unroll
    for (int mf = 0; mf < 2; mf++)
#pragma unroll
        for (int nf = 0; nf < 8; nf++)
#pragma unroll
            for (int c = 0; c < 4; c++) acc[mf][nf][c] = 0.0f;

    int buf = 0;
    for (int k0 = 0; k0 < K; k0 += GKK) {
        const bool has_next = (k0 + GKK < K);
        float4 na0, na1, nb0, nb1;
        if (has_next) {
            na0 = *(const float4*)(Aptr + k0 + GKK);
            na1 = *(const float4*)(Aptr + k0 + GKK + 8);
            nb0 = *(const float4*)(Wptr + (size_t)(k0 + GKK) * Nc);
            nb1 = *(const float4*)(Wptr + (size_t)(k0 + GKK) * Nc + wstride8);
        }

#pragma unroll
        for (int ks = 0; ks < 2; ks++) {
            const int kb = ks * 8;
            unsigned af[2][4];
#pragma unroll
            for (int mf = 0; mf < 2; mf++) {
                const int rb = wm + mf * 16 + gID;
                af[mf][0] = __float_as_uint(As[buf][kb + tq][rb]);
                af[mf][1] = __float_as_uint(As[buf][kb + tq][rb + 8]);
                af[mf][2] = __float_as_uint(As[buf][kb + tq + 4][rb]);
                af[mf][3] = __float_as_uint(As[buf][kb + tq + 4][rb + 8]);
            }
#pragma unroll
            for (int nf = 0; nf < 8; nf++) {
                const int cb = wn + nf * 8 + gID;
                unsigned b0 = __float_as_uint(Bs[buf][kb + tq][cb]);
                unsigned b1 = __float_as_uint(Bs[buf][kb + tq + 4][cb]);
                MMA_TF32(acc[0][nf], af[0][0], af[0][1], af[0][2], af[0][3], b0, b1);
                MMA_TF32(acc[1][nf], af[1][0], af[1][1], af[1][2], af[1][3], b0, b1);
            }
        }

        if (has_next) {
            As[buf ^ 1][ak0 + 0][arow] = tf32r(na0.x);
            As[buf ^ 1][ak0 + 1][arow] = tf32r(na0.y);
            As[buf ^ 1][ak0 + 2][arow] = tf32r(na0.z);
            As[buf ^ 1][ak0 + 3][arow] = tf32r(na0.w);
            As[buf ^ 1][ak0 + 8][arow] = tf32r(na1.x);
            As[buf ^ 1][ak0 + 9][arow] = tf32r(na1.y);
            As[buf ^ 1][ak0 + 10][arow] = tf32r(na1.z);
            As[buf ^ 1][ak0 + 11][arow] = tf32r(na1.w);
            *(float4*)&Bs[buf ^ 1][brow][bcol] =
                make_float4(tf32r(nb0.x), tf32r(nb0.y), tf32r(nb0.z), tf32r(nb0.w));
            *(float4*)&Bs[buf ^ 1][brow + 8][bcol] =
                make_float4(tf32r(nb1.x), tf32r(nb1.y), tf32r(nb1.z), tf32r(nb1.w));
            __syncthreads();
            buf ^= 1;
        }
    }

    // epilogue: C fragment layout -> bias (+gelu) -> float2 stores
#pragma unroll
    for (int mf = 0; mf < 2; mf++) {
        const int r0 = row0 + wm + mf * 16 + gID;
#pragma unroll
        for (int nf = 0; nf < 8; nf++) {
            const int c = col0 + wn + nf * 8 + tq * 2;
            const float bx = bias[c], by = bias[c + 1];
            float v0 = acc[mf][nf][0] + bx;
            float v1 = acc[mf][nf][1] + by;
            float v2 = acc[mf][nf][2] + bx;
            float v3 = acc[mf][nf][3] + by;
            if (apply_gelu) {
                v0 = 0.5f * v0 * (1.0f + erff(v0 * 0.70710678118654752f));
                v1 = 0.5f * v1 * (1.0f + erff(v1 * 0.70710678118654752f));
                v2 = 0.5f * v2 * (1.0f + erff(v2 * 0.70710678118654752f));
                v3 = 0.5f * v3 * (1.0f + erff(v3 * 0.70710678118654752f));
            }
            *(float2*)&C[(size_t)r0 * Nc + c] = make_float2(v0, v1);
            *(float2*)&C[(size_t)(r0 + 8) * Nc + c] = make_float2(v2, v3);
        }
    }
}

__global__ __launch_bounds__(256, 2)
void gemm128_kernel(const float* __restrict__ A,
                    const float* __restrict__ W,
                    const float* __restrict__ bias,
                    float* __restrict__ C,
                    int M, int K, int Nc, int apply_gelu) {
    gemm128_body(A, W, bias, C, M, K, Nc, apply_gelu);
}

// Batched QKV: blockIdx.z selects {x@Wq, x@Wk, xv@Wv}. One launch, 3x grid.
__global__ __launch_bounds__(256, 2)
void gemm_qkv_kernel(const float* __restrict__ x, const float* __restrict__ xv,
                     const float* __restrict__ Wq, const float* __restrict__ Wk,
                     const float* __restrict__ Wv,
                     const float* __restrict__ bq, const float* __restrict__ bk,
                     const float* __restrict__ bv,
                     float* __restrict__ q, float* __restrict__ k,
                     float* __restrict__ v, int M, int K, int Nc) {
    const float* A;
    const float* W;
    const float* b;
    float* C;
    if (blockIdx.z == 0)      { A = x;  W = Wq; b = bq; C = q; }
    else if (blockIdx.z == 1) { A = x;  W = Wk; b = bk; C = k; }
    else                      { A = xv; W = Wv; b = bv; C = v; }
    gemm128_body(A, W, b, C, M, K, Nc, 0);
}

// ------------------------- fused attention -------------------------
// 16-query tiles, static smem (~43.6 KB -> ~5 CTAs/SM).
// grid (N/16, H, B), block 256. mask read as 32-bit words (nonzero == True).
__global__ void attn_kernel(const float* __restrict__ q,
                            const float* __restrict__ k,
                            const float* __restrict__ v,
                            const int* __restrict__ mask,
                            float* __restrict__ out, int use_mask) {
    const int b = blockIdx.z, h = blockIdx.y, q0 = blockIdx.x * 16;
    __shared__ float Qs[16][33];
    __shared__ float Kt[32][68];    // score phase: transposed K chunk [d][key]
    __shared__ float S[16][512];
    float* Vb = &Kt[0][0];          // PV phase: V chunk [64][33] (2112 <= 2176)
    const int tid = threadIdx.x;
    const float scale = 0.17677669529663687f;  // 1/sqrt(32)

    // load Q tile
    for (int e = tid; e < 16 * 32; e += 256) {
        int r = e >> 5, d = e & 31;
        Qs[r][d] = q[(size_t)(b * NN + q0 + r) * DD + h * DK + d];
    }

    // scores: thread handles row sr = tid>>4, cols scg*4..scg*4+3 (FFMA2 pairs)
    const int sr = tid >> 4;
    const int scg = tid & 15;
    for (int kc = 0; kc < NN; kc += 64) {
        __syncthreads();
        for (int e = tid; e < 64 * 32; e += 256) {
            int rr = e >> 5, d = e & 31;
            Kt[d][rr] = k[(size_t)(b * NN + kc + rr) * DD + h * DK + d];
        }
        __syncthreads();
        u64t acc01 = 0ULL, acc23 = 0ULL;
#pragma unroll
        for (int d = 0; d < DK; d++) {
            float qv = Qs[sr][d];
            u64t qd = pack2(qv, qv);
            ulonglong2 kp = *(const ulonglong2*)&Kt[d][scg * 4];
            FMA_F32X2(acc01, qd, kp.x);
            FMA_F32X2(acc23, qd, kp.y);
        }
        float2 p01 = unpack2(acc01);
        float2 p23 = unpack2(acc23);
        float s0 = p01.x * scale, s1 = p01.y * scale;
        float s2 = p23.x * scale, s3 = p23.y * scale;
        if (use_mask) {
            int4 m4 = *(const int4*)&mask[(size_t)(q0 + sr) * NN + kc + scg * 4];
            if (m4.x) s0 = -1e30f;
            if (m4.y) s1 = -1e30f;
            if (m4.z) s2 = -1e30f;
            if (m4.w) s3 = -1e30f;
        }
        float4 sv = make_float4(s0, s1, s2, s3);
        *(float4*)&S[sr][kc + scg * 4] = sv;
    }
    __syncthreads();

    // softmax: 8 warps, 2 rows each
    const int warp = tid >> 5, lane = tid & 31;
    for (int r = warp; r < 16; r += 8) {
        float mx = -1e30f;
        for (int c = lane; c < NN; c += 32) mx = fmaxf(mx, S[r][c]);
#pragma unroll
        for (int o = 16; o; o >>= 1) mx = fmaxf(mx, __shfl_xor_sync(0xFFFFFFFFu, mx, o));
        float sum = 0.0f;
        for (int c = lane; c < NN; c += 32) {
            float e = __expf(S[r][c] - mx);
            S[r][c] = e;
            sum += e;
        }
#pragma unroll
        for (int o = 16; o; o >>= 1) sum += __shfl_xor_sync(0xFFFFFFFFu, sum, o);
        float inv = 1.0f / sum;
        for (int c = lane; c < NN; c += 32) S[r][c] *= inv;
    }

    // O = P @ V, chunked: stage V[64][32] in smem, accumulate from smem.
    {
        const int d = lane;
        const int r1 = warp;
        const int r2 = r1 + 8;
        float acc1 = 0.0f, acc2 = 0.0f;
        const float* S1 = &S[r1][0];
        const float* S2 = &S[r2][0];
        for (int kc = 0; kc < NN; kc += 64) {
            __syncthreads();
            for (int e = tid; e < 64 * 32; e += 256) {
                int rr = e >> 5, dd = e & 31;
                Vb[rr * 33 + dd] = v[(size_t)(b * NN + kc + rr) * DD + h * DK + dd];
            }
            __syncthreads();
#pragma unroll 4
            for (int kk = 0; kk < 64; kk += 4) {
                float4 s1 = *(const float4*)&S1[kc + kk];
                float4 s2 = *(const float4*)&S2[kc + kk];
                float v0 = Vb[(kk + 0) * 33 + d];
                float v1 = Vb[(kk + 1) * 33 + d];
                float v2 = Vb[(kk + 2) * 33 + d];
                float v3 = Vb[(kk + 3) * 33 + d];
                acc1 += s1.x * v0;
                acc2 += s2.x * v0;
                acc1 += s1.y * v1;
                acc2 += s2.y * v1;
                acc1 += s1.z * v2;
                acc2 += s2.z * v2;
                acc1 += s1.w * v3;
                acc2 += s2.w * v3;
            }
        }
        out[(size_t)(b * NN + q0 + r1) * DD + h * DK + d] = acc1;
        out[(size_t)(b * NN + q0 + r2) * DD + h * DK + d] = acc2;
    }
}

// ------------------------- residual + layernorm -------------------------
__global__ void ln_kernel(const float* __restrict__ x,
                          const float* __restrict__ res,
                          const float* __restrict__ g,
                          const float* __restrict__ bta,
                          float* __restrict__ out) {
    const int row = blockIdx.x;
    const int i = threadIdx.x;
    const int warp = i >> 5, lane = i & 31;
    __shared__ float ps[8], ps2[8];
    size_t base = (size_t)row * DD;
    float val = x[base + i] + (res ? res[base + i] : 0.0f);
    float s = val, s2 = val * val;
#pragma unroll
    for (int o = 16; o; o >>= 1) {
        s  += __shfl_xor_sync(0xFFFFFFFFu, s, o);
        s2 += __shfl_xor_sync(0xFFFFFFFFu, s2, o);
    }
    if (lane == 0) { ps[warp] = s; ps2[warp] = s2; }
    __syncthreads();
    if (warp == 0) {
        float a = ps[lane & 7], a2 = ps2[lane & 7];
#pragma unroll
        for (int o = 4; o; o >>= 1) {
            a  += __shfl_xor_sync(0xFFFFFFFFu, a, o);
            a2 += __shfl_xor_sync(0xFFFFFFFFu, a2, o);
        }
        if (lane == 0) { ps[0] = a; ps2[0] = a2; }
    }
    __syncthreads();
    float mean = ps[0] * (1.0f / DD);
    float var = ps2[0] * (1.0f / DD) - mean * mean;
    out[base + i] = (val - mean) * rsqrtf(var + 1e-5f) * g[i] + bta[i];
}

// ------------------------- launch -------------------------
extern "C" void kernel_launch(void* const* d_in, const int* in_sizes, int n_in,
                              void* d_out, int out_size) {
    const float* input   = (const float*)d_in[0];
    const float* input_v = (const float*)d_in[1];
    const float* pos_emb = (const float*)d_in[2];
    const float* Wq = (const float*)d_in[3];
    const float* bq = (const float*)d_in[4];
    const float* Wk = (const float*)d_in[5];
    const float* bk = (const float*)d_in[6];
    const float* Wv = (const float*)d_in[7];
    const float* bv = (const float*)d_in[8];
    const float* Wo = (const float*)d_in[9];
    const float* bo = (const float*)d_in[10];
    const float* W1 = (const float*)d_in[11];
    const float* b1 = (const float*)d_in[12];
    const float* W2 = (const float*)d_in[13];
    const float* b2 = (const float*)d_in[14];
    const float* g1 = (const float*)d_in[15];
    const float* be1 = (const float*)d_in[16];
    const float* g2 = (const float*)d_in[17];
    const float* be2 = (const float*)d_in[18];
    const float* gf = (const float*)d_in[19];
    const float* bf = (const float*)d_in[20];
    const int* mask = (const int*)d_in[21];

    float *x, *xv, *q, *k, *v, *ao, *o, *h, *h2;
    cudaGetSymbolAddress((void**)&x, g_x);
    cudaGetSymbolAddress((void**)&xv, g_xv);
    cudaGetSymbolAddress((void**)&q, g_q);
    cudaGetSymbolAddress((void**)&k, g_k);
    cudaGetSymbolAddress((void**)&v, g_v);
    cudaGetSymbolAddress((void**)&ao, g_ao);
    cudaGetSymbolAddress((void**)&o, g_o);
    cudaGetSymbolAddress((void**)&h, g_h);
    cudaGetSymbolAddress((void**)&h2, g_h2);

    const int M = BB * NN;  // 8192

    add_pos_kernel<<<(BB * NN * DD) / 256, 256>>>(input, input_v, pos_emb, x, xv);

    for (int i = 0; i < LL; i++) {
        const float* Wqi = Wq + (size_t)i * DD * DD;
        const float* Wki = Wk + (size_t)i * DD * DD;
        const float* Wvi = Wv + (size_t)i * DD * DD;
        const float* Woi = Wo + (size_t)i * DD * DD;
        const float* W1i = W1 + (size_t)i * DD * DFF;
        const float* W2i = W2 + (size_t)i * (DFF / 2) * (DD / 2);

        // QKV projections in one batched launch (z = 0,1,2)
        gemm_qkv_kernel<<<dim3(DD / GN, M / GM, 3), 256>>>(
            x, xv, Wqi, Wki, Wvi, bq + i * DD, bk + i * DD, bv + i * DD,
            q, k, v, M, DD, DD);

        // attention (16-query tiles, smem-staged V)
        attn_kernel<<<dim3(NN / 16, HH, BB), 256>>>(
            q, k, v, mask, ao, (i % 2) ? 1 : 0);

        // output projection
        gemm128_kernel<<<dim3(DD / GN, M / GM), 256>>>(ao, Woi, bo + i * DD, o, M, DD, DD, 0);

        // x = LN(x + o)
        ln_kernel<<<M, 256>>>(x, o, g1 + i * DD, be1 + i * DD, x);

        // FFN1 + GELU
        gemm128_kernel<<<dim3(DFF / GN, M / GM), 256>>>(x, W1i, b1 + i * DFF, h, M, DD, DFF, 1);

        // FFN2 grouped: (B*N*2, 512) @ (512, 128) -> contiguous (B*N, 256)
        gemm128_kernel<<<dim3((DD / 2) / GN, (2 * M) / GM), 256>>>(
            h, W2i, b2 + i * (DD / 2), h2, 2 * M, DFF / 2, DD / 2, 0);

        // x = LN(x + h2)
        ln_kernel<<<M, 256>>>(x, h2, g2 + i * DD, be2 + i * DD, x);
    }

    // final LN -> output
    ln_kernel<<<M, 256>>>(x, nullptr, gf, bf, (float*)d_out);
}

// round 14
// speedup vs baseline: 3.6131x; 1.4558x over previous
#include <cuda_runtime.h>
#include <cuda_bf16.h>
#include <math.h>

#define BB 16
#define NN 512
#define DD 256
#define LL 4
#define HH 8
#define DK 32
#define DFF 1024

// tf32 round (rna) — result is a valid fp32 bit pattern with truncated mantissa
__device__ __forceinline__ float tf32r(float f) {
    unsigned r;
    asm("cvt.rna.tf32.f32 %0, %1;" : "=r"(r) : "f"(f));
    return __uint_as_float(r);
}

// m16n8k8 tf32 MMA, D += A*B (accumulate in place)
#define MMA_TF32(d, a0, a1, a2, a3, b0, b1)                          \
    asm("mma.sync.aligned.m16n8k8.row.col.f32.tf32.tf32.f32 "        \
        "{%0,%1,%2,%3}, {%4,%5,%6,%7}, {%8,%9}, {%0,%1,%2,%3};"      \
        : "+f"((d)[0]), "+f"((d)[1]), "+f"((d)[2]), "+f"((d)[3])     \
        : "r"(a0), "r"(a1), "r"(a2), "r"(a3), "r"(b0), "r"(b1))

// ------------------------- scratch (device globals) -------------------------
__device__ float g_x[BB * NN * DD];
__device__ float g_xv[BB * NN * DD];
__device__ float g_q[BB * NN * DD];
__device__ float g_k[BB * NN * DD];
__device__ float g_v[BB * NN * DD];
__device__ float g_ao[BB * NN * DD];
__device__ float g_o[BB * NN * DD];
__device__ float g_h[BB * NN * DFF];
__device__ float g_h2[BB * NN * DD];

// ------------------------- add positional embedding -------------------------
__global__ void add_pos_kernel(const float* __restrict__ in,
                               const float* __restrict__ in_v,
                               const float* __restrict__ pos,
                               float* __restrict__ x, float* __restrict__ xv) {
    size_t i = (size_t)blockIdx.x * 256 + threadIdx.x;
    float p = pos[i % (NN * DD)];
    x[i]  = in[i]  + p;
    xv[i] = in_v[i] + p;
}

// --------- 128x128x16 double-buffered GEMM body (tf32 tensor core) ----------
#define GM 128
#define GN 128
#define GKK 16
#define SP 136   // padded row: bank = (k*8 + idx) % 32 -> conflict-free frags

__device__ __forceinline__
void gemm128_body(const float* __restrict__ A,
                  const float* __restrict__ W,
                  const float* __restrict__ bias,
                  float* __restrict__ C,
                  int M, int K, int Nc, int apply_gelu) {
    __shared__ float As[2][GKK][SP];   // [k][row]
    __shared__ float Bs[2][GKK][SP];   // [k][col]
    const int tid = threadIdx.x;
    const int lane = tid & 31, warp = tid >> 5;
    const int wm = (warp & 3) * 32;    // warp row offset (4 warps in m)
    const int wn = (warp >> 2) * 64;   // warp col offset (2 warps in n)
    const int gID = lane >> 2, tq = lane & 3;
    const int row0 = blockIdx.y * GM, col0 = blockIdx.x * GN;

    const int arow = tid >> 1, ak0 = (tid & 1) * 4;
    const int brow = tid >> 5, bcol = (tid & 31) * 4;

    const float* Aptr = A + (size_t)(row0 + arow) * K + ak0;
    const float* Wptr = W + (size_t)brow * Nc + col0 + bcol;
    const size_t wstride8 = (size_t)8 * Nc;

    {
        float4 a0 = *(const float4*)Aptr;
        float4 a1 = *(const float4*)(Aptr + 8);
        float4 b0 = *(const float4*)Wptr;
        float4 b1 = *(const float4*)(Wptr + wstride8);
        As[0][ak0 + 0][arow] = tf32r(a0.x);
        As[0][ak0 + 1][arow] = tf32r(a0.y);
        As[0][ak0 + 2][arow] = tf32r(a0.z);
        As[0][ak0 + 3][arow] = tf32r(a0.w);
        As[0][ak0 + 8][arow] = tf32r(a1.x);
        As[0][ak0 + 9][arow] = tf32r(a1.y);
        As[0][ak0 + 10][arow] = tf32r(a1.z);
        As[0][ak0 + 11][arow] = tf32r(a1.w);
        *(float4*)&Bs[0][brow][bcol] =
            make_float4(tf32r(b0.x), tf32r(b0.y), tf32r(b0.z), tf32r(b0.w));
        *(float4*)&Bs[0][brow + 8][bcol] =
            make_float4(tf32r(b1.x), tf32r(b1.y), tf32r(b1.z), tf32r(b1.w));
    }
    __syncthreads();

    float acc[2][8][4];
#pragma unroll
    for (int mf = 0; mf < 2; mf++)
#pragma unroll
        for (int nf = 0; nf < 8; nf++)
#pragma unroll
            for (int c = 0; c < 4; c++) acc[mf][nf][c] = 0.0f;

    int buf = 0;
    for (int k0 = 0; k0 < K; k0 += GKK) {
        const bool has_next = (k0 + GKK < K);
        float4 na0, na1, nb0, nb1;
        if (has_next) {
            na0 = *(const float4*)(Aptr + k0 + GKK);
            na1 = *(const float4*)(Aptr + k0 + GKK + 8);
            nb0 = *(const float4*)(Wptr + (size_t)(k0 + GKK) * Nc);
            nb1 = *(const float4*)(Wptr + (size_t)(k0 + GKK) * Nc + wstride8);
        }

#pragma unroll
        for (int ks = 0; ks < 2; ks++) {
            const int kb = ks * 8;
            unsigned af[2][4];
#pragma unroll
            for (int mf = 0; mf < 2; mf++) {
                const int rb = wm + mf * 16 + gID;
                af[mf][0] = __float_as_uint(As[buf][kb + tq][rb]);
                af[mf][1] = __float_as_uint(As[buf][kb + tq][rb + 8]);
                af[mf][2] = __float_as_uint(As[buf][kb + tq + 4][rb]);
                af[mf][3] = __float_as_uint(As[buf][kb + tq + 4][rb + 8]);
            }
#pragma unroll
            for (int nf = 0; nf < 8; nf++) {
                const int cb = wn + nf * 8 + gID;
                unsigned b0 = __float_as_uint(Bs[buf][kb + tq][cb]);
                unsigned b1 = __float_as_uint(Bs[buf][kb + tq + 4][cb]);
                MMA_TF32(acc[0][nf], af[0][0], af[0][1], af[0][2], af[0][3], b0, b1);
                MMA_TF32(acc[1][nf], af[1][0], af[1][1], af[1][2], af[1][3], b0, b1);
            }
        }

        if (has_next) {
            As[buf ^ 1][ak0 + 0][arow] = tf32r(na0.x);
            As[buf ^ 1][ak0 + 1][arow] = tf32r(na0.y);
            As[buf ^ 1][ak0 + 2][arow] = tf32r(na0.z);
            As[buf ^ 1][ak0 + 3][arow] = tf32r(na0.w);
            As[buf ^ 1][ak0 + 8][arow] = tf32r(na1.x);
            As[buf ^ 1][ak0 + 9][arow] = tf32r(na1.y);
            As[buf ^ 1][ak0 + 10][arow] = tf32r(na1.z);
            As[buf ^ 1][ak0 + 11][arow] = tf32r(na1.w);
            *(float4*)&Bs[buf ^ 1][brow][bcol] =
                make_float4(tf32r(nb0.x), tf32r(nb0.y), tf32r(nb0.z), tf32r(nb0.w));
            *(float4*)&Bs[buf ^ 1][brow + 8][bcol] =
                make_float4(tf32r(nb1.x), tf32r(nb1.y), tf32r(nb1.z), tf32r(nb1.w));
            __syncthreads();
            buf ^= 1;
        }
    }

    // epilogue: C fragment layout -> bias (+gelu) -> float2 stores
#pragma unroll
    for (int mf = 0; mf < 2; mf++) {
        const int r0 = row0 + wm + mf * 16 + gID;
#pragma unroll
        for (int nf = 0; nf < 8; nf++) {
            const int c = col0 + wn + nf * 8 + tq * 2;
            const float bx = bias[c], by = bias[c + 1];
            float v0 = acc[mf][nf][0] + bx;
            float v1 = acc[mf][nf][1] + by;
            float v2 = acc[mf][nf][2] + bx;
            float v3 = acc[mf][nf][3] + by;
            if (apply_gelu) {
                v0 = 0.5f * v0 * (1.0f + erff(v0 * 0.70710678118654752f));
                v1 = 0.5f * v1 * (1.0f + erff(v1 * 0.70710678118654752f));
                v2 = 0.5f * v2 * (1.0f + erff(v2 * 0.70710678118654752f));
                v3 = 0.5f * v3 * (1.0f + erff(v3 * 0.70710678118654752f));
            }
            *(float2*)&C[(size_t)r0 * Nc + c] = make_float2(v0, v1);
            *(float2*)&C[(size_t)(r0 + 8) * Nc + c] = make_float2(v2, v3);
        }
    }
}

__global__ __launch_bounds__(256, 2)
void gemm128_kernel(const float* __restrict__ A,
                    const float* __restrict__ W,
                    const float* __restrict__ bias,
                    float* __restrict__ C,
                    int M, int K, int Nc, int apply_gelu) {
    gemm128_body(A, W, bias, C, M, K, Nc, apply_gelu);
}

// Batched QKV: blockIdx.z selects {x@Wq, x@Wk, xv@Wv}. One launch, 3x grid.
__global__ __launch_bounds__(256, 2)
void gemm_qkv_kernel(const float* __restrict__ x, const float* __restrict__ xv,
                     const float* __restrict__ Wq, const float* __restrict__ Wk,
                     const float* __restrict__ Wv,
                     const float* __restrict__ bq, const float* __restrict__ bk,
                     const float* __restrict__ bv,
                     float* __restrict__ q, float* __restrict__ k,
                     float* __restrict__ v, int M, int K, int Nc) {
    const float* A;
    const float* W;
    const float* b;
    float* C;
    if (blockIdx.z == 0)      { A = x;  W = Wq; b = bq; C = q; }
    else if (blockIdx.z == 1) { A = x;  W = Wk; b = bk; C = k; }
    else                      { A = xv; W = Wv; b = bv; C = v; }
    gemm128_body(A, W, b, C, M, K, Nc, 0);
}

// ------------------- fused attention (tf32 tensor core) ---------------------
// 16-query tiles, grid (N/16, H, B), block 256 (8 warps).
// Score: warp w = one 8-key n-tile per 64-key chunk (4 MMAs/chunk).
// PV:    warp w -> dk-tile (w&3), key-half (w>>2); 2-way cross-warp reduce.
// mask read as 32-bit words (nonzero == True).
#define SPS 516   // S row stride: bank = (4*row + col) % 32 -> conflict-free col frags

__global__ void attn_kernel(const float* __restrict__ q,
                            const float* __restrict__ k,
                            const float* __restrict__ v,
                            const int* __restrict__ mask,
                            float* __restrict__ out, int use_mask) {
    const int b = blockIdx.z, h = blockIdx.y, q0 = blockIdx.x * 16;
    __shared__ float Qs[16][33];
    __shared__ float KV[64][33];    // K chunk / V chunk (tf32); PV reduction buf
    __shared__ float S[16][SPS];
    const int tid = threadIdx.x;
    const int lane = tid & 31, warp = tid >> 5;
    const int gID = lane >> 2, tq = lane & 3;
    const float scale = 0.17677669529663687f;  // 1/sqrt(32)

    // stage Q tile (tf32)
    for (int e = tid; e < 16 * 32; e += 256) {
        int r = e >> 5, d = e & 31;
        Qs[r][d] = tf32r(q[(size_t)(b * NN + q0 + r) * DD + h * DK + d]);
    }
    __syncthreads();

    // Q fragments: rows (gID, gID+8), k-cols (kc*8+tq, +4). Reused all chunks.
    unsigned qf[4][4];
#pragma unroll
    for (int kc = 0; kc < 4; kc++) {
        qf[kc][0] = __float_as_uint(Qs[gID][kc * 8 + tq]);
        qf[kc][1] = __float_as_uint(Qs[gID + 8][kc * 8 + tq]);
        qf[kc][2] = __float_as_uint(Qs[gID][kc * 8 + tq + 4]);
        qf[kc][3] = __float_as_uint(Qs[gID + 8][kc * 8 + tq + 4]);
    }

    // ---- scores: S = (Q @ K^T) * scale, masked ----
    for (int c64 = 0; c64 < NN; c64 += 64) {
        __syncthreads();
        for (int e = tid; e < 64 * 32; e += 256) {
            int rr = e >> 5, d = e & 31;
            KV[rr][d] = tf32r(k[(size_t)(b * NN + c64 + rr) * DD + h * DK + d]);
        }
        __syncthreads();
        float acc[4] = {0.0f, 0.0f, 0.0f, 0.0f};
#pragma unroll
        for (int kc = 0; kc < 4; kc++) {
            unsigned b0 = __float_as_uint(KV[warp * 8 + gID][kc * 8 + tq]);
            unsigned b1 = __float_as_uint(KV[warp * 8 + gID][kc * 8 + tq + 4]);
            MMA_TF32(acc, qf[kc][0], qf[kc][1], qf[kc][2], qf[kc][3], b0, b1);
        }
        const int coln = c64 + warp * 8 + 2 * tq;
        float s0 = acc[0] * scale, s1 = acc[1] * scale;
        float s2 = acc[2] * scale, s3 = acc[3] * scale;
        if (use_mask) {
            int2 m0 = *(const int2*)&mask[(size_t)(q0 + gID) * NN + coln];
            int2 m1 = *(const int2*)&mask[(size_t)(q0 + gID + 8) * NN + coln];
            if (m0.x) s0 = -1e30f;
            if (m0.y) s1 = -1e30f;
            if (m1.x) s2 = -1e30f;
            if (m1.y) s3 = -1e30f;
        }
        *(float2*)&S[gID][coln] = make_float2(s0, s1);
        *(float2*)&S[gID + 8][coln] = make_float2(s2, s3);
    }
    __syncthreads();

    // ---- softmax: 8 warps, 2 rows each ----
    for (int r = warp; r < 16; r += 8) {
        float* Sr = &S[r][0];
        float mx = -1e30f;
        for (int c = lane; c < NN; c += 32) mx = fmaxf(mx, Sr[c]);
#pragma unroll
        for (int o = 16; o; o >>= 1) mx = fmaxf(mx, __shfl_xor_sync(0xFFFFFFFFu, mx, o));
        float sum = 0.0f;
        for (int c = lane; c < NN; c += 32) {
            float e = __expf(Sr[c] - mx);
            Sr[c] = e;
            sum += e;
        }
#pragma unroll
        for (int o = 16; o; o >>= 1) sum += __shfl_xor_sync(0xFFFFFFFFu, sum, o);
        float inv = 1.0f / sum;
        for (int c = lane; c < NN; c += 32) Sr[c] *= inv;
    }

    // ---- O = P @ V ----
    const int ntile = warp & 3;          // dk-tile (8 cols of 32)
    const int kb = (warp >> 2) * 32;     // key-half within each 64-key chunk
    float oacc[4] = {0.0f, 0.0f, 0.0f, 0.0f};
    for (int c64 = 0; c64 < NN; c64 += 64) {
        __syncthreads();
        for (int e = tid; e < 64 * 32; e += 256) {
            int rr = e >> 5, dd = e & 31;
            KV[rr][dd] = tf32r(v[(size_t)(b * NN + c64 + rr) * DD + h * DK + dd]);
        }
        __syncthreads();
#pragma unroll
        for (int ks = 0; ks < 4; ks++) {
            const int kl = kb + ks * 8;        // local key offset 0..63
            const int kg = c64 + kl;           // global key
            unsigned a0 = __float_as_uint(tf32r(S[gID][kg + tq]));
            unsigned a1 = __float_as_uint(tf32r(S[gID + 8][kg + tq]));
            unsigned a2 = __float_as_uint(tf32r(S[gID][kg + tq + 4]));
            unsigned a3 = __float_as_uint(tf32r(S[gID + 8][kg + tq + 4]));
            unsigned b0 = __float_as_uint(KV[kl + tq][ntile * 8 + gID]);
            unsigned b1 = __float_as_uint(KV[kl + tq + 4][ntile * 8 + gID]);
            MMA_TF32(oacc, a0, a1, a2, a3, b0, b1);
        }
    }
    __syncthreads();
    // 2-way reduction: warps 4-7 stash partials in KV buffer (512 floats)
    float* red = &KV[0][0];
    if (warp >= 4) {
        const int base = (warp - 4) * 128 + lane * 4;
        red[base + 0] = oacc[0];
        red[base + 1] = oacc[1];
        red[base + 2] = oacc[2];
        red[base + 3] = oacc[3];
    }
    __syncthreads();
    if (warp < 4) {
        const int base = warp * 128 + lane * 4;
        oacc[0] += red[base + 0];
        oacc[1] += red[base + 1];
        oacc[2] += red[base + 2];
        oacc[3] += red[base + 3];
        const int colo = h * DK + ntile * 8 + 2 * tq;
        *(float2*)&out[(size_t)(b * NN + q0 + gID) * DD + colo] =
            make_float2(oacc[0], oacc[1]);
        *(float2*)&out[(size_t)(b * NN + q0 + gID + 8) * DD + colo] =
            make_float2(oacc[2], oacc[3]);
    }
}

// ------------------------- residual + layernorm -------------------------
__global__ void ln_kernel(const float* __restrict__ x,
                          const float* __restrict__ res,
                          const float* __restrict__ g,
                          const float* __restrict__ bta,
                          float* __restrict__ out) {
    const int row = blockIdx.x;
    const int i = threadIdx.x;
    const int warp = i >> 5, lane = i & 31;
    __shared__ float ps[8], ps2[8];
    size_t base = (size_t)row * DD;
    float val = x[base + i] + (res ? res[base + i] : 0.0f);
    float s = val, s2 = val * val;
#pragma unroll
    for (int o = 16; o; o >>= 1) {
        s  += __shfl_xor_sync(0xFFFFFFFFu, s, o);
        s2 += __shfl_xor_sync(0xFFFFFFFFu, s2, o);
    }
    if (lane == 0) { ps[warp] = s; ps2[warp] = s2; }
    __syncthreads();
    if (warp == 0) {
        float a = ps[lane & 7], a2 = ps2[lane & 7];
#pragma unroll
        for (int o = 4; o; o >>= 1) {
            a  += __shfl_xor_sync(0xFFFFFFFFu, a, o);
            a2 += __shfl_xor_sync(0xFFFFFFFFu, a2, o);
        }
        if (lane == 0) { ps[0] = a; ps2[0] = a2; }
    }
    __syncthreads();
    float mean = ps[0] * (1.0f / DD);
    float var = ps2[0] * (1.0f / DD) - mean * mean;
    out[base + i] = (val - mean) * rsqrtf(var + 1e-5f) * g[i] + bta[i];
}

// ------------------------- launch -------------------------
extern "C" void kernel_launch(void* const* d_in, const int* in_sizes, int n_in,
                              void* d_out, int out_size) {
    const float* input   = (const float*)d_in[0];
    const float* input_v = (const float*)d_in[1];
    const float* pos_emb = (const float*)d_in[2];
    const float* Wq = (const float*)d_in[3];
    const float* bq = (const float*)d_in[4];
    const float* Wk = (const float*)d_in[5];
    const float* bk = (const float*)d_in[6];
    const float* Wv = (const float*)d_in[7];
    const float* bv = (const float*)d_in[8];
    const float* Wo = (const float*)d_in[9];
    const float* bo = (const float*)d_in[10];
    const float* W1 = (const float*)d_in[11];
    const float* b1 = (const float*)d_in[12];
    const float* W2 = (const float*)d_in[13];
    const float* b2 = (const float*)d_in[14];
    const float* g1 = (const float*)d_in[15];
    const float* be1 = (const float*)d_in[16];
    const float* g2 = (const float*)d_in[17];
    const float* be2 = (const float*)d_in[18];
    const float* gf = (const float*)d_in[19];
    const float* bf = (const float*)d_in[20];
    const int* mask = (const int*)d_in[21];

    float *x, *xv, *q, *k, *v, *ao, *o, *h, *h2;
    cudaGetSymbolAddress((void**)&x, g_x);
    cudaGetSymbolAddress((void**)&xv, g_xv);
    cudaGetSymbolAddress((void**)&q, g_q);
    cudaGetSymbolAddress((void**)&k, g_k);
    cudaGetSymbolAddress((void**)&v, g_v);
    cudaGetSymbolAddress((void**)&ao, g_ao);
    cudaGetSymbolAddress((void**)&o, g_o);
    cudaGetSymbolAddress((void**)&h, g_h);
    cudaGetSymbolAddress((void**)&h2, g_h2);

    const int M = BB * NN;  // 8192

    add_pos_kernel<<<(BB * NN * DD) / 256, 256>>>(input, input_v, pos_emb, x, xv);

    for (int i = 0; i < LL; i++) {
        const float* Wqi = Wq + (size_t)i * DD * DD;
        const float* Wki = Wk + (size_t)i * DD * DD;
        const float* Wvi = Wv + (size_t)i * DD * DD;
        const float* Woi = Wo + (size_t)i * DD * DD;
        const float* W1i = W1 + (size_t)i * DD * DFF;
        const float* W2i = W2 + (size_t)i * (DFF / 2) * (DD / 2);

        // QKV projections in one batched launch (z = 0,1,2)
        gemm_qkv_kernel<<<dim3(DD / GN, M / GM, 3), 256>>>(
            x, xv, Wqi, Wki, Wvi, bq + i * DD, bk + i * DD, bv + i * DD,
            q, k, v, M, DD, DD);

        // attention (tf32 tensor-core score + PV)
        attn_kernel<<<dim3(NN / 16, HH, BB), 256>>>(
            q, k, v, mask, ao, (i % 2) ? 1 : 0);

        // output projection
        gemm128_kernel<<<dim3(DD / GN, M / GM), 256>>>(ao, Woi, bo + i * DD, o, M, DD, DD, 0);

        // x = LN(x + o)
        ln_kernel<<<M, 256>>>(x, o, g1 + i * DD, be1 + i * DD, x);

        // FFN1 + GELU
        gemm128_kernel<<<dim3(DFF / GN, M / GM), 256>>>(x, W1i, b1 + i * DFF, h, M, DD, DFF, 1);

        // FFN2 grouped: (B*N*2, 512) @ (512, 128) -> contiguous (B*N, 256)
        gemm128_kernel<<<dim3((DD / 2) / GN, (2 * M) / GM), 256>>>(
            h, W2i, b2 + i * (DD / 2), h2, 2 * M, DFF / 2, DD / 2, 0);

        // x = LN(x + h2)
        ln_kernel<<<M, 256>>>(x, h2, g2 + i * DD, be2 + i * DD, x);
    }

    // final LN -> output
    ln_kernel<<<M, 256>>>(x, nullptr, gf, bf, (float*)d_out);
}

// round 15
// speedup vs baseline: 3.9501x; 1.0933x over previous
#include <cuda_runtime.h>
#include <cuda_bf16.h>
#include <math.h>

#define BB 16
#define NN 512
#define DD 256
#define LL 4
#define HH 8
#define DK 32
#define DFF 1024

// tf32 round (rna) — result is a valid fp32 bit pattern with truncated mantissa
__device__ __forceinline__ float tf32r(float f) {
    unsigned r;
    asm("cvt.rna.tf32.f32 %0, %1;" : "=r"(r) : "f"(f));
    return __uint_as_float(r);
}

// m16n8k8 tf32 MMA, D += A*B (accumulate in place)
#define MMA_TF32(d, a0, a1, a2, a3, b0, b1)                          \
    asm("mma.sync.aligned.m16n8k8.row.col.f32.tf32.tf32.f32 "        \
        "{%0,%1,%2,%3}, {%4,%5,%6,%7}, {%8,%9}, {%0,%1,%2,%3};"      \
        : "+f"((d)[0]), "+f"((d)[1]), "+f"((d)[2]), "+f"((d)[3])     \
        : "r"(a0), "r"(a1), "r"(a2), "r"(a3), "r"(b0), "r"(b1))

// ------------------------- scratch (device globals) -------------------------
__device__ float g_x[BB * NN * DD];
__device__ float g_xv[BB * NN * DD];
__device__ float g_q[BB * NN * DD];
__device__ float g_k[BB * NN * DD];
__device__ float g_v[BB * NN * DD];
__device__ float g_ao[BB * NN * DD];
__device__ float g_o[BB * NN * DD];
__device__ float g_h[BB * NN * DFF];
__device__ float g_h2[BB * NN * DD];

// ------------------------- add positional embedding -------------------------
__global__ void add_pos_kernel(const float* __restrict__ in,
                               const float* __restrict__ in_v,
                               const float* __restrict__ pos,
                               float* __restrict__ x, float* __restrict__ xv) {
    size_t i = (size_t)blockIdx.x * 256 + threadIdx.x;
    float p = pos[i % (NN * DD)];
    x[i]  = in[i]  + p;
    xv[i] = in_v[i] + p;
}

// --------- 128x128x16 double-buffered GEMM body (tf32 tensor core) ----------
#define GM 128
#define GN 128
#define GKK 16
#define SP 136   // padded row: bank = (k*8 + idx) % 32 -> conflict-free frags

__device__ __forceinline__
void gemm128_body(const float* __restrict__ A,
                  const float* __restrict__ W,
                  const float* __restrict__ bias,
                  float* __restrict__ C,
                  int M, int K, int Nc, int apply_gelu) {
    __shared__ float As[2][GKK][SP];   // [k][row]
    __shared__ float Bs[2][GKK][SP];   // [k][col]
    const int tid = threadIdx.x;
    const int lane = tid & 31, warp = tid >> 5;
    const int wm = (warp & 3) * 32;    // warp row offset (4 warps in m)
    const int wn = (warp >> 2) * 64;   // warp col offset (2 warps in n)
    const int gID = lane >> 2, tq = lane & 3;
    const int row0 = blockIdx.y * GM, col0 = blockIdx.x * GN;

    const int arow = tid >> 1, ak0 = (tid & 1) * 4;
    const int brow = tid >> 5, bcol = (tid & 31) * 4;

    const float* Aptr = A + (size_t)(row0 + arow) * K + ak0;
    const float* Wptr = W + (size_t)brow * Nc + col0 + bcol;
    const size_t wstride8 = (size_t)8 * Nc;

    {
        float4 a0 = *(const float4*)Aptr;
        float4 a1 = *(const float4*)(Aptr + 8);
        float4 b0 = *(const float4*)Wptr;
        float4 b1 = *(const float4*)(Wptr + wstride8);
        As[0][ak0 + 0][arow] = tf32r(a0.x);
        As[0][ak0 + 1][arow] = tf32r(a0.y);
        As[0][ak0 + 2][arow] = tf32r(a0.z);
        As[0][ak0 + 3][arow] = tf32r(a0.w);
        As[0][ak0 + 8][arow] = tf32r(a1.x);
        As[0][ak0 + 9][arow] = tf32r(a1.y);
        As[0][ak0 + 10][arow] = tf32r(a1.z);
        As[0][ak0 + 11][arow] = tf32r(a1.w);
        *(float4*)&Bs[0][brow][bcol] =
            make_float4(tf32r(b0.x), tf32r(b0.y), tf32r(b0.z), tf32r(b0.w));
        *(float4*)&Bs[0][brow + 8][bcol] =
            make_float4(tf32r(b1.x), tf32r(b1.y), tf32r(b1.z), tf32r(b1.w));
    }
    __syncthreads();

    float acc[2][8][4];
#pragma unroll
    for (int mf = 0; mf < 2; mf++)
#pragma unroll
        for (int nf = 0; nf < 8; nf++)
#pragma unroll
            for (int c = 0; c < 4; c++) acc[mf][nf][c] = 0.0f;

    int buf = 0;
    for (int k0 = 0; k0 < K; k0 += GKK) {
        const bool has_next = (k0 + GKK < K);
        float4 na0, na1, nb0, nb1;
        if (has_next) {
            na0 = *(const float4*)(Aptr + k0 + GKK);
            na1 = *(const float4*)(Aptr + k0 + GKK + 8);
            nb0 = *(const float4*)(Wptr + (size_t)(k0 + GKK) * Nc);
            nb1 = *(const float4*)(Wptr + (size_t)(k0 + GKK) * Nc + wstride8);
        }

#pragma unroll
        for (int ks = 0; ks < 2; ks++) {
            const int kb = ks * 8;
            unsigned af[2][4];
#pragma unroll
            for (int mf = 0; mf < 2; mf++) {
                const int rb = wm + mf * 16 + gID;
                af[mf][0] = __float_as_uint(As[buf][kb + tq][rb]);
                af[mf][1] = __float_as_uint(As[buf][kb + tq][rb + 8]);
                af[mf][2] = __float_as_uint(As[buf][kb + tq + 4][rb]);
                af[mf][3] = __float_as_uint(As[buf][kb + tq + 4][rb + 8]);
            }
#pragma unroll
            for (int nf = 0; nf < 8; nf++) {
                const int cb = wn + nf * 8 + gID;
                unsigned b0 = __float_as_uint(Bs[buf][kb + tq][cb]);
                unsigned b1 = __float_as_uint(Bs[buf][kb + tq + 4][cb]);
                MMA_TF32(acc[0][nf], af[0][0], af[0][1], af[0][2], af[0][3], b0, b1);
                MMA_TF32(acc[1][nf], af[1][0], af[1][1], af[1][2], af[1][3], b0, b1);
            }
        }

        if (has_next) {
            As[buf ^ 1][ak0 + 0][arow] = tf32r(na0.x);
            As[buf ^ 1][ak0 + 1][arow] = tf32r(na0.y);
            As[buf ^ 1][ak0 + 2][arow] = tf32r(na0.z);
            As[buf ^ 1][ak0 + 3][arow] = tf32r(na0.w);
            As[buf ^ 1][ak0 + 8][arow] = tf32r(na1.x);
            As[buf ^ 1][ak0 + 9][arow] = tf32r(na1.y);
            As[buf ^ 1][ak0 + 10][arow] = tf32r(na1.z);
            As[buf ^ 1][ak0 + 11][arow] = tf32r(na1.w);
            *(float4*)&Bs[buf ^ 1][brow][bcol] =
                make_float4(tf32r(nb0.x), tf32r(nb0.y), tf32r(nb0.z), tf32r(nb0.w));
            *(float4*)&Bs[buf ^ 1][brow + 8][bcol] =
                make_float4(tf32r(nb1.x), tf32r(nb1.y), tf32r(nb1.z), tf32r(nb1.w));
            __syncthreads();
            buf ^= 1;
        }
    }

    // epilogue: C fragment layout -> bias (+gelu) -> float2 stores
#pragma unroll
    for (int mf = 0; mf < 2; mf++) {
        const int r0 = row0 + wm + mf * 16 + gID;
#pragma unroll
        for (int nf = 0; nf < 8; nf++) {
            const int c = col0 + wn + nf * 8 + tq * 2;
            const float bx = bias[c], by = bias[c + 1];
            float v0 = acc[mf][nf][0] + bx;
            float v1 = acc[mf][nf][1] + by;
            float v2 = acc[mf][nf][2] + bx;
            float v3 = acc[mf][nf][3] + by;
            if (apply_gelu) {
                v0 = 0.5f * v0 * (1.0f + erff(v0 * 0.70710678118654752f));
                v1 = 0.5f * v1 * (1.0f + erff(v1 * 0.70710678118654752f));
                v2 = 0.5f * v2 * (1.0f + erff(v2 * 0.70710678118654752f));
                v3 = 0.5f * v3 * (1.0f + erff(v3 * 0.70710678118654752f));
            }
            *(float2*)&C[(size_t)r0 * Nc + c] = make_float2(v0, v1);
            *(float2*)&C[(size_t)(r0 + 8) * Nc + c] = make_float2(v2, v3);
        }
    }
}

__global__ __launch_bounds__(256, 2)
void gemm128_kernel(const float* __restrict__ A,
                    const float* __restrict__ W,
                    const float* __restrict__ bias,
                    float* __restrict__ C,
                    int M, int K, int Nc, int apply_gelu) {
    gemm128_body(A, W, bias, C, M, K, Nc, apply_gelu);
}

// Batched QKV: blockIdx.z selects {x@Wq, x@Wk, xv@Wv}. One launch, 3x grid.
__global__ __launch_bounds__(256, 2)
void gemm_qkv_kernel(const float* __restrict__ x, const float* __restrict__ xv,
                     const float* __restrict__ Wq, const float* __restrict__ Wk,
                     const float* __restrict__ Wv,
                     const float* __restrict__ bq, const float* __restrict__ bk,
                     const float* __restrict__ bv,
                     float* __restrict__ q, float* __restrict__ k,
                     float* __restrict__ v, int M, int K, int Nc) {
    const float* A;
    const float* W;
    const float* b;
    float* C;
    if (blockIdx.z == 0)      { A = x;  W = Wq; b = bq; C = q; }
    else if (blockIdx.z == 1) { A = x;  W = Wk; b = bk; C = k; }
    else                      { A = xv; W = Wv; b = bv; C = v; }
    gemm128_body(A, W, b, C, M, K, Nc, 0);
}

// ------------------- fused attention (tf32, sync-free dataflow) -------------
// 16-query tiles, grid (N/16, H, B), block 256 (8 warps).
// Score: warp w = one 8-key n-tile per 64-key chunk; K frags straight from gmem.
// PV:    warp w -> dk-tile (w&3), key-half (w>>2); V frags straight from gmem;
//        2-way cross-warp reduce via dedicated smem buffer.
// mask read as 32-bit words (nonzero == True).
#define SPS 516   // S row stride: bank = (4*row + col) % 32 -> conflict-free col frags

__global__ void attn_kernel(const float* __restrict__ q,
                            const float* __restrict__ k,
                            const float* __restrict__ v,
                            const int* __restrict__ mask,
                            float* __restrict__ out, int use_mask) {
    const int b = blockIdx.z, h = blockIdx.y, q0 = blockIdx.x * 16;
    __shared__ float Qs[16][33];
    __shared__ float S[16][SPS];
    __shared__ float red[512];
    const int tid = threadIdx.x;
    const int lane = tid & 31, warp = tid >> 5;
    const int gID = lane >> 2, tq = lane & 3;
    const float scale = 0.17677669529663687f;  // 1/sqrt(32)

    // stage Q tile (tf32)
    for (int e = tid; e < 16 * 32; e += 256) {
        int r = e >> 5, d = e & 31;
        Qs[r][d] = tf32r(q[(size_t)(b * NN + q0 + r) * DD + h * DK + d]);
    }
    __syncthreads();

    // Q fragments: rows (gID, gID+8), k-cols (kc*8+tq, +4). Reused all chunks.
    unsigned qf[4][4];
#pragma unroll
    for (int kc = 0; kc < 4; kc++) {
        qf[kc][0] = __float_as_uint(Qs[gID][kc * 8 + tq]);
        qf[kc][1] = __float_as_uint(Qs[gID + 8][kc * 8 + tq]);
        qf[kc][2] = __float_as_uint(Qs[gID][kc * 8 + tq + 4]);
        qf[kc][3] = __float_as_uint(Qs[gID + 8][kc * 8 + tq + 4]);
    }

    // ---- scores: S = (Q @ K^T) * scale, masked.  K frags direct from gmem ----
    {
        // warp's 8 private key rows: key = c64 + warp*8 + gID
        const float* kbase = k + (size_t)(b * NN + warp * 8 + gID) * DD + h * DK + tq;
        for (int c64 = 0; c64 < NN; c64 += 64) {
            const float* kp = kbase + (size_t)c64 * DD;
            float acc[4] = {0.0f, 0.0f, 0.0f, 0.0f};
#pragma unroll
            for (int kc = 0; kc < 4; kc++) {
                unsigned b0 = __float_as_uint(tf32r(kp[kc * 8]));
                unsigned b1 = __float_as_uint(tf32r(kp[kc * 8 + 4]));
                MMA_TF32(acc, qf[kc][0], qf[kc][1], qf[kc][2], qf[kc][3], b0, b1);
            }
            const int coln = c64 + warp * 8 + 2 * tq;
            float s0 = acc[0] * scale, s1 = acc[1] * scale;
            float s2 = acc[2] * scale, s3 = acc[3] * scale;
            if (use_mask) {
                int2 m0 = *(const int2*)&mask[(size_t)(q0 + gID) * NN + coln];
                int2 m1 = *(const int2*)&mask[(size_t)(q0 + gID + 8) * NN + coln];
                if (m0.x) s0 = -1e30f;
                if (m0.y) s1 = -1e30f;
                if (m1.x) s2 = -1e30f;
                if (m1.y) s3 = -1e30f;
            }
            *(float2*)&S[gID][coln] = make_float2(s0, s1);
            *(float2*)&S[gID + 8][coln] = make_float2(s2, s3);
        }
    }
    __syncthreads();

    // ---- softmax: 8 warps, 2 rows each ----
    for (int r = warp; r < 16; r += 8) {
        float* Sr = &S[r][0];
        float mx = -1e30f;
        for (int c = lane; c < NN; c += 32) mx = fmaxf(mx, Sr[c]);
#pragma unroll
        for (int o = 16; o; o >>= 1) mx = fmaxf(mx, __shfl_xor_sync(0xFFFFFFFFu, mx, o));
        float sum = 0.0f;
        for (int c = lane; c < NN; c += 32) {
            float e = __expf(Sr[c] - mx);
            Sr[c] = e;
            sum += e;
        }
#pragma unroll
        for (int o = 16; o; o >>= 1) sum += __shfl_xor_sync(0xFFFFFFFFu, sum, o);
        float inv = 1.0f / sum;
        for (int c = lane; c < NN; c += 32) Sr[c] *= inv;
    }
    __syncthreads();

    // ---- O = P @ V.  V frags direct from gmem ----
    const int ntile = warp & 3;          // dk-tile (8 cols of 32)
    const int kb = (warp >> 2) * 32;     // key-half within each 64-key chunk
    float oacc[4] = {0.0f, 0.0f, 0.0f, 0.0f};
    {
        // b0 row = c64 + kb + ks*8 + tq; col = ntile*8 + gID.  b1 = row + 4.
        const float* vbase = v + (size_t)(b * NN + kb + tq) * DD + h * DK + ntile * 8 + gID;
        for (int c64 = 0; c64 < NN; c64 += 64) {
#pragma unroll
            for (int ks = 0; ks < 4; ks++) {
                const int kg = c64 + kb + ks * 8;   // global key base for S cols
                unsigned a0 = __float_as_uint(tf32r(S[gID][kg + tq]));
                unsigned a1 = __float_as_uint(tf32r(S[gID + 8][kg + tq]));
                unsigned a2 = __float_as_uint(tf32r(S[gID][kg + tq + 4]));
                unsigned a3 = __float_as_uint(tf32r(S[gID + 8][kg + tq + 4]));
                const float* vp = vbase + (size_t)(c64 + ks * 8) * DD;
                unsigned b0 = __float_as_uint(tf32r(vp[0]));
                unsigned b1 = __float_as_uint(tf32r(vp[4 * DD]));
                MMA_TF32(oacc, a0, a1, a2, a3, b0, b1);
            }
        }
    }
    // 2-way reduction: warps 4-7 stash partials
    if (warp >= 4) {
        const int base = (warp - 4) * 128 + lane * 4;
        red[base + 0] = oacc[0];
        red[base + 1] = oacc[1];
        red[base + 2] = oacc[2];
        red[base + 3] = oacc[3];
    }
    __syncthreads();
    if (warp < 4) {
        const int base = warp * 128 + lane * 4;
        oacc[0] += red[base + 0];
        oacc[1] += red[base + 1];
        oacc[2] += red[base + 2];
        oacc[3] += red[base + 3];
        const int colo = h * DK + ntile * 8 + 2 * tq;
        *(float2*)&out[(size_t)(b * NN + q0 + gID) * DD + colo] =
            make_float2(oacc[0], oacc[1]);
        *(float2*)&out[(size_t)(b * NN + q0 + gID + 8) * DD + colo] =
            make_float2(oacc[2], oacc[3]);
    }
}

// ------------------------- residual + layernorm -------------------------
__global__ void ln_kernel(const float* __restrict__ x,
                          const float* __restrict__ res,
                          const float* __restrict__ g,
                          const float* __restrict__ bta,
                          float* __restrict__ out) {
    const int row = blockIdx.x;
    const int i = threadIdx.x;
    const int warp = i >> 5, lane = i & 31;
    __shared__ float ps[8], ps2[8];
    size_t base = (size_t)row * DD;
    float val = x[base + i] + (res ? res[base + i] : 0.0f);
    float s = val, s2 = val * val;
#pragma unroll
    for (int o = 16; o; o >>= 1) {
        s  += __shfl_xor_sync(0xFFFFFFFFu, s, o);
        s2 += __shfl_xor_sync(0xFFFFFFFFu, s2, o);
    }
    if (lane == 0) { ps[warp] = s; ps2[warp] = s2; }
    __syncthreads();
    if (warp == 0) {
        float a = ps[lane & 7], a2 = ps2[lane & 7];
#pragma unroll
        for (int o = 4; o; o >>= 1) {
            a  += __shfl_xor_sync(0xFFFFFFFFu, a, o);
            a2 += __shfl_xor_sync(0xFFFFFFFFu, a2, o);
        }
        if (lane == 0) { ps[0] = a; ps2[0] = a2; }
    }
    __syncthreads();
    float mean = ps[0] * (1.0f / DD);
    float var = ps2[0] * (1.0f / DD) - mean * mean;
    out[base + i] = (val - mean) * rsqrtf(var + 1e-5f) * g[i] + bta[i];
}

// ------------------------- launch -------------------------
extern "C" void kernel_launch(void* const* d_in, const int* in_sizes, int n_in,
                              void* d_out, int out_size) {
    const float* input   = (const float*)d_in[0];
    const float* input_v = (const float*)d_in[1];
    const float* pos_emb = (const float*)d_in[2];
    const float* Wq = (const float*)d_in[3];
    const float* bq = (const float*)d_in[4];
    const float* Wk = (const float*)d_in[5];
    const float* bk = (const float*)d_in[6];
    const float* Wv = (const float*)d_in[7];
    const float* bv = (const float*)d_in[8];
    const float* Wo = (const float*)d_in[9];
    const float* bo = (const float*)d_in[10];
    const float* W1 = (const float*)d_in[11];
    const float* b1 = (const float*)d_in[12];
    const float* W2 = (const float*)d_in[13];
    const float* b2 = (const float*)d_in[14];
    const float* g1 = (const float*)d_in[15];
    const float* be1 = (const float*)d_in[16];
    const float* g2 = (const float*)d_in[17];
    const float* be2 = (const float*)d_in[18];
    const float* gf = (const float*)d_in[19];
    const float* bf = (const float*)d_in[20];
    const int* mask = (const int*)d_in[21];

    float *x, *xv, *q, *k, *v, *ao, *o, *h, *h2;
    cudaGetSymbolAddress((void**)&x, g_x);
    cudaGetSymbolAddress((void**)&xv, g_xv);
    cudaGetSymbolAddress((void**)&q, g_q);
    cudaGetSymbolAddress((void**)&k, g_k);
    cudaGetSymbolAddress((void**)&v, g_v);
    cudaGetSymbolAddress((void**)&ao, g_ao);
    cudaGetSymbolAddress((void**)&o, g_o);
    cudaGetSymbolAddress((void**)&h, g_h);
    cudaGetSymbolAddress((void**)&h2, g_h2);

    const int M = BB * NN;  // 8192

    add_pos_kernel<<<(BB * NN * DD) / 256, 256>>>(input, input_v, pos_emb, x, xv);

    for (int i = 0; i < LL; i++) {
        const float* Wqi = Wq + (size_t)i * DD * DD;
        const float* Wki = Wk + (size_t)i * DD * DD;
        const float* Wvi = Wv + (size_t)i * DD * DD;
        const float* Woi = Wo + (size_t)i * DD * DD;
        const float* W1i = W1 + (size_t)i * DD * DFF;
        const float* W2i = W2 + (size_t)i * (DFF / 2) * (DD / 2);

        // QKV projections in one batched launch (z = 0,1,2)
        gemm_qkv_kernel<<<dim3(DD / GN, M / GM, 3), 256>>>(
            x, xv, Wqi, Wki, Wvi, bq + i * DD, bk + i * DD, bv + i * DD,
            q, k, v, M, DD, DD);

        // attention (tf32 tensor-core, sync-free dataflow)
        attn_kernel<<<dim3(NN / 16, HH, BB), 256>>>(
            q, k, v, mask, ao, (i % 2) ? 1 : 0);

        // output projection
        gemm128_kernel<<<dim3(DD / GN, M / GM), 256>>>(ao, Woi, bo + i * DD, o, M, DD, DD, 0);

        // x = LN(x + o)
        ln_kernel<<<M, 256>>>(x, o, g1 + i * DD, be1 + i * DD, x);

        // FFN1 + GELU
        gemm128_kernel<<<dim3(DFF / GN, M / GM), 256>>>(x, W1i, b1 + i * DFF, h, M, DD, DFF, 1);

        // FFN2 grouped: (B*N*2, 512) @ (512, 128) -> contiguous (B*N, 256)
        gemm128_kernel<<<dim3((DD / 2) / GN, (2 * M) / GM), 256>>>(
            h, W2i, b2 + i * (DD / 2), h2, 2 * M, DFF / 2, DD / 2, 0);

        // x = LN(x + h2)
        ln_kernel<<<M, 256>>>(x, h2, g2 + i * DD, be2 + i * DD, x);
    }

    // final LN -> output
    ln_kernel<<<M, 256>>>(x, nullptr, gf, bf, (float*)d_out);
}

// round 16
// speedup vs baseline: 4.0233x; 1.0185x over previous
#include <cuda_runtime.h>
#include <cuda_bf16.h>
#include <math.h>

#define BB 16
#define NN 512
#define DD 256
#define LL 4
#define HH 8
#define DK 32
#define DFF 1024

// tf32 round (rna) — result is a valid fp32 bit pattern with truncated mantissa
__device__ __forceinline__ float tf32r(float f) {
    unsigned r;
    asm("cvt.rna.tf32.f32 %0, %1;" : "=r"(r) : "f"(f));
    return __uint_as_float(r);
}

// m16n8k8 tf32 MMA, D += A*B (accumulate in place)
#define MMA_TF32(d, a0, a1, a2, a3, b0, b1)                          \
    asm("mma.sync.aligned.m16n8k8.row.col.f32.tf32.tf32.f32 "        \
        "{%0,%1,%2,%3}, {%4,%5,%6,%7}, {%8,%9}, {%0,%1,%2,%3};"      \
        : "+f"((d)[0]), "+f"((d)[1]), "+f"((d)[2]), "+f"((d)[3])     \
        : "r"(a0), "r"(a1), "r"(a2), "r"(a3), "r"(b0), "r"(b1))

// ------------------------- scratch (device globals) -------------------------
__device__ float g_x[BB * NN * DD];
__device__ float g_xv[BB * NN * DD];
__device__ float g_q[BB * NN * DD];
__device__ float g_k[BB * NN * DD];
__device__ float g_v[BB * NN * DD];
__device__ float g_ao[BB * NN * DD];
__device__ float g_o[BB * NN * DD];
__device__ float g_h[BB * NN * DFF];
__device__ float g_h2[BB * NN * DD];

// ------------------------- add positional embedding -------------------------
__global__ void add_pos_kernel(const float* __restrict__ in,
                               const float* __restrict__ in_v,
                               const float* __restrict__ pos,
                               float* __restrict__ x, float* __restrict__ xv) {
    size_t i = (size_t)blockIdx.x * 256 + threadIdx.x;
    float p = pos[i % (NN * DD)];
    x[i]  = in[i]  + p;
    xv[i] = in_v[i] + p;
}

// --------- 128x128x16 double-buffered GEMM body (tf32 tensor core) ----------
#define GM 128
#define GN 128
#define GKK 16
#define SP 136   // padded row: bank = (k*8 + idx) % 32 -> conflict-free frags

__device__ __forceinline__
void gemm128_body(const float* __restrict__ A,
                  const float* __restrict__ W,
                  const float* __restrict__ bias,
                  float* __restrict__ C,
                  int M, int K, int Nc, int apply_gelu) {
    __shared__ float As[2][GKK][SP];   // [k][row]
    __shared__ float Bs[2][GKK][SP];   // [k][col]
    const int tid = threadIdx.x;
    const int lane = tid & 31, warp = tid >> 5;
    const int wm = (warp & 3) * 32;    // warp row offset (4 warps in m)
    const int wn = (warp >> 2) * 64;   // warp col offset (2 warps in n)
    const int gID = lane >> 2, tq = lane & 3;
    const int row0 = blockIdx.y * GM, col0 = blockIdx.x * GN;

    const int arow = tid >> 1, ak0 = (tid & 1) * 4;
    const int brow = tid >> 5, bcol = (tid & 31) * 4;

    const float* Aptr = A + (size_t)(row0 + arow) * K + ak0;
    const float* Wptr = W + (size_t)brow * Nc + col0 + bcol;
    const size_t wstride8 = (size_t)8 * Nc;

    {
        float4 a0 = *(const float4*)Aptr;
        float4 a1 = *(const float4*)(Aptr + 8);
        float4 b0 = *(const float4*)Wptr;
        float4 b1 = *(const float4*)(Wptr + wstride8);
        As[0][ak0 + 0][arow] = tf32r(a0.x);
        As[0][ak0 + 1][arow] = tf32r(a0.y);
        As[0][ak0 + 2][arow] = tf32r(a0.z);
        As[0][ak0 + 3][arow] = tf32r(a0.w);
        As[0][ak0 + 8][arow] = tf32r(a1.x);
        As[0][ak0 + 9][arow] = tf32r(a1.y);
        As[0][ak0 + 10][arow] = tf32r(a1.z);
        As[0][ak0 + 11][arow] = tf32r(a1.w);
        *(float4*)&Bs[0][brow][bcol] =
            make_float4(tf32r(b0.x), tf32r(b0.y), tf32r(b0.z), tf32r(b0.w));
        *(float4*)&Bs[0][brow + 8][bcol] =
            make_float4(tf32r(b1.x), tf32r(b1.y), tf32r(b1.z), tf32r(b1.w));
    }
    __syncthreads();

    float acc[2][8][4];
#pragma unroll
    for (int mf = 0; mf < 2; mf++)
#pragma unroll
        for (int nf = 0; nf < 8; nf++)
#pragma unroll
            for (int c = 0; c < 4; c++) acc[mf][nf][c] = 0.0f;

    int buf = 0;
    for (int k0 = 0; k0 < K; k0 += GKK) {
        const bool has_next = (k0 + GKK < K);
        float4 na0, na1, nb0, nb1;
        if (has_next) {
            na0 = *(const float4*)(Aptr + k0 + GKK);
            na1 = *(const float4*)(Aptr + k0 + GKK + 8);
            nb0 = *(const float4*)(Wptr + (size_t)(k0 + GKK) * Nc);
            nb1 = *(const float4*)(Wptr + (size_t)(k0 + GKK) * Nc + wstride8);
        }

#pragma unroll
        for (int ks = 0; ks < 2; ks++) {
            const int kb = ks * 8;
            unsigned af[2][4];
#pragma unroll
            for (int mf = 0; mf < 2; mf++) {
                const int rb = wm + mf * 16 + gID;
                af[mf][0] = __float_as_uint(As[buf][kb + tq][rb]);
                af[mf][1] = __float_as_uint(As[buf][kb + tq][rb + 8]);
                af[mf][2] = __float_as_uint(As[buf][kb + tq + 4][rb]);
                af[mf][3] = __float_as_uint(As[buf][kb + tq + 4][rb + 8]);
            }
#pragma unroll
            for (int nf = 0; nf < 8; nf++) {
                const int cb = wn + nf * 8 + gID;
                unsigned b0 = __float_as_uint(Bs[buf][kb + tq][cb]);
                unsigned b1 = __float_as_uint(Bs[buf][kb + tq + 4][cb]);
                MMA_TF32(acc[0][nf], af[0][0], af[0][1], af[0][2], af[0][3], b0, b1);
                MMA_TF32(acc[1][nf], af[1][0], af[1][1], af[1][2], af[1][3], b0, b1);
            }
        }

        if (has_next) {
            As[buf ^ 1][ak0 + 0][arow] = tf32r(na0.x);
            As[buf ^ 1][ak0 + 1][arow] = tf32r(na0.y);
            As[buf ^ 1][ak0 + 2][arow] = tf32r(na0.z);
            As[buf ^ 1][ak0 + 3][arow] = tf32r(na0.w);
            As[buf ^ 1][ak0 + 8][arow] = tf32r(na1.x);
            As[buf ^ 1][ak0 + 9][arow] = tf32r(na1.y);
            As[buf ^ 1][ak0 + 10][arow] = tf32r(na1.z);
            As[buf ^ 1][ak0 + 11][arow] = tf32r(na1.w);
            *(float4*)&Bs[buf ^ 1][brow][bcol] =
                make_float4(tf32r(nb0.x), tf32r(nb0.y), tf32r(nb0.z), tf32r(nb0.w));
            *(float4*)&Bs[buf ^ 1][brow + 8][bcol] =
                make_float4(tf32r(nb1.x), tf32r(nb1.y), tf32r(nb1.z), tf32r(nb1.w));
            __syncthreads();
            buf ^= 1;
        }
    }

    // epilogue: C fragment layout -> bias (+gelu) -> float2 stores
#pragma unroll
    for (int mf = 0; mf < 2; mf++) {
        const int r0 = row0 + wm + mf * 16 + gID;
#pragma unroll
        for (int nf = 0; nf < 8; nf++) {
            const int c = col0 + wn + nf * 8 + tq * 2;
            const float bx = bias[c], by = bias[c + 1];
            float v0 = acc[mf][nf][0] + bx;
            float v1 = acc[mf][nf][1] + by;
            float v2 = acc[mf][nf][2] + bx;
            float v3 = acc[mf][nf][3] + by;
            if (apply_gelu) {
                v0 = 0.5f * v0 * (1.0f + erff(v0 * 0.70710678118654752f));
                v1 = 0.5f * v1 * (1.0f + erff(v1 * 0.70710678118654752f));
                v2 = 0.5f * v2 * (1.0f + erff(v2 * 0.70710678118654752f));
                v3 = 0.5f * v3 * (1.0f + erff(v3 * 0.70710678118654752f));
            }
            *(float2*)&C[(size_t)r0 * Nc + c] = make_float2(v0, v1);
            *(float2*)&C[(size_t)(r0 + 8) * Nc + c] = make_float2(v2, v3);
        }
    }
}

__global__ __launch_bounds__(256, 2)
void gemm128_kernel(const float* __restrict__ A,
                    const float* __restrict__ W,
                    const float* __restrict__ bias,
                    float* __restrict__ C,
                    int M, int K, int Nc, int apply_gelu) {
    gemm128_body(A, W, bias, C, M, K, Nc, apply_gelu);
}

// Batched QKV: blockIdx.z selects {x@Wq, x@Wk, xv@Wv}. One launch, 3x grid.
__global__ __launch_bounds__(256, 2)
void gemm_qkv_kernel(const float* __restrict__ x, const float* __restrict__ xv,
                     const float* __restrict__ Wq, const float* __restrict__ Wk,
                     const float* __restrict__ Wv,
                     const float* __restrict__ bq, const float* __restrict__ bk,
                     const float* __restrict__ bv,
                     float* __restrict__ q, float* __restrict__ k,
                     float* __restrict__ v, int M, int K, int Nc) {
    const float* A;
    const float* W;
    const float* b;
    float* C;
    if (blockIdx.z == 0)      { A = x;  W = Wq; b = bq; C = q; }
    else if (blockIdx.z == 1) { A = x;  W = Wk; b = bk; C = k; }
    else                      { A = xv; W = Wv; b = bv; C = v; }
    gemm128_body(A, W, b, C, M, K, Nc, 0);
}

// ------------------- fused attention (tf32, sync-free dataflow) -------------
// 16-query tiles, grid (N/16, H, B), block 256 (8 warps).
// Score: warp w = one 8-key n-tile per 64-key chunk; K frags straight from gmem.
// Softmax writes tf32-rounded P -> PV loads raw bits (no cvt).
// PV:    warp w -> dk-tile (w&3), key-half (w>>2); V frags straight from gmem;
//        2-way cross-warp reduce via dedicated smem buffer.
// mask read as 32-bit words (nonzero == True).
#define SPS 516   // S row stride: bank = (4*row + col) % 32 -> conflict-free col frags

__global__ void attn_kernel(const float* __restrict__ q,
                            const float* __restrict__ k,
                            const float* __restrict__ v,
                            const int* __restrict__ mask,
                            float* __restrict__ out, int use_mask) {
    const int b = blockIdx.z, h = blockIdx.y, q0 = blockIdx.x * 16;
    __shared__ float Qs[16][33];
    __shared__ float S[16][SPS];
    __shared__ float red[512];
    const int tid = threadIdx.x;
    const int lane = tid & 31, warp = tid >> 5;
    const int gID = lane >> 2, tq = lane & 3;
    const float scale = 0.17677669529663687f;  // 1/sqrt(32)

    // stage Q tile (tf32)
    for (int e = tid; e < 16 * 32; e += 256) {
        int r = e >> 5, d = e & 31;
        Qs[r][d] = tf32r(q[(size_t)(b * NN + q0 + r) * DD + h * DK + d]);
    }
    __syncthreads();

    // Q fragments: rows (gID, gID+8), k-cols (kc*8+tq, +4). Reused all chunks.
    unsigned qf[4][4];
#pragma unroll
    for (int kc = 0; kc < 4; kc++) {
        qf[kc][0] = __float_as_uint(Qs[gID][kc * 8 + tq]);
        qf[kc][1] = __float_as_uint(Qs[gID + 8][kc * 8 + tq]);
        qf[kc][2] = __float_as_uint(Qs[gID][kc * 8 + tq + 4]);
        qf[kc][3] = __float_as_uint(Qs[gID + 8][kc * 8 + tq + 4]);
    }

    // ---- scores: S = (Q @ K^T) * scale, masked.  K frags direct from gmem ----
    {
        // warp's 8 private key rows: key = c64 + warp*8 + gID
        const float* kbase = k + (size_t)(b * NN + warp * 8 + gID) * DD + h * DK + tq;
        for (int c64 = 0; c64 < NN; c64 += 64) {
            const float* kp = kbase + (size_t)c64 * DD;
            float acc[4] = {0.0f, 0.0f, 0.0f, 0.0f};
#pragma unroll
            for (int kc = 0; kc < 4; kc++) {
                unsigned b0 = __float_as_uint(tf32r(kp[kc * 8]));
                unsigned b1 = __float_as_uint(tf32r(kp[kc * 8 + 4]));
                MMA_TF32(acc, qf[kc][0], qf[kc][1], qf[kc][2], qf[kc][3], b0, b1);
            }
            const int coln = c64 + warp * 8 + 2 * tq;
            float s0 = acc[0] * scale, s1 = acc[1] * scale;
            float s2 = acc[2] * scale, s3 = acc[3] * scale;
            if (use_mask) {
                int2 m0 = *(const int2*)&mask[(size_t)(q0 + gID) * NN + coln];
                int2 m1 = *(const int2*)&mask[(size_t)(q0 + gID + 8) * NN + coln];
                if (m0.x) s0 = -1e30f;
                if (m0.y) s1 = -1e30f;
                if (m1.x) s2 = -1e30f;
                if (m1.y) s3 = -1e30f;
            }
            *(float2*)&S[gID][coln] = make_float2(s0, s1);
            *(float2*)&S[gID + 8][coln] = make_float2(s2, s3);
        }
    }
    __syncthreads();

    // ---- softmax: 8 warps, 2 rows each.  Final store is tf32-rounded P. ----
    for (int r = warp; r < 16; r += 8) {
        float* Sr = &S[r][0];
        float mx = -1e30f;
        for (int c = lane; c < NN; c += 32) mx = fmaxf(mx, Sr[c]);
#pragma unroll
        for (int o = 16; o; o >>= 1) mx = fmaxf(mx, __shfl_xor_sync(0xFFFFFFFFu, mx, o));
        float sum = 0.0f;
        for (int c = lane; c < NN; c += 32) {
            float e = __expf(Sr[c] - mx);
            Sr[c] = e;
            sum += e;
        }
#pragma unroll
        for (int o = 16; o; o >>= 1) sum += __shfl_xor_sync(0xFFFFFFFFu, sum, o);
        float inv = 1.0f / sum;
        for (int c = lane; c < NN; c += 32) Sr[c] = tf32r(Sr[c] * inv);
    }
    __syncthreads();

    // ---- O = P @ V.  V frags direct from gmem; P already tf32 in S ----
    const int ntile = warp & 3;          // dk-tile (8 cols of 32)
    const int kb = (warp >> 2) * 32;     // key-half within each 64-key chunk
    float oacc[4] = {0.0f, 0.0f, 0.0f, 0.0f};
    {
        // b0 row = c64 + kb + ks*8 + tq; col = ntile*8 + gID.  b1 = row + 4.
        const float* vbase = v + (size_t)(b * NN + kb + tq) * DD + h * DK + ntile * 8 + gID;
        for (int c64 = 0; c64 < NN; c64 += 64) {
#pragma unroll
            for (int ks = 0; ks < 4; ks++) {
                const int kg = c64 + kb + ks * 8;   // global key base for S cols
                unsigned a0 = __float_as_uint(S[gID][kg + tq]);
                unsigned a1 = __float_as_uint(S[gID + 8][kg + tq]);
                unsigned a2 = __float_as_uint(S[gID][kg + tq + 4]);
                unsigned a3 = __float_as_uint(S[gID + 8][kg + tq + 4]);
                const float* vp = vbase + (size_t)(c64 + ks * 8) * DD;
                unsigned b0 = __float_as_uint(tf32r(vp[0]));
                unsigned b1 = __float_as_uint(tf32r(vp[4 * DD]));
                MMA_TF32(oacc, a0, a1, a2, a3, b0, b1);
            }
        }
    }
    // 2-way reduction: warps 4-7 stash partials
    if (warp >= 4) {
        const int base = (warp - 4) * 128 + lane * 4;
        red[base + 0] = oacc[0];
        red[base + 1] = oacc[1];
        red[base + 2] = oacc[2];
        red[base + 3] = oacc[3];
    }
    __syncthreads();
    if (warp < 4) {
        const int base = warp * 128 + lane * 4;
        oacc[0] += red[base + 0];
        oacc[1] += red[base + 1];
        oacc[2] += red[base + 2];
        oacc[3] += red[base + 3];
        const int colo = h * DK + ntile * 8 + 2 * tq;
        *(float2*)&out[(size_t)(b * NN + q0 + gID) * DD + colo] =
            make_float2(oacc[0], oacc[1]);
        *(float2*)&out[(size_t)(b * NN + q0 + gID + 8) * DD + colo] =
            make_float2(oacc[2], oacc[3]);
    }
}

// ------------------- residual + layernorm (warp-per-row) --------------------
// grid: B*N/8 blocks, 256 threads = 8 warps, one row per warp. No block sync.
__global__ void ln_kernel(const float* __restrict__ x,
                          const float* __restrict__ res,
                          const float* __restrict__ g,
                          const float* __restrict__ bta,
                          float* __restrict__ out) {
    const int warp = threadIdx.x >> 5, lane = threadIdx.x & 31;
    const int row = blockIdx.x * 8 + warp;
    const int col = lane * 8;
    size_t base = (size_t)row * DD + col;

    float4 v0 = *(const float4*)&x[base];
    float4 v1 = *(const float4*)&x[base + 4];
    if (res) {
        float4 r0 = *(const float4*)&res[base];
        float4 r1 = *(const float4*)&res[base + 4];
        v0.x += r0.x; v0.y += r0.y; v0.z += r0.z; v0.w += r0.w;
        v1.x += r1.x; v1.y += r1.y; v1.z += r1.z; v1.w += r1.w;
    }
    float vals[8] = {v0.x, v0.y, v0.z, v0.w, v1.x, v1.y, v1.z, v1.w};
    float s = 0.0f, s2 = 0.0f;
#pragma unroll
    for (int j = 0; j < 8; j++) {
        s += vals[j];
        s2 += vals[j] * vals[j];
    }
#pragma unroll
    for (int o = 16; o; o >>= 1) {
        s  += __shfl_xor_sync(0xFFFFFFFFu, s, o);
        s2 += __shfl_xor_sync(0xFFFFFFFFu, s2, o);
    }
    float mean = s * (1.0f / DD);
    float var = s2 * (1.0f / DD) - mean * mean;
    float rstd = rsqrtf(var + 1e-5f);

    float4 g0 = *(const float4*)&g[col];
    float4 g1 = *(const float4*)&g[col + 4];
    float4 b0 = *(const float4*)&bta[col];
    float4 b1 = *(const float4*)&bta[col + 4];
    float go[8] = {g0.x, g0.y, g0.z, g0.w, g1.x, g1.y, g1.z, g1.w};
    float bo[8] = {b0.x, b0.y, b0.z, b0.w, b1.x, b1.y, b1.z, b1.w};
    float o0[8];
#pragma unroll
    for (int j = 0; j < 8; j++)
        o0[j] = (vals[j] - mean) * rstd * go[j] + bo[j];
    *(float4*)&out[base] = *(float4*)o0;
    *(float4*)&out[base + 4] = *(float4*)(o0 + 4);
}

// ------------------------- launch -------------------------
extern "C" void kernel_launch(void* const* d_in, const int* in_sizes, int n_in,
                              void* d_out, int out_size) {
    const float* input   = (const float*)d_in[0];
    const float* input_v = (const float*)d_in[1];
    const float* pos_emb = (const float*)d_in[2];
    const float* Wq = (const float*)d_in[3];
    const float* bq = (const float*)d_in[4];
    const float* Wk = (const float*)d_in[5];
    const float* bk = (const float*)d_in[6];
    const float* Wv = (const float*)d_in[7];
    const float* bv = (const float*)d_in[8];
    const float* Wo = (const float*)d_in[9];
    const float* bo = (const float*)d_in[10];
    const float* W1 = (const float*)d_in[11];
    const float* b1 = (const float*)d_in[12];
    const float* W2 = (const float*)d_in[13];
    const float* b2 = (const float*)d_in[14];
    const float* g1 = (const float*)d_in[15];
    const float* be1 = (const float*)d_in[16];
    const float* g2 = (const float*)d_in[17];
    const float* be2 = (const float*)d_in[18];
    const float* gf = (const float*)d_in[19];
    const float* bf = (const float*)d_in[20];
    const int* mask = (const int*)d_in[21];

    float *x, *xv, *q, *k, *v, *ao, *o, *h, *h2;
    cudaGetSymbolAddress((void**)&x, g_x);
    cudaGetSymbolAddress((void**)&xv, g_xv);
    cudaGetSymbolAddress((void**)&q, g_q);
    cudaGetSymbolAddress((void**)&k, g_k);
    cudaGetSymbolAddress((void**)&v, g_v);
    cudaGetSymbolAddress((void**)&ao, g_ao);
    cudaGetSymbolAddress((void**)&o, g_o);
    cudaGetSymbolAddress((void**)&h, g_h);
    cudaGetSymbolAddress((void**)&h2, g_h2);

    const int M = BB * NN;  // 8192

    add_pos_kernel<<<(BB * NN * DD) / 256, 256>>>(input, input_v, pos_emb, x, xv);

    for (int i = 0; i < LL; i++) {
        const float* Wqi = Wq + (size_t)i * DD * DD;
        const float* Wki = Wk + (size_t)i * DD * DD;
        const float* Wvi = Wv + (size_t)i * DD * DD;
        const float* Woi = Wo + (size_t)i * DD * DD;
        const float* W1i = W1 + (size_t)i * DD * DFF;
        const float* W2i = W2 + (size_t)i * (DFF / 2) * (DD / 2);

        // QKV projections in one batched launch (z = 0,1,2)
        gemm_qkv_kernel<<<dim3(DD / GN, M / GM, 3), 256>>>(
            x, xv, Wqi, Wki, Wvi, bq + i * DD, bk + i * DD, bv + i * DD,
            q, k, v, M, DD, DD);

        // attention (tf32 tensor-core, sync-free dataflow)
        attn_kernel<<<dim3(NN / 16, HH, BB), 256>>>(
            q, k, v, mask, ao, (i % 2) ? 1 : 0);

        // output projection
        gemm128_kernel<<<dim3(DD / GN, M / GM), 256>>>(ao, Woi, bo + i * DD, o, M, DD, DD, 0);

        // x = LN(x + o)
        ln_kernel<<<M / 8, 256>>>(x, o, g1 + i * DD, be1 + i * DD, x);

        // FFN1 + GELU
        gemm128_kernel<<<dim3(DFF / GN, M / GM), 256>>>(x, W1i, b1 + i * DFF, h, M, DD, DFF, 1);

        // FFN2 grouped: (B*N*2, 512) @ (512, 128) -> contiguous (B*N, 256)
        gemm128_kernel<<<dim3((DD / 2) / GN, (2 * M) / GM), 256>>>(
            h, W2i, b2 + i * (DD / 2), h2, 2 * M, DFF / 2, DD / 2, 0);

        // x = LN(x + h2)
        ln_kernel<<<M / 8, 256>>>(x, h2, g2 + i * DD, be2 + i * DD, x);
    }

    // final LN -> output
    ln_kernel<<<M / 8, 256>>>(x, nullptr, gf, bf, (float*)d_out);
}

// round 17
// speedup vs baseline: 4.0512x; 1.0069x over previous
#include <cuda_runtime.h>
#include <cuda_bf16.h>
#include <math.h>

#define BB 16
#define NN 512
#define DD 256
#define LL 4
#define HH 8
#define DK 32
#define DFF 1024

// tf32 round (rna) — result is a valid fp32 bit pattern with truncated mantissa
__device__ __forceinline__ float tf32r(float f) {
    unsigned r;
    asm("cvt.rna.tf32.f32 %0, %1;" : "=r"(r) : "f"(f));
    return __uint_as_float(r);
}

// m16n8k8 tf32 MMA, D += A*B (accumulate in place)
#define MMA_TF32(d, a0, a1, a2, a3, b0, b1)                          \
    asm("mma.sync.aligned.m16n8k8.row.col.f32.tf32.tf32.f32 "        \
        "{%0,%1,%2,%3}, {%4,%5,%6,%7}, {%8,%9}, {%0,%1,%2,%3};"      \
        : "+f"((d)[0]), "+f"((d)[1]), "+f"((d)[2]), "+f"((d)[3])     \
        : "r"(a0), "r"(a1), "r"(a2), "r"(a3), "r"(b0), "r"(b1))

// ------------------------- scratch (device globals) -------------------------
__device__ float g_x[BB * NN * DD];
__device__ float g_xv[BB * NN * DD];
__device__ float g_q[BB * NN * DD];
__device__ float g_k[BB * NN * DD];
__device__ float g_v[BB * NN * DD];
__device__ float g_ao[BB * NN * DD];
__device__ float g_o[BB * NN * DD];
__device__ float g_h[BB * NN * DFF];
__device__ float g_h2[BB * NN * DD];

// ------------------------- add positional embedding -------------------------
__global__ void add_pos_kernel(const float* __restrict__ in,
                               const float* __restrict__ in_v,
                               const float* __restrict__ pos,
                               float* __restrict__ x, float* __restrict__ xv) {
    size_t i = (size_t)blockIdx.x * 256 + threadIdx.x;
    float p = pos[i % (NN * DD)];
    x[i]  = in[i]  + p;
    xv[i] = in_v[i] + p;
}

// --------- 64x128x16 double-buffered GEMM body (tf32 tensor core) -----------
// Smaller M-tile -> grids >= 256 blocks -> >=2 CTAs/SM for latency hiding.
// 8 warps: 2 in m (32 rows each) x 4 in n (32 cols each). acc = 2x4 frags.
#define GM 64
#define GN 128
#define GKK 16
#define SPA 72    // A row stride: 72 % 32 == 8 -> conflict-free frag loads
#define SPB 136   // B row stride: 136 % 32 == 8

__device__ __forceinline__
void gemm64_body(const float* __restrict__ A,
                 const float* __restrict__ W,
                 const float* __restrict__ bias,
                 float* __restrict__ C,
                 int M, int K, int Nc, int apply_gelu) {
    __shared__ float As[2][GKK][SPA];   // [k][row], 64 rows
    __shared__ float Bs[2][GKK][SPB];   // [k][col], 128 cols
    const int tid = threadIdx.x;
    const int lane = tid & 31, warp = tid >> 5;
    const int wm = (warp & 1) * 32;     // warp row offset (2 warps in m)
    const int wn = (warp >> 1) * 32;    // warp col offset (4 warps in n)
    const int gID = lane >> 2, tq = lane & 3;
    const int row0 = blockIdx.y * GM, col0 = blockIdx.x * GN;

    // A: each thread stores 1 float4: row = tid>>2 (0..63), kquad = (tid&3)*4
    const int arow = tid >> 2, ak0 = (tid & 3) * 4;
    // B: each thread stores 2 float4s: k rows brow, brow+8; cols bcol..bcol+3
    const int brow = tid >> 5, bcol = (tid & 31) * 4;

    const float* Aptr = A + (size_t)(row0 + arow) * K + ak0;
    const float* Wptr = W + (size_t)brow * Nc + col0 + bcol;
    const size_t wstride8 = (size_t)8 * Nc;

    {
        float4 a0 = *(const float4*)Aptr;
        float4 b0 = *(const float4*)Wptr;
        float4 b1 = *(const float4*)(Wptr + wstride8);
        As[0][ak0 + 0][arow] = tf32r(a0.x);
        As[0][ak0 + 1][arow] = tf32r(a0.y);
        As[0][ak0 + 2][arow] = tf32r(a0.z);
        As[0][ak0 + 3][arow] = tf32r(a0.w);
        *(float4*)&Bs[0][brow][bcol] =
            make_float4(tf32r(b0.x), tf32r(b0.y), tf32r(b0.z), tf32r(b0.w));
        *(float4*)&Bs[0][brow + 8][bcol] =
            make_float4(tf32r(b1.x), tf32r(b1.y), tf32r(b1.z), tf32r(b1.w));
    }
    __syncthreads();

    float acc[2][4][4];
#pragma unroll
    for (int mf = 0; mf < 2; mf++)
#pragma unroll
        for (int nf = 0; nf < 4; nf++)
#pragma unroll
            for (int c = 0; c < 4; c++) acc[mf][nf][c] = 0.0f;

    int buf = 0;
    for (int k0 = 0; k0 < K; k0 += GKK) {
        const bool has_next = (k0 + GKK < K);
        float4 na0, nb0, nb1;
        if (has_next) {
            na0 = *(const float4*)(Aptr + k0 + GKK);
            nb0 = *(const float4*)(Wptr + (size_t)(k0 + GKK) * Nc);
            nb1 = *(const float4*)(Wptr + (size_t)(k0 + GKK) * Nc + wstride8);
        }

#pragma unroll
        for (int ks = 0; ks < 2; ks++) {
            const int kb = ks * 8;
            unsigned af[2][4];
#pragma unroll
            for (int mf = 0; mf < 2; mf++) {
                const int rb = wm + mf * 16 + gID;
                af[mf][0] = __float_as_uint(As[buf][kb + tq][rb]);
                af[mf][1] = __float_as_uint(As[buf][kb + tq][rb + 8]);
                af[mf][2] = __float_as_uint(As[buf][kb + tq + 4][rb]);
                af[mf][3] = __float_as_uint(As[buf][kb + tq + 4][rb + 8]);
            }
#pragma unroll
            for (int nf = 0; nf < 4; nf++) {
                const int cb = wn + nf * 8 + gID;
                unsigned b0 = __float_as_uint(Bs[buf][kb + tq][cb]);
                unsigned b1 = __float_as_uint(Bs[buf][kb + tq + 4][cb]);
                MMA_TF32(acc[0][nf], af[0][0], af[0][1], af[0][2], af[0][3], b0, b1);
                MMA_TF32(acc[1][nf], af[1][0], af[1][1], af[1][2], af[1][3], b0, b1);
            }
        }

        if (has_next) {
            As[buf ^ 1][ak0 + 0][arow] = tf32r(na0.x);
            As[buf ^ 1][ak0 + 1][arow] = tf32r(na0.y);
            As[buf ^ 1][ak0 + 2][arow] = tf32r(na0.z);
            As[buf ^ 1][ak0 + 3][arow] = tf32r(na0.w);
            *(float4*)&Bs[buf ^ 1][brow][bcol] =
                make_float4(tf32r(nb0.x), tf32r(nb0.y), tf32r(nb0.z), tf32r(nb0.w));
            *(float4*)&Bs[buf ^ 1][brow + 8][bcol] =
                make_float4(tf32r(nb1.x), tf32r(nb1.y), tf32r(nb1.z), tf32r(nb1.w));
            __syncthreads();
            buf ^= 1;
        }
    }

    // epilogue: C fragment layout -> bias (+gelu) -> float2 stores
#pragma unroll
    for (int mf = 0; mf < 2; mf++) {
        const int r0 = row0 + wm + mf * 16 + gID;
#pragma unroll
        for (int nf = 0; nf < 4; nf++) {
            const int c = col0 + wn + nf * 8 + tq * 2;
            const float bx = bias[c], by = bias[c + 1];
            float v0 = acc[mf][nf][0] + bx;
            float v1 = acc[mf][nf][1] + by;
            float v2 = acc[mf][nf][2] + bx;
            float v3 = acc[mf][nf][3] + by;
            if (apply_gelu) {
                v0 = 0.5f * v0 * (1.0f + erff(v0 * 0.70710678118654752f));
                v1 = 0.5f * v1 * (1.0f + erff(v1 * 0.70710678118654752f));
                v2 = 0.5f * v2 * (1.0f + erff(v2 * 0.70710678118654752f));
                v3 = 0.5f * v3 * (1.0f + erff(v3 * 0.70710678118654752f));
            }
            *(float2*)&C[(size_t)r0 * Nc + c] = make_float2(v0, v1);
            *(float2*)&C[(size_t)(r0 + 8) * Nc + c] = make_float2(v2, v3);
        }
    }
}

__global__ __launch_bounds__(256, 2)
void gemm128_kernel(const float* __restrict__ A,
                    const float* __restrict__ W,
                    const float* __restrict__ bias,
                    float* __restrict__ C,
                    int M, int K, int Nc, int apply_gelu) {
    gemm64_body(A, W, bias, C, M, K, Nc, apply_gelu);
}

// Batched QKV: blockIdx.z selects {x@Wq, x@Wk, xv@Wv}. One launch, 3x grid.
__global__ __launch_bounds__(256, 2)
void gemm_qkv_kernel(const float* __restrict__ x, const float* __restrict__ xv,
                     const float* __restrict__ Wq, const float* __restrict__ Wk,
                     const float* __restrict__ Wv,
                     const float* __restrict__ bq, const float* __restrict__ bk,
                     const float* __restrict__ bv,
                     float* __restrict__ q, float* __restrict__ k,
                     float* __restrict__ v, int M, int K, int Nc) {
    const float* A;
    const float* W;
    const float* b;
    float* C;
    if (blockIdx.z == 0)      { A = x;  W = Wq; b = bq; C = q; }
    else if (blockIdx.z == 1) { A = x;  W = Wk; b = bk; C = k; }
    else                      { A = xv; W = Wv; b = bv; C = v; }
    gemm64_body(A, W, b, C, M, K, Nc, 0);
}

// ------------------- fused attention (tf32, sync-free dataflow) -------------
// 16-query tiles, grid (N/16, H, B), block 256 (8 warps).
// Score: warp w = one 8-key n-tile per 64-key chunk; K frags straight from gmem.
// Softmax writes tf32-rounded P -> PV loads raw bits (no cvt).
// PV:    warp w -> dk-tile (w&3), key-half (w>>2); V frags straight from gmem;
//        2-way cross-warp reduce via dedicated smem buffer.
// mask read as 32-bit words (nonzero == True).
#define SPS 516   // S row stride: bank = (4*row + col) % 32 -> conflict-free col frags

__global__ void attn_kernel(const float* __restrict__ q,
                            const float* __restrict__ k,
                            const float* __restrict__ v,
                            const int* __restrict__ mask,
                            float* __restrict__ out, int use_mask) {
    const int b = blockIdx.z, h = blockIdx.y, q0 = blockIdx.x * 16;
    __shared__ float Qs[16][33];
    __shared__ float S[16][SPS];
    __shared__ float red[512];
    const int tid = threadIdx.x;
    const int lane = tid & 31, warp = tid >> 5;
    const int gID = lane >> 2, tq = lane & 3;
    const float scale = 0.17677669529663687f;  // 1/sqrt(32)

    // stage Q tile (tf32)
    for (int e = tid; e < 16 * 32; e += 256) {
        int r = e >> 5, d = e & 31;
        Qs[r][d] = tf32r(q[(size_t)(b * NN + q0 + r) * DD + h * DK + d]);
    }
    __syncthreads();

    // Q fragments: rows (gID, gID+8), k-cols (kc*8+tq, +4). Reused all chunks.
    unsigned qf[4][4];
#pragma unroll
    for (int kc = 0; kc < 4; kc++) {
        qf[kc][0] = __float_as_uint(Qs[gID][kc * 8 + tq]);
        qf[kc][1] = __float_as_uint(Qs[gID + 8][kc * 8 + tq]);
        qf[kc][2] = __float_as_uint(Qs[gID][kc * 8 + tq + 4]);
        qf[kc][3] = __float_as_uint(Qs[gID + 8][kc * 8 + tq + 4]);
    }

    // ---- scores: S = (Q @ K^T) * scale, masked.  K frags direct from gmem ----
    {
        // warp's 8 private key rows: key = c64 + warp*8 + gID
        const float* kbase = k + (size_t)(b * NN + warp * 8 + gID) * DD + h * DK + tq;
        for (int c64 = 0; c64 < NN; c64 += 64) {
            const float* kp = kbase + (size_t)c64 * DD;
            float acc[4] = {0.0f, 0.0f, 0.0f, 0.0f};
#pragma unroll
            for (int kc = 0; kc < 4; kc++) {
                unsigned b0 = __float_as_uint(tf32r(kp[kc * 8]));
                unsigned b1 = __float_as_uint(tf32r(kp[kc * 8 + 4]));
                MMA_TF32(acc, qf[kc][0], qf[kc][1], qf[kc][2], qf[kc][3], b0, b1);
            }
            const int coln = c64 + warp * 8 + 2 * tq;
            float s0 = acc[0] * scale, s1 = acc[1] * scale;
            float s2 = acc[2] * scale, s3 = acc[3] * scale;
            if (use_mask) {
                int2 m0 = *(const int2*)&mask[(size_t)(q0 + gID) * NN + coln];
                int2 m1 = *(const int2*)&mask[(size_t)(q0 + gID + 8) * NN + coln];
                if (m0.x) s0 = -1e30f;
                if (m0.y) s1 = -1e30f;
                if (m1.x) s2 = -1e30f;
                if (m1.y) s3 = -1e30f;
            }
            *(float2*)&S[gID][coln] = make_float2(s0, s1);
            *(float2*)&S[gID + 8][coln] = make_float2(s2, s3);
        }
    }
    __syncthreads();

    // ---- softmax: 8 warps, 2 rows each.  Final store is tf32-rounded P. ----
    for (int r = warp; r < 16; r += 8) {
        float* Sr = &S[r][0];
        float mx = -1e30f;
        for (int c = lane; c < NN; c += 32) mx = fmaxf(mx, Sr[c]);
#pragma unroll
        for (int o = 16; o; o >>= 1) mx = fmaxf(mx, __shfl_xor_sync(0xFFFFFFFFu, mx, o));
        float sum = 0.0f;
        for (int c = lane; c < NN; c += 32) {
            float e = __expf(Sr[c] - mx);
            Sr[c] = e;
            sum += e;
        }
#pragma unroll
        for (int o = 16; o; o >>= 1) sum += __shfl_xor_sync(0xFFFFFFFFu, sum, o);
        float inv = 1.0f / sum;
        for (int c = lane; c < NN; c += 32) Sr[c] = tf32r(Sr[c] * inv);
    }
    __syncthreads();

    // ---- O = P @ V.  V frags direct from gmem; P already tf32 in S ----
    const int ntile = warp & 3;          // dk-tile (8 cols of 32)
    const int kb = (warp >> 2) * 32;     // key-half within each 64-key chunk
    float oacc[4] = {0.0f, 0.0f, 0.0f, 0.0f};
    {
        // b0 row = c64 + kb + ks*8 + tq; col = ntile*8 + gID.  b1 = row + 4.
        const float* vbase = v + (size_t)(b * NN + kb + tq) * DD + h * DK + ntile * 8 + gID;
        for (int c64 = 0; c64 < NN; c64 += 64) {
#pragma unroll
            for (int ks = 0; ks < 4; ks++) {
                const int kg = c64 + kb + ks * 8;   // global key base for S cols
                unsigned a0 = __float_as_uint(S[gID][kg + tq]);
                unsigned a1 = __float_as_uint(S[gID + 8][kg + tq]);
                unsigned a2 = __float_as_uint(S[gID][kg + tq + 4]);
                unsigned a3 = __float_as_uint(S[gID + 8][kg + tq + 4]);
                const float* vp = vbase + (size_t)(c64 + ks * 8) * DD;
                unsigned b0 = __float_as_uint(tf32r(vp[0]));
                unsigned b1 = __float_as_uint(tf32r(vp[4 * DD]));
                MMA_TF32(oacc, a0, a1, a2, a3, b0, b1);
            }
        }
    }
    // 2-way reduction: warps 4-7 stash partials
    if (warp >= 4) {
        const int base = (warp - 4) * 128 + lane * 4;
        red[base + 0] = oacc[0];
        red[base + 1] = oacc[1];
        red[base + 2] = oacc[2];
        red[base + 3] = oacc[3];
    }
    __syncthreads();
    if (warp < 4) {
        const int base = warp * 128 + lane * 4;
        oacc[0] += red[base + 0];
        oacc[1] += red[base + 1];
        oacc[2] += red[base + 2];
        oacc[3] += red[base + 3];
        const int colo = h * DK + ntile * 8 + 2 * tq;
        *(float2*)&out[(size_t)(b * NN + q0 + gID) * DD + colo] =
            make_float2(oacc[0], oacc[1]);
        *(float2*)&out[(size_t)(b * NN + q0 + gID + 8) * DD + colo] =
            make_float2(oacc[2], oacc[3]);
    }
}

// ------------------- residual + layernorm (warp-per-row) --------------------
// grid: B*N/8 blocks, 256 threads = 8 warps, one row per warp. No block sync.
__global__ void ln_kernel(const float* __restrict__ x,
                          const float* __restrict__ res,
                          const float* __restrict__ g,
                          const float* __restrict__ bta,
                          float* __restrict__ out) {
    const int warp = threadIdx.x >> 5, lane = threadIdx.x & 31;
    const int row = blockIdx.x * 8 + warp;
    const int col = lane * 8;
    size_t base = (size_t)row * DD + col;

    float4 v0 = *(const float4*)&x[base];
    float4 v1 = *(const float4*)&x[base + 4];
    if (res) {
        float4 r0 = *(const float4*)&res[base];
        float4 r1 = *(const float4*)&res[base + 4];
        v0.x += r0.x; v0.y += r0.y; v0.z += r0.z; v0.w += r0.w;
        v1.x += r1.x; v1.y += r1.y; v1.z += r1.z; v1.w += r1.w;
    }
    float vals[8] = {v0.x, v0.y, v0.z, v0.w, v1.x, v1.y, v1.z, v1.w};
    float s = 0.0f, s2 = 0.0f;
#pragma unroll
    for (int j = 0; j < 8; j++) {
        s += vals[j];
        s2 += vals[j] * vals[j];
    }
#pragma unroll
    for (int o = 16; o; o >>= 1) {
        s  += __shfl_xor_sync(0xFFFFFFFFu, s, o);
        s2 += __shfl_xor_sync(0xFFFFFFFFu, s2, o);
    }
    float mean = s * (1.0f / DD);
    float var = s2 * (1.0f / DD) - mean * mean;
    float rstd = rsqrtf(var + 1e-5f);

    float4 g0 = *(const float4*)&g[col];
    float4 g1 = *(const float4*)&g[col + 4];
    float4 b0 = *(const float4*)&bta[col];
    float4 b1 = *(const float4*)&bta[col + 4];
    float go[8] = {g0.x, g0.y, g0.z, g0.w, g1.x, g1.y, g1.z, g1.w};
    float bo[8] = {b0.x, b0.y, b0.z, b0.w, b1.x, b1.y, b1.z, b1.w};
    float o0[8];
#pragma unroll
    for (int j = 0; j < 8; j++)
        o0[j] = (vals[j] - mean) * rstd * go[j] + bo[j];
    *(float4*)&out[base] = *(float4*)o0;
    *(float4*)&out[base + 4] = *(float4*)(o0 + 4);
}

// ------------------------- launch -------------------------
extern "C" void kernel_launch(void* const* d_in, const int* in_sizes, int n_in,
                              void* d_out, int out_size) {
    const float* input   = (const float*)d_in[0];
    const float* input_v = (const float*)d_in[1];
    const float* pos_emb = (const float*)d_in[2];
    const float* Wq = (const float*)d_in[3];
    const float* bq = (const float*)d_in[4];
    const float* Wk = (const float*)d_in[5];
    const float* bk = (const float*)d_in[6];
    const float* Wv = (const float*)d_in[7];
    const float* bv = (const float*)d_in[8];
    const float* Wo = (const float*)d_in[9];
    const float* bo = (const float*)d_in[10];
    const float* W1 = (const float*)d_in[11];
    const float* b1 = (const float*)d_in[12];
    const float* W2 = (const float*)d_in[13];
    const float* b2 = (const float*)d_in[14];
    const float* g1 = (const float*)d_in[15];
    const float* be1 = (const float*)d_in[16];
    const float* g2 = (const float*)d_in[17];
    const float* be2 = (const float*)d_in[18];
    const float* gf = (const float*)d_in[19];
    const float* bf = (const float*)d_in[20];
    const int* mask = (const int*)d_in[21];

    float *x, *xv, *q, *k, *v, *ao, *o, *h, *h2;
    cudaGetSymbolAddress((void**)&x, g_x);
    cudaGetSymbolAddress((void**)&xv, g_xv);
    cudaGetSymbolAddress((void**)&q, g_q);
    cudaGetSymbolAddress((void**)&k, g_k);
    cudaGetSymbolAddress((void**)&v, g_v);
    cudaGetSymbolAddress((void**)&ao, g_ao);
    cudaGetSymbolAddress((void**)&o, g_o);
    cudaGetSymbolAddress((void**)&h, g_h);
    cudaGetSymbolAddress((void**)&h2, g_h2);

    const int M = BB * NN;  // 8192

    add_pos_kernel<<<(BB * NN * DD) / 256, 256>>>(input, input_v, pos_emb, x, xv);

    for (int i = 0; i < LL; i++) {
        const float* Wqi = Wq + (size_t)i * DD * DD;
        const float* Wki = Wk + (size_t)i * DD * DD;
        const float* Wvi = Wv + (size_t)i * DD * DD;
        const float* Woi = Wo + (size_t)i * DD * DD;
        const float* W1i = W1 + (size_t)i * DD * DFF;
        const float* W2i = W2 + (size_t)i * (DFF / 2) * (DD / 2);

        // QKV projections in one batched launch (z = 0,1,2)
        gemm_qkv_kernel<<<dim3(DD / GN, M / GM, 3), 256>>>(
            x, xv, Wqi, Wki, Wvi, bq + i * DD, bk + i * DD, bv + i * DD,
            q, k, v, M, DD, DD);

        // attention (tf32 tensor-core, sync-free dataflow)
        attn_kernel<<<dim3(NN / 16, HH, BB), 256>>>(
            q, k, v, mask, ao, (i % 2) ? 1 : 0);

        // output projection
        gemm128_kernel<<<dim3(DD / GN, M / GM), 256>>>(ao, Woi, bo + i * DD, o, M, DD, DD, 0);

        // x = LN(x + o)
        ln_kernel<<<M / 8, 256>>>(x, o, g1 + i * DD, be1 + i * DD, x);

        // FFN1 + GELU
        gemm128_kernel<<<dim3(DFF / GN, M / GM), 256>>>(x, W1i, b1 + i * DFF, h, M, DD, DFF, 1);

        // FFN2 grouped: (B*N*2, 512) @ (512, 128) -> contiguous (B*N, 256)
        gemm128_kernel<<<dim3((DD / 2) / GN, (2 * M) / GM), 256>>>(
            h, W2i, b2 + i * (DD / 2), h2, 2 * M, DFF / 2, DD / 2, 0);

        // x = LN(x + h2)
        ln_kernel<<<M / 8, 256>>>(x, h2, g2 + i * DD, be2 + i * DD, x);
    }

    // final LN -> output
    ln_kernel<<<M / 8, 256>>>(x, nullptr, gf, bf, (float*)d_out);
}